// round 1
// baseline (speedup 1.0000x reference)
#include <cuda_runtime.h>
#include <math.h>

#define B_  4
#define S_  2048
#define D_  1024
#define H_  16
#define HD_ 64
#define SCALE_ 0.125f   // 1/sqrt(64)

// ---------------------------------------------------------------------------
// Scratch (allocation-free: __device__ globals). float4 arrays for 16B align.
// ---------------------------------------------------------------------------
__device__ float4 g_q4[(size_t)B_ * H_ * S_ * HD_ / 4];   // (B,H,S,HD) 32MB
__device__ float4 g_k4[(size_t)B_ * H_ * S_ * HD_ / 4];
__device__ float4 g_v4[(size_t)B_ * H_ * S_ * HD_ / 4];
__device__ float4 g_ctx4[(size_t)B_ * S_ * D_ / 4];       // (B,S,D)   32MB
__device__ unsigned char g_mask8[(size_t)S_ * S_];        // expanded mask, 4MB
__device__ int g_mask_is_byte;

// ---------------------------------------------------------------------------
// Mask dtype probe: if elements are 4 bytes (int32/float32), byte (4i+1) is
// always 0 for values {0,1}/{0.0f,1.0f}. If 1-byte bool, those bytes are
// random 0/1 -> almost surely some nonzero among 16384 samples.
// ---------------------------------------------------------------------------
__global__ void detect_mask_kernel(const unsigned char* __restrict__ m) {
    __shared__ int any;
    if (threadIdx.x == 0) any = 0;
    __syncthreads();
    int found = 0;
    for (int i = threadIdx.x; i < 16384; i += 256)
        if (m[4 * i + 1] != 0) found = 1;
    if (found) atomicOr(&any, 1);
    __syncthreads();
    if (threadIdx.x == 0) g_mask_is_byte = any;
}

__global__ void expand_mask_kernel(const void* __restrict__ mraw) {
    int idx = blockIdx.x * blockDim.x + threadIdx.x;
    if (idx >= S_ * S_) return;
    unsigned char v;
    if (g_mask_is_byte)
        v = (((const unsigned char*)mraw)[idx] != 0) ? 1 : 0;
    else
        v = (((const int*)mraw)[idx] != 0) ? 1 : 0;   // covers int32 and f32 bits
    g_mask8[idx] = v;
}

// ---------------------------------------------------------------------------
// Tiled SGEMM:  Y[8192,1024] = X[8192,1024] @ W[1024,1024] + bias
// BM=BN=128, BK=16, 256 threads, 8x8 per thread.
// xsel: 0 -> Xext, 1 -> g_ctx
// ysel: 0 -> Yext row-major; 1/2/3 -> split-heads into g_q/g_k/g_v (B,H,S,HD)
// ---------------------------------------------------------------------------
__global__ __launch_bounds__(256)
void gemm_kernel(const float* __restrict__ Xext, int xsel,
                 const float* __restrict__ W, const float* __restrict__ bias,
                 float* __restrict__ Yext, int ysel)
{
    const float* X = (xsel == 0) ? Xext : (const float*)g_ctx4;

    __shared__ float As[16][128];   // A transposed: As[k][m]
    __shared__ float Bs[16][128];   // Bs[k][n]

    const int tid = threadIdx.x;
    const int tr  = tid >> 4;        // 0..15
    const int tc  = tid & 15;        // 0..15
    const int m0  = blockIdx.y * 128;
    const int n0  = blockIdx.x * 128;

    // load mappings
    const int lm  = tid >> 1;            // A row within tile (0..127)
    const int lk  = (tid & 1) * 8;       // A k offset (0 or 8)
    const int lbk = tid >> 4;            // B k row (0..15)
    const int lbn = (tid & 15) * 8;      // B n offset

    float acc[8][8];
#pragma unroll
    for (int i = 0; i < 8; i++)
#pragma unroll
        for (int j = 0; j < 8; j++) acc[i][j] = 0.0f;

    for (int k0 = 0; k0 < D_; k0 += 16) {
        float4 a0 = *(const float4*)(X + (size_t)(m0 + lm) * D_ + k0 + lk);
        float4 a1 = *(const float4*)(X + (size_t)(m0 + lm) * D_ + k0 + lk + 4);
        float4 b0 = *(const float4*)(W + (size_t)(k0 + lbk) * D_ + n0 + lbn);
        float4 b1 = *(const float4*)(W + (size_t)(k0 + lbk) * D_ + n0 + lbn + 4);

        As[lk + 0][lm] = a0.x; As[lk + 1][lm] = a0.y;
        As[lk + 2][lm] = a0.z; As[lk + 3][lm] = a0.w;
        As[lk + 4][lm] = a1.x; As[lk + 5][lm] = a1.y;
        As[lk + 6][lm] = a1.z; As[lk + 7][lm] = a1.w;
        *(float4*)&Bs[lbk][lbn]     = b0;
        *(float4*)&Bs[lbk][lbn + 4] = b1;
        __syncthreads();

#pragma unroll
        for (int kk = 0; kk < 16; kk++) {
            float4 xa0 = *(const float4*)&As[kk][tr * 8];
            float4 xa1 = *(const float4*)&As[kk][tr * 8 + 4];
            float4 xb0 = *(const float4*)&Bs[kk][tc * 8];
            float4 xb1 = *(const float4*)&Bs[kk][tc * 8 + 4];
            float av[8] = {xa0.x, xa0.y, xa0.z, xa0.w, xa1.x, xa1.y, xa1.z, xa1.w};
            float bv[8] = {xb0.x, xb0.y, xb0.z, xb0.w, xb1.x, xb1.y, xb1.z, xb1.w};
#pragma unroll
            for (int i = 0; i < 8; i++)
#pragma unroll
                for (int j = 0; j < 8; j++)
                    acc[i][j] = fmaf(av[i], bv[j], acc[i][j]);
        }
        __syncthreads();
    }

    float* dst = (ysel == 1) ? (float*)g_q4
               : (ysel == 2) ? (float*)g_k4
               : (ysel == 3) ? (float*)g_v4 : Yext;

#pragma unroll
    for (int i = 0; i < 8; i++) {
        const int row = m0 + tr * 8 + i;
#pragma unroll
        for (int j = 0; j < 8; j++) {
            const int col = n0 + tc * 8 + j;
            float v = acc[i][j] + bias[col];
            if (ysel == 0) {
                dst[(size_t)row * D_ + col] = v;
            } else {
                const int b = row >> 11;      // / S_
                const int s = row & (S_ - 1);
                const int h = col >> 6;       // / HD_
                const int d = col & (HD_ - 1);
                dst[((size_t)(b * H_ + h) * S_ + s) * HD_ + d] = v;
            }
        }
    }
}

// ---------------------------------------------------------------------------
// Flash attention: per (b,h), BQ=64 query rows per block, iterate kv in
// tiles of BK=32. 256 threads as 16x16: thread(ty,tx) owns score rows
// 4*ty+i (i<4), score cols tx+16*j (j<2), output dims tx+16*jd (jd<4).
// Online softmax with warp-shuffle row reductions (rows live in one warp
// half: lanes share row across the 16 tx lanes).
// ---------------------------------------------------------------------------
#define BQ 64
#define BK 32
#define KSTRIDE 68   // K tile row stride (floats), 16B-aligned, low-conflict
#define PSTRIDE 36   // P tile row stride (floats), 16B-aligned

__global__ __launch_bounds__(256)
void attn_kernel()
{
    __shared__ float Qs[BQ][HD_];                 // 16 KB
    __shared__ float KP[BQ * PSTRIDE];            // 9 KB: K[32][68] / P[64][36]
    __shared__ float Vs[BK][HD_];                 // 8 KB

    const int tid = threadIdx.x;
    const int ty  = tid >> 4;   // 0..15
    const int tx  = tid & 15;   // 0..15
    const int q0  = blockIdx.x * BQ;
    const int bh  = blockIdx.y;               // b*H + h

    const float* Qp = (const float*)g_q4 + (size_t)bh * S_ * HD_;
    const float* Kp = (const float*)g_k4 + (size_t)bh * S_ * HD_;
    const float* Vp = (const float*)g_v4 + (size_t)bh * S_ * HD_;

    // load Q tile (coalesced)
    for (int t = tid; t < BQ * HD_; t += 256) {
        int r = t >> 6, d = t & 63;
        Qs[r][d] = Qp[(size_t)(q0 + r) * HD_ + d];
    }

    float m_run[4], l_run[4], acc[4][4];
#pragma unroll
    for (int i = 0; i < 4; i++) {
        m_run[i] = -INFINITY; l_run[i] = 0.0f;
#pragma unroll
        for (int jd = 0; jd < 4; jd++) acc[i][jd] = 0.0f;
    }

    for (int k0 = 0; k0 < S_; k0 += BK) {
        __syncthreads();   // Qs ready (iter0); KP/Vs free (prev PV done)

        for (int t = tid; t < BK * HD_; t += 256) {
            int c = t >> 6, d = t & 63;
            KP[c * KSTRIDE + d] = Kp[(size_t)(k0 + c) * HD_ + d];
            Vs[c][d]            = Vp[(size_t)(k0 + c) * HD_ + d];
        }
        __syncthreads();

        // ---- scores: s[i][j] = Q[4ty+i] . K[tx+16j] ----
        float s[4][2];
#pragma unroll
        for (int i = 0; i < 4; i++) { s[i][0] = 0.0f; s[i][1] = 0.0f; }

#pragma unroll
        for (int d4 = 0; d4 < HD_ / 4; d4++) {
            float4 qv[4], kv[2];
#pragma unroll
            for (int i = 0; i < 4; i++)
                qv[i] = *(const float4*)&Qs[4 * ty + i][d4 * 4];
#pragma unroll
            for (int j = 0; j < 2; j++)
                kv[j] = *(const float4*)&KP[(tx + 16 * j) * KSTRIDE + d4 * 4];
#pragma unroll
            for (int i = 0; i < 4; i++)
#pragma unroll
                for (int j = 0; j < 2; j++) {
                    s[i][j] = fmaf(qv[i].x, kv[j].x, s[i][j]);
                    s[i][j] = fmaf(qv[i].y, kv[j].y, s[i][j]);
                    s[i][j] = fmaf(qv[i].z, kv[j].z, s[i][j]);
                    s[i][j] = fmaf(qv[i].w, kv[j].w, s[i][j]);
                }
        }

        // ---- scale + mask ----
#pragma unroll
        for (int i = 0; i < 4; i++) {
            const int qq = q0 + 4 * ty + i;
#pragma unroll
            for (int j = 0; j < 2; j++) {
                const int kk = k0 + tx + 16 * j;
                s[i][j] = g_mask8[(size_t)qq * S_ + kk] ? s[i][j] * SCALE_
                                                        : -1e30f;
            }
        }

        // ---- row max across the 16 tx lanes ----
        float tmax[4];
#pragma unroll
        for (int i = 0; i < 4; i++) tmax[i] = fmaxf(s[i][0], s[i][1]);
#pragma unroll
        for (int off = 1; off < 16; off <<= 1)
#pragma unroll
            for (int i = 0; i < 4; i++)
                tmax[i] = fmaxf(tmax[i], __shfl_xor_sync(0xffffffffu, tmax[i], off));

        // ---- online softmax update ----
        float p[4][2], tsum[4];
#pragma unroll
        for (int i = 0; i < 4; i++) {
            float mnew = fmaxf(m_run[i], tmax[i]);
            float corr = __expf(m_run[i] - mnew);
            m_run[i] = mnew;
            p[i][0] = __expf(s[i][0] - mnew);
            p[i][1] = __expf(s[i][1] - mnew);
            tsum[i] = p[i][0] + p[i][1];
            l_run[i] *= corr;
#pragma unroll
            for (int jd = 0; jd < 4; jd++) acc[i][jd] *= corr;
        }
#pragma unroll
        for (int off = 1; off < 16; off <<= 1)
#pragma unroll
            for (int i = 0; i < 4; i++)
                tsum[i] += __shfl_xor_sync(0xffffffffu, tsum[i], off);
#pragma unroll
        for (int i = 0; i < 4; i++) l_run[i] += tsum[i];

        __syncthreads();   // all lanes done reading K before P overwrites it
#pragma unroll
        for (int i = 0; i < 4; i++)
#pragma unroll
            for (int j = 0; j < 2; j++)
                KP[(4 * ty + i) * PSTRIDE + tx + 16 * j] = p[i][j];
        __syncthreads();

        // ---- acc += P @ V ----
#pragma unroll 2
        for (int c = 0; c < BK; c += 4) {
            float pr[4][4];
#pragma unroll
            for (int i = 0; i < 4; i++) {
                float4 t = *(const float4*)&KP[(4 * ty + i) * PSTRIDE + c];
                pr[i][0] = t.x; pr[i][1] = t.y; pr[i][2] = t.z; pr[i][3] = t.w;
            }
#pragma unroll
            for (int cc = 0; cc < 4; cc++) {
                float vv[4];
#pragma unroll
                for (int jd = 0; jd < 4; jd++)
                    vv[jd] = Vs[c + cc][tx + 16 * jd];
#pragma unroll
                for (int i = 0; i < 4; i++)
#pragma unroll
                    for (int jd = 0; jd < 4; jd++)
                        acc[i][jd] = fmaf(pr[i][cc], vv[jd], acc[i][jd]);
            }
        }
    }

    // ---- epilogue: normalize + write ctx in (B,S,D) layout ----
    const int b = bh >> 4;
    const int h = bh & 15;
    float* ctx = (float*)g_ctx4;
#pragma unroll
    for (int i = 0; i < 4; i++) {
        const float inv = 1.0f / l_run[i];
        const int r = q0 + 4 * ty + i;
#pragma unroll
        for (int jd = 0; jd < 4; jd++)
            ctx[((size_t)b * S_ + r) * D_ + h * HD_ + tx + 16 * jd] =
                acc[i][jd] * inv;
    }
}

// ---------------------------------------------------------------------------
// Launch
// ---------------------------------------------------------------------------
extern "C" void kernel_launch(void* const* d_in, const int* in_sizes, int n_in,
                              void* d_out, int out_size)
{
    const float* queries = (const float*)d_in[0];
    const float* keys    = (const float*)d_in[1];
    const float* values  = (const float*)d_in[2];
    const void*  mask    = d_in[3];
    const float* Wq = (const float*)d_in[4];
    const float* bq = (const float*)d_in[5];
    const float* Wk = (const float*)d_in[6];
    const float* bk = (const float*)d_in[7];
    const float* Wv = (const float*)d_in[8];
    const float* bv = (const float*)d_in[9];
    const float* Wo = (const float*)d_in[10];
    const float* bo = (const float*)d_in[11];
    float* out = (float*)d_out;

    (void)in_sizes; (void)n_in; (void)out_size;

    // mask dtype probe + expansion
    detect_mask_kernel<<<1, 256>>>((const unsigned char*)mask);
    expand_mask_kernel<<<(S_ * S_ + 255) / 256, 256>>>(mask);

    // QKV projections -> split-heads scratch
    dim3 ggrid(D_ / 128, (B_ * S_) / 128);   // (8, 64)
    gemm_kernel<<<ggrid, 256>>>(queries, 0, Wq, bq, nullptr, 1);
    gemm_kernel<<<ggrid, 256>>>(keys,    0, Wk, bk, nullptr, 2);
    gemm_kernel<<<ggrid, 256>>>(values,  0, Wv, bv, nullptr, 3);

    // attention
    dim3 agrid(S_ / BQ, B_ * H_);            // (32, 64)
    attn_kernel<<<agrid, 256>>>();

    // output projection: ctx @ Wo + bo -> d_out
    gemm_kernel<<<ggrid, 256>>>(nullptr, 1, Wo, bo, out, 0);
}

// round 2
// speedup vs baseline: 1.2411x; 1.2411x over previous
#include <cuda_runtime.h>
#include <math.h>

#define B_  4
#define S_  2048
#define D_  1024
#define H_  16
#define HD_ 64
#define SCALE_ 0.125f   // 1/sqrt(64)

// ---------------------------------------------------------------------------
// Scratch (allocation-free: __device__ globals). float4 arrays for 16B align.
// ---------------------------------------------------------------------------
__device__ float4 g_q4[(size_t)B_ * H_ * S_ * HD_ / 4];   // (B,H,S,HD) 32MB
__device__ float4 g_k4[(size_t)B_ * H_ * S_ * HD_ / 4];
__device__ float4 g_v4[(size_t)B_ * H_ * S_ * HD_ / 4];
__device__ float4 g_ctx4[(size_t)B_ * S_ * D_ / 4];       // (B,S,D)   32MB
__device__ unsigned char g_mask8[(size_t)S_ * S_];        // expanded mask, 4MB
__device__ int g_mask_is_byte;

// ---------------------------------------------------------------------------
// Mask dtype probe (unchanged from R1 — proven correct).
// ---------------------------------------------------------------------------
__global__ void detect_mask_kernel(const unsigned char* __restrict__ m) {
    __shared__ int any;
    if (threadIdx.x == 0) any = 0;
    __syncthreads();
    int found = 0;
    for (int i = threadIdx.x; i < 16384; i += 256)
        if (m[4 * i + 1] != 0) found = 1;
    if (found) atomicOr(&any, 1);
    __syncthreads();
    if (threadIdx.x == 0) g_mask_is_byte = any;
}

__global__ void expand_mask_kernel(const void* __restrict__ mraw) {
    int idx = blockIdx.x * blockDim.x + threadIdx.x;
    if (idx >= S_ * S_) return;
    unsigned char v;
    if (g_mask_is_byte)
        v = (((const unsigned char*)mraw)[idx] != 0) ? 1 : 0;
    else
        v = (((const int*)mraw)[idx] != 0) ? 1 : 0;
    g_mask8[idx] = v;
}

// ---------------------------------------------------------------------------
// SGEMM v2: Y[8192,1024] = X[8192,1024] @ W[1024,1024] + bias
// 128x128 tile, BK=8, double-buffered smem + register prefetch.
// 256 threads = 8 warps in 2x4; warp tile 64x32; lane 8x4; thread 8x8 as
// 2x2 chunks of 4x4. All fragment LDS are conflict-free.
// ---------------------------------------------------------------------------
__global__ __launch_bounds__(256, 2)
void gemm_kernel(const float* __restrict__ Xext, int xsel,
                 const float* __restrict__ W, const float* __restrict__ bias,
                 float* __restrict__ Yext, int ysel)
{
    const float* X = (xsel == 0) ? Xext : (const float*)g_ctx4;

    __shared__ float As[2][8][132];   // A^T: [k][m], pad->conflict-free STS+LDS
    __shared__ float Bs[2][8][128];   // [k][n]

    const int tid  = threadIdx.x;
    const int m0   = blockIdx.y * 128;
    const int n0   = blockIdx.x * 128;
    const int w    = tid >> 5;
    const int lane = tid & 31;
    const int wr   = w >> 2;          // 0..1
    const int wc   = w & 3;           // 0..3
    const int lr   = lane >> 2;       // 0..7
    const int lc   = lane & 3;        // 0..3
    const int rA   = wr * 64 + lr * 4;   // row base (chunk1 = +32)
    const int cB   = wc * 32 + lc * 4;   // col base (chunk1 = +16)

    // gmem load mapping
    const int a_row = tid >> 1;            // 0..127
    const int a_k   = (tid & 1) * 4;       // 0 or 4
    const int b_k   = tid >> 5;            // 0..7
    const int b_col = (tid & 31) * 4;      // 0..124

    const float* Aptr = X + (size_t)(m0 + a_row) * D_ + a_k;
    const float* Bptr = W + (size_t)b_k * D_ + n0 + b_col;

    float acc[2][2][4][4];
#pragma unroll
    for (int rc = 0; rc < 2; rc++)
#pragma unroll
        for (int cc = 0; cc < 2; cc++)
#pragma unroll
            for (int i = 0; i < 4; i++)
#pragma unroll
                for (int j = 0; j < 4; j++) acc[rc][cc][i][j] = 0.0f;

    // prologue: stage 0
    float4 pa = *(const float4*)Aptr;
    float4 pb = *(const float4*)Bptr;
    As[0][a_k + 0][a_row] = pa.x; As[0][a_k + 1][a_row] = pa.y;
    As[0][a_k + 2][a_row] = pa.z; As[0][a_k + 3][a_row] = pa.w;
    *(float4*)&Bs[0][b_k][b_col] = pb;
    __syncthreads();

    int cur = 0;
    for (int k0 = 0; k0 < D_; k0 += 8) {
        const bool has_next = (k0 + 8 < D_);
        if (has_next) {
            pa = *(const float4*)(Aptr + k0 + 8);
            pb = *(const float4*)(Bptr + (size_t)(k0 + 8) * D_);
        }

#pragma unroll
        for (int kk = 0; kk < 8; kk++) {
            float4 a0 = *(const float4*)&As[cur][kk][rA];
            float4 a1 = *(const float4*)&As[cur][kk][rA + 32];
            float4 b0 = *(const float4*)&Bs[cur][kk][cB];
            float4 b1 = *(const float4*)&Bs[cur][kk][cB + 16];
            float av[2][4] = {{a0.x, a0.y, a0.z, a0.w}, {a1.x, a1.y, a1.z, a1.w}};
            float bv[2][4] = {{b0.x, b0.y, b0.z, b0.w}, {b1.x, b1.y, b1.z, b1.w}};
#pragma unroll
            for (int rc = 0; rc < 2; rc++)
#pragma unroll
                for (int i = 0; i < 4; i++)
#pragma unroll
                    for (int cc = 0; cc < 2; cc++)
#pragma unroll
                        for (int j = 0; j < 4; j++)
                            acc[rc][cc][i][j] =
                                fmaf(av[rc][i], bv[cc][j], acc[rc][cc][i][j]);
        }

        if (has_next) {
            const int nxt = cur ^ 1;
            As[nxt][a_k + 0][a_row] = pa.x; As[nxt][a_k + 1][a_row] = pa.y;
            As[nxt][a_k + 2][a_row] = pa.z; As[nxt][a_k + 3][a_row] = pa.w;
            *(float4*)&Bs[nxt][b_k][b_col] = pb;
        }
        __syncthreads();
        cur ^= 1;
    }

    float* dst = (ysel == 1) ? (float*)g_q4
               : (ysel == 2) ? (float*)g_k4
               : (ysel == 3) ? (float*)g_v4 : Yext;

#pragma unroll
    for (int rc = 0; rc < 2; rc++)
#pragma unroll
        for (int i = 0; i < 4; i++) {
            const int row = m0 + rA + rc * 32 + i;
#pragma unroll
            for (int cc = 0; cc < 2; cc++) {
                const int col = n0 + cB + cc * 16;
                float4 v;
                v.x = acc[rc][cc][i][0] + bias[col + 0];
                v.y = acc[rc][cc][i][1] + bias[col + 1];
                v.z = acc[rc][cc][i][2] + bias[col + 2];
                v.w = acc[rc][cc][i][3] + bias[col + 3];
                if (ysel == 0) {
                    *(float4*)&dst[(size_t)row * D_ + col] = v;
                } else {
                    const int b = row >> 11;
                    const int s = row & (S_ - 1);
                    const int h = col >> 6;
                    const int d = col & (HD_ - 1);
                    *(float4*)&dst[((size_t)(b * H_ + h) * S_ + s) * HD_ + d] = v;
                }
            }
        }
}

// ---------------------------------------------------------------------------
// Flash attention v2: BQ=64, BK=64. 256 threads as 16x16.
// Thread: 4 q-rows (4ty+i) x 4 k-cols (tx+16j); output dims tx+16jd.
// Smem (dynamic, 51.2KB): Qs[64][68], KP[64][68] (K then reused as P),
// Vs[64][64]. 4 syncthreads per 64-wide kv tile (was 4 per 32-wide).
// ---------------------------------------------------------------------------
#define AQ 64
#define AK 64
#define QKST 68                       // Q/K/P row stride (floats)
#define QOFF 0
#define KPOFF (AQ * QKST)             // 4352
#define VOFF  (KPOFF + AK * QKST)     // 8704
#define ATTN_SMEM_FLOATS (VOFF + AK * HD_)   // 12800 floats = 51200 B

__global__ __launch_bounds__(256, 2)
void attn_kernel()
{
    extern __shared__ float sm[];

    const int tid = threadIdx.x;
    const int ty  = tid >> 4;   // 0..15
    const int tx  = tid & 15;   // 0..15
    const int q0  = blockIdx.x * AQ;
    const int bh  = blockIdx.y;

    const float* Qp = (const float*)g_q4 + (size_t)bh * S_ * HD_;
    const float* Kp = (const float*)g_k4 + (size_t)bh * S_ * HD_;
    const float* Vp = (const float*)g_v4 + (size_t)bh * S_ * HD_;

    // load Q tile
    for (int t = tid; t < AQ * HD_; t += 256) {
        int r = t >> 6, d = t & 63;
        sm[QOFF + r * QKST + d] = Qp[(size_t)(q0 + r) * HD_ + d];
    }

    float m_run[4], l_run[4], acc[4][4];
#pragma unroll
    for (int i = 0; i < 4; i++) {
        m_run[i] = -INFINITY; l_run[i] = 0.0f;
#pragma unroll
        for (int jd = 0; jd < 4; jd++) acc[i][jd] = 0.0f;
    }

    for (int k0 = 0; k0 < S_; k0 += AK) {
        __syncthreads();   // Q ready (iter0); prior PV reads of KP/Vs done

        for (int t = tid; t < AK * HD_; t += 256) {
            int c = t >> 6, d = t & 63;
            sm[KPOFF + c * QKST + d] = Kp[(size_t)(k0 + c) * HD_ + d];
            sm[VOFF  + c * HD_  + d] = Vp[(size_t)(k0 + c) * HD_ + d];
        }
        __syncthreads();

        // ---- scores s[i][j] = Q[4ty+i] . K[tx+16j] ----
        float s[4][4];
#pragma unroll
        for (int i = 0; i < 4; i++)
#pragma unroll
            for (int j = 0; j < 4; j++) s[i][j] = 0.0f;

#pragma unroll 8
        for (int d4 = 0; d4 < HD_ / 4; d4++) {
            float4 qv[4], kv[4];
#pragma unroll
            for (int i = 0; i < 4; i++)
                qv[i] = *(const float4*)&sm[QOFF + (4 * ty + i) * QKST + d4 * 4];
#pragma unroll
            for (int j = 0; j < 4; j++)
                kv[j] = *(const float4*)&sm[KPOFF + (tx + 16 * j) * QKST + d4 * 4];
#pragma unroll
            for (int i = 0; i < 4; i++)
#pragma unroll
                for (int j = 0; j < 4; j++) {
                    s[i][j] = fmaf(qv[i].x, kv[j].x, s[i][j]);
                    s[i][j] = fmaf(qv[i].y, kv[j].y, s[i][j]);
                    s[i][j] = fmaf(qv[i].z, kv[j].z, s[i][j]);
                    s[i][j] = fmaf(qv[i].w, kv[j].w, s[i][j]);
                }
        }

        // ---- scale + mask ----
#pragma unroll
        for (int i = 0; i < 4; i++) {
            const unsigned char* mrow =
                &g_mask8[(size_t)(q0 + 4 * ty + i) * S_ + k0];
#pragma unroll
            for (int j = 0; j < 4; j++)
                s[i][j] = mrow[tx + 16 * j] ? s[i][j] * SCALE_ : -1e30f;
        }

        // ---- row max (4 local cols, then 16 tx lanes) ----
        float tmax[4];
#pragma unroll
        for (int i = 0; i < 4; i++)
            tmax[i] = fmaxf(fmaxf(s[i][0], s[i][1]), fmaxf(s[i][2], s[i][3]));
#pragma unroll
        for (int off = 1; off < 16; off <<= 1)
#pragma unroll
            for (int i = 0; i < 4; i++)
                tmax[i] = fmaxf(tmax[i], __shfl_xor_sync(0xffffffffu, tmax[i], off));

        // ---- online softmax update (p overwrites s) ----
        float tsum[4];
#pragma unroll
        for (int i = 0; i < 4; i++) {
            float mnew = fmaxf(m_run[i], tmax[i]);
            float corr = __expf(m_run[i] - mnew);
            m_run[i] = mnew;
            float t0 = __expf(s[i][0] - mnew);
            float t1 = __expf(s[i][1] - mnew);
            float t2 = __expf(s[i][2] - mnew);
            float t3 = __expf(s[i][3] - mnew);
            s[i][0] = t0; s[i][1] = t1; s[i][2] = t2; s[i][3] = t3;
            tsum[i] = (t0 + t1) + (t2 + t3);
            l_run[i] *= corr;
#pragma unroll
            for (int jd = 0; jd < 4; jd++) acc[i][jd] *= corr;
        }
#pragma unroll
        for (int off = 1; off < 16; off <<= 1)
#pragma unroll
            for (int i = 0; i < 4; i++)
                tsum[i] += __shfl_xor_sync(0xffffffffu, tsum[i], off);
#pragma unroll
        for (int i = 0; i < 4; i++) l_run[i] += tsum[i];

        __syncthreads();   // all K reads done before P overwrites
#pragma unroll
        for (int i = 0; i < 4; i++)
#pragma unroll
            for (int j = 0; j < 4; j++)
                sm[KPOFF + (4 * ty + i) * QKST + tx + 16 * j] = s[i][j];
        __syncthreads();

        // ---- acc += P @ V ----
#pragma unroll 4
        for (int c0 = 0; c0 < AK; c0 += 4) {
            float prr[4][4];
#pragma unroll
            for (int i = 0; i < 4; i++) {
                float4 t = *(const float4*)&sm[KPOFF + (4 * ty + i) * QKST + c0];
                prr[i][0] = t.x; prr[i][1] = t.y; prr[i][2] = t.z; prr[i][3] = t.w;
            }
#pragma unroll
            for (int cc = 0; cc < 4; cc++) {
                float vv[4];
#pragma unroll
                for (int jd = 0; jd < 4; jd++)
                    vv[jd] = sm[VOFF + (c0 + cc) * HD_ + tx + 16 * jd];
#pragma unroll
                for (int i = 0; i < 4; i++)
#pragma unroll
                    for (int jd = 0; jd < 4; jd++)
                        acc[i][jd] = fmaf(prr[i][cc], vv[jd], acc[i][jd]);
            }
        }
    }

    // ---- epilogue ----
    const int b = bh >> 4;
    const int h = bh & 15;
    float* ctx = (float*)g_ctx4;
#pragma unroll
    for (int i = 0; i < 4; i++) {
        const float inv = 1.0f / l_run[i];
        const int r = q0 + 4 * ty + i;
#pragma unroll
        for (int jd = 0; jd < 4; jd++)
            ctx[((size_t)b * S_ + r) * D_ + h * HD_ + tx + 16 * jd] =
                acc[i][jd] * inv;
    }
}

// ---------------------------------------------------------------------------
// Launch
// ---------------------------------------------------------------------------
extern "C" void kernel_launch(void* const* d_in, const int* in_sizes, int n_in,
                              void* d_out, int out_size)
{
    const float* queries = (const float*)d_in[0];
    const float* keys    = (const float*)d_in[1];
    const float* values  = (const float*)d_in[2];
    const void*  mask    = d_in[3];
    const float* Wq = (const float*)d_in[4];
    const float* bq = (const float*)d_in[5];
    const float* Wk = (const float*)d_in[6];
    const float* bk = (const float*)d_in[7];
    const float* Wv = (const float*)d_in[8];
    const float* bv = (const float*)d_in[9];
    const float* Wo = (const float*)d_in[10];
    const float* bo = (const float*)d_in[11];
    float* out = (float*)d_out;

    (void)in_sizes; (void)n_in; (void)out_size;

    // opt-in to >48KB dynamic smem for attention (idempotent, not an alloc)
    cudaFuncSetAttribute(attn_kernel,
                         cudaFuncAttributeMaxDynamicSharedMemorySize,
                         ATTN_SMEM_FLOATS * (int)sizeof(float));

    detect_mask_kernel<<<1, 256>>>((const unsigned char*)mask);
    expand_mask_kernel<<<(S_ * S_ + 255) / 256, 256>>>(mask);

    dim3 ggrid(D_ / 128, (B_ * S_) / 128);   // (8, 64)
    gemm_kernel<<<ggrid, 256>>>(queries, 0, Wq, bq, nullptr, 1);
    gemm_kernel<<<ggrid, 256>>>(keys,    0, Wk, bk, nullptr, 2);
    gemm_kernel<<<ggrid, 256>>>(values,  0, Wv, bv, nullptr, 3);

    dim3 agrid(S_ / AQ, B_ * H_);            // (32, 64)
    attn_kernel<<<agrid, 256, ATTN_SMEM_FLOATS * (int)sizeof(float)>>>();

    gemm_kernel<<<ggrid, 256>>>(nullptr, 1, Wo, bo, out, 0);
}

// round 4
// speedup vs baseline: 1.5821x; 1.2748x over previous
#include <cuda_runtime.h>
#include <cuda_bf16.h>
#include <math.h>
#include <stdint.h>

#define B_  4
#define S_  2048
#define D_  1024
#define H_  16
#define HD_ 64
#define SCALE_ 0.125f   // 1/sqrt(64)

// ---------------------------------------------------------------------------
// Scratch (allocation-free __device__ globals)
// ---------------------------------------------------------------------------
__device__ float4 g_q4[(size_t)B_ * H_ * S_ * HD_ / 4];
__device__ float4 g_k4[(size_t)B_ * H_ * S_ * HD_ / 4];
__device__ float4 g_v4[(size_t)B_ * H_ * S_ * HD_ / 4];
__device__ float4 g_ctx4[(size_t)B_ * S_ * D_ / 4];
__device__ uint2 g_xb0[(size_t)B_ * S_ * D_ / 4];   // bf16 X big   [8192][1024]
__device__ uint2 g_xb1[(size_t)B_ * S_ * D_ / 4];   // bf16 X small
__device__ uint2 g_wtb0[(size_t)D_ * D_ / 4];       // bf16 W^T big [n][k]
__device__ uint2 g_wtb1[(size_t)D_ * D_ / 4];       // bf16 W^T small
__device__ unsigned char g_mask8[(size_t)S_ * S_];
__device__ int g_mask_is_byte;

// ---------------------------------------------------------------------------
// PTX helpers (sm_80-era: valid on plain compute_100 target)
// ---------------------------------------------------------------------------
__device__ __forceinline__ uint32_t smem_u32(const void* p) {
    uint32_t a;
    asm("{ .reg .u64 t; cvta.to.shared.u64 t, %1; cvt.u32.u64 %0, t; }"
        : "=r"(a) : "l"(p));
    return a;
}
#define CP_ASYNC16(dst, src) \
    asm volatile("cp.async.cg.shared.global [%0], [%1], 16;" \
                 :: "r"(dst), "l"(src) : "memory")
#define CP_COMMIT()  asm volatile("cp.async.commit_group;" ::: "memory")
#define CP_WAIT1()   asm volatile("cp.async.wait_group 1;" ::: "memory")
#define CP_WAIT0()   asm volatile("cp.async.wait_group 0;" ::: "memory")

__device__ __forceinline__ void ldsm4(uint32_t* r, uint32_t addr) {
    asm volatile("ldmatrix.sync.aligned.m8n8.x4.shared.b16 {%0,%1,%2,%3}, [%4];"
                 : "=r"(r[0]), "=r"(r[1]), "=r"(r[2]), "=r"(r[3]) : "r"(addr));
}
__device__ __forceinline__ void mma_bf16(float* c, const uint32_t* a,
                                         const uint32_t* b) {
    asm volatile(
        "mma.sync.aligned.m16n8k16.row.col.f32.bf16.bf16.f32 "
        "{%0,%1,%2,%3}, {%4,%5,%6,%7}, {%8,%9}, {%0,%1,%2,%3};"
        : "+f"(c[0]), "+f"(c[1]), "+f"(c[2]), "+f"(c[3])
        : "r"(a[0]), "r"(a[1]), "r"(a[2]), "r"(a[3]), "r"(b[0]), "r"(b[1]));
}

// ---------------------------------------------------------------------------
// Mask dtype probe (proven)
// ---------------------------------------------------------------------------
__global__ void detect_mask_kernel(const unsigned char* __restrict__ m) {
    __shared__ int any;
    if (threadIdx.x == 0) any = 0;
    __syncthreads();
    int found = 0;
    for (int i = threadIdx.x; i < 16384; i += 256)
        if (m[4 * i + 1] != 0) found = 1;
    if (found) atomicOr(&any, 1);
    __syncthreads();
    if (threadIdx.x == 0) g_mask_is_byte = any;
}

__global__ void expand_mask_kernel(const void* __restrict__ mraw) {
    int idx = blockIdx.x * blockDim.x + threadIdx.x;
    if (idx >= S_ * S_) return;
    unsigned char v;
    if (g_mask_is_byte) v = (((const unsigned char*)mraw)[idx] != 0) ? 1 : 0;
    else                v = (((const int*)mraw)[idx] != 0) ? 1 : 0;
    g_mask8[idx] = v;
}

// ---------------------------------------------------------------------------
// Prep: split X (fp32) -> bf16 big + bf16 residual
// ---------------------------------------------------------------------------
__global__ void split_x_kernel(const float4* __restrict__ srcext, int xsel) {
    const float4* src = xsel ? g_ctx4 : srcext;
    size_t i = (size_t)blockIdx.x * 256 + threadIdx.x;
    float4 x = src[i];
    __nv_bfloat16 h0x = __float2bfloat16(x.x);
    __nv_bfloat16 h0y = __float2bfloat16(x.y);
    __nv_bfloat16 h0z = __float2bfloat16(x.z);
    __nv_bfloat16 h0w = __float2bfloat16(x.w);
    float rx = x.x - __bfloat162float(h0x);
    float ry = x.y - __bfloat162float(h0y);
    float rz = x.z - __bfloat162float(h0z);
    float rw = x.w - __bfloat162float(h0w);
    __nv_bfloat162 b0a; b0a.x = h0x; b0a.y = h0y;
    __nv_bfloat162 b0b; b0b.x = h0z; b0b.y = h0w;
    __nv_bfloat162 b1a = __floats2bfloat162_rn(rx, ry);
    __nv_bfloat162 b1b = __floats2bfloat162_rn(rz, rw);
    uint2 u0, u1;
    u0.x = *(uint32_t*)&b0a; u0.y = *(uint32_t*)&b0b;
    u1.x = *(uint32_t*)&b1a; u1.y = *(uint32_t*)&b1b;
    g_xb0[i] = u0;
    g_xb1[i] = u1;
}

// Prep: WT[n][k] = W[k][n], split to bf16 pairs. grid (32,32), block (32,8).
__global__ void split_wt_kernel(const float* __restrict__ W) {
    __shared__ float t[32][33];
    const int tx = threadIdx.x, ty = threadIdx.y;
    const int n0 = blockIdx.x * 32, k0 = blockIdx.y * 32;
    __nv_bfloat16* wb0 = (__nv_bfloat16*)g_wtb0;
    __nv_bfloat16* wb1 = (__nv_bfloat16*)g_wtb1;
#pragma unroll
    for (int j = 0; j < 32; j += 8)
        t[ty + j][tx] = W[(size_t)(k0 + ty + j) * D_ + n0 + tx];
    __syncthreads();
#pragma unroll
    for (int j = 0; j < 32; j += 8) {
        float v = t[tx][ty + j];                 // = W[k0+tx][n0+ty+j]
        __nv_bfloat16 b = __float2bfloat16(v);
        float r = v - __bfloat162float(b);
        size_t o = (size_t)(n0 + ty + j) * D_ + k0 + tx;
        wb0[o] = b;
        wb1[o] = __float2bfloat16(r);
    }
}

// ---------------------------------------------------------------------------
// bf16x3 mma.sync GEMM: Y[8192,1024] = X @ W + bias
// CTA 128x128, BK=32, 2-stage cp.async pipeline.
// Smem tiles: Ab0, Ab1, Bb0, Bb1 each [128 rows][32 bf16] padded to 80B/row.
// 8 warps (2m x 4n), warp tile 64x32, fragments m16n8k16.
// ---------------------------------------------------------------------------
#define TPB  10240                 // tile bytes: 128 * 80
#define STGB (4 * TPB)             // stage bytes: 40960
#define GSMEM (2 * STGB)           // 81920

__global__ __launch_bounds__(256)
void mma_gemm_kernel(const float* __restrict__ bias,
                     float* __restrict__ Yext, int ysel)
{
    extern __shared__ char sm[];
    const uint32_t sbase = smem_u32(sm);

    const int tid  = threadIdx.x;
    const int wid  = tid >> 5;
    const int lane = tid & 31;
    const int wm   = wid >> 2;       // 0..1
    const int wn   = wid & 3;        // 0..3
    const int m0   = blockIdx.y * 128;
    const int n0   = blockIdx.x * 128;

    // cp.async mapping: 512 16B-segments per tile, 2 iters of 256 threads
    const int lrow0 = tid >> 2;             // rows 0..63   (iter 0)
    const int lseg  = (tid & 3) * 16;       // byte seg within 64B row data

    const char* pxb0 = (const char*)g_xb0;
    const char* pxb1 = (const char*)g_xb1;
    const char* pwb0 = (const char*)g_wtb0;
    const char* pwb1 = (const char*)g_wtb1;

    float c[4][4][4];
#pragma unroll
    for (int i = 0; i < 4; i++)
#pragma unroll
        for (int j = 0; j < 4; j++)
#pragma unroll
            for (int r = 0; r < 4; r++) c[i][j][r] = 0.0f;

    // ---- stage loader ----
#define LOAD_STAGE(st, kt) do {                                               \
    const uint32_t sb = sbase + (st) * STGB;                                  \
    const int kbyte = (kt) * 64;  /* 32 bf16 = 64B */                         \
    _Pragma("unroll")                                                         \
    for (int it = 0; it < 2; it++) {                                          \
        const int row = lrow0 + it * 64;                                      \
        const uint32_t doff = (uint32_t)(row * 80 + lseg);                    \
        const size_t gx = (size_t)(m0 + row) * 2048 + kbyte + lseg;           \
        const size_t gw = (size_t)(n0 + row) * 2048 + kbyte + lseg;           \
        CP_ASYNC16(sb + 0 * TPB + doff, pxb0 + gx);                           \
        CP_ASYNC16(sb + 1 * TPB + doff, pxb1 + gx);                           \
        CP_ASYNC16(sb + 2 * TPB + doff, pwb0 + gw);                           \
        CP_ASYNC16(sb + 3 * TPB + doff, pwb1 + gw);                           \
    }                                                                         \
    CP_COMMIT();                                                              \
} while (0)

    // ldmatrix lane offsets
    const uint32_t aoffs = (uint32_t)((lane & 15) * 80 + (lane >> 4) * 16);
    const uint32_t boffs = (uint32_t)(((lane >> 4) * 8 + (lane & 7)) * 80 +
                                      ((lane >> 3) & 1) * 16);

    LOAD_STAGE(0, 0);

    const int NT = D_ / 32;   // 32 k-tiles
    for (int kt = 0; kt < NT; kt++) {
        if (kt + 1 < NT) { LOAD_STAGE((kt + 1) & 1, kt + 1); CP_WAIT1(); }
        else             { CP_WAIT0(); }
        __syncthreads();

        const uint32_t sb = sbase + (kt & 1) * STGB;

#pragma unroll
        for (int ks = 0; ks < 2; ks++) {
            const uint32_t kb = (uint32_t)(ks * 32);

            uint32_t a0[4][4], a1[4][4];
#pragma unroll
            for (int i = 0; i < 4; i++) {
                const uint32_t ad =
                    sb + (uint32_t)((wm * 64 + 16 * i) * 80) + aoffs + kb;
                ldsm4(a0[i], ad);
                ldsm4(a1[i], ad + TPB);
            }
            uint32_t b0r[4][2], b1r[4][2];
#pragma unroll
            for (int p = 0; p < 2; p++) {
                const uint32_t bd =
                    sb + 2 * TPB + (uint32_t)((wn * 32 + 16 * p) * 80) + boffs + kb;
                uint32_t t0[4], t1[4];
                ldsm4(t0, bd);
                ldsm4(t1, bd + TPB);
                b0r[2 * p][0] = t0[0]; b0r[2 * p][1] = t0[1];
                b0r[2 * p + 1][0] = t0[2]; b0r[2 * p + 1][1] = t0[3];
                b1r[2 * p][0] = t1[0]; b1r[2 * p][1] = t1[1];
                b1r[2 * p + 1][0] = t1[2]; b1r[2 * p + 1][1] = t1[3];
            }
#pragma unroll
            for (int i = 0; i < 4; i++)
#pragma unroll
                for (int j = 0; j < 4; j++) {
                    mma_bf16(c[i][j], a0[i], b0r[j]);   // big*big
                    mma_bf16(c[i][j], a0[i], b1r[j]);   // big*small
                    mma_bf16(c[i][j], a1[i], b0r[j]);   // small*big
                }
        }
        __syncthreads();   // stage consumed; next iter may overwrite it
    }

    // ---- epilogue: bias + store (row-major or split-heads) ----
    float* dst = (ysel == 1) ? (float*)g_q4
               : (ysel == 2) ? (float*)g_k4
               : (ysel == 3) ? (float*)g_v4 : Yext;

#pragma unroll
    for (int i = 0; i < 4; i++) {
        const int r0 = m0 + wm * 64 + 16 * i + (lane >> 2);
#pragma unroll
        for (int j = 0; j < 4; j++) {
            const int colp = n0 + wn * 32 + 8 * j + 2 * (lane & 3);
            const float bx = bias[colp], by = bias[colp + 1];
            float2 v0 = {c[i][j][0] + bx, c[i][j][1] + by};
            float2 v1 = {c[i][j][2] + bx, c[i][j][3] + by};
            if (ysel == 0) {
                *(float2*)&dst[(size_t)r0 * D_ + colp] = v0;
                *(float2*)&dst[(size_t)(r0 + 8) * D_ + colp] = v1;
            } else {
                const int h = colp >> 6;
                const int d = colp & 63;
                {
                    const int bb = r0 >> 11, s = r0 & (S_ - 1);
                    *(float2*)&dst[((size_t)(bb * H_ + h) * S_ + s) * HD_ + d] = v0;
                }
                {
                    const int r1 = r0 + 8;
                    const int bb = r1 >> 11, s = r1 & (S_ - 1);
                    *(float2*)&dst[((size_t)(bb * H_ + h) * S_ + s) * HD_ + d] = v1;
                }
            }
        }
    }
#undef LOAD_STAGE
}

// ---------------------------------------------------------------------------
// Flash attention (unchanged from R2 — proven at 3744us total)
// ---------------------------------------------------------------------------
#define AQ 64
#define AK 64
#define QKST 68
#define QOFF 0
#define KPOFF (AQ * QKST)
#define VOFF  (KPOFF + AK * QKST)
#define ATTN_SMEM_FLOATS (VOFF + AK * HD_)

__global__ __launch_bounds__(256, 2)
void attn_kernel()
{
    extern __shared__ float smf[];

    const int tid = threadIdx.x;
    const int ty  = tid >> 4;
    const int tx  = tid & 15;
    const int q0  = blockIdx.x * AQ;
    const int bh  = blockIdx.y;

    const float* Qp = (const float*)g_q4 + (size_t)bh * S_ * HD_;
    const float* Kp = (const float*)g_k4 + (size_t)bh * S_ * HD_;
    const float* Vp = (const float*)g_v4 + (size_t)bh * S_ * HD_;

    for (int t = tid; t < AQ * HD_; t += 256) {
        int r = t >> 6, d = t & 63;
        smf[QOFF + r * QKST + d] = Qp[(size_t)(q0 + r) * HD_ + d];
    }

    float m_run[4], l_run[4], acc[4][4];
#pragma unroll
    for (int i = 0; i < 4; i++) {
        m_run[i] = -INFINITY; l_run[i] = 0.0f;
#pragma unroll
        for (int jd = 0; jd < 4; jd++) acc[i][jd] = 0.0f;
    }

    for (int k0 = 0; k0 < S_; k0 += AK) {
        __syncthreads();

        for (int t = tid; t < AK * HD_; t += 256) {
            int cc = t >> 6, d = t & 63;
            smf[KPOFF + cc * QKST + d] = Kp[(size_t)(k0 + cc) * HD_ + d];
            smf[VOFF  + cc * HD_  + d] = Vp[(size_t)(k0 + cc) * HD_ + d];
        }
        __syncthreads();

        float s[4][4];
#pragma unroll
        for (int i = 0; i < 4; i++)
#pragma unroll
            for (int j = 0; j < 4; j++) s[i][j] = 0.0f;

#pragma unroll 8
        for (int d4 = 0; d4 < HD_ / 4; d4++) {
            float4 qv[4], kv[4];
#pragma unroll
            for (int i = 0; i < 4; i++)
                qv[i] = *(const float4*)&smf[QOFF + (4 * ty + i) * QKST + d4 * 4];
#pragma unroll
            for (int j = 0; j < 4; j++)
                kv[j] = *(const float4*)&smf[KPOFF + (tx + 16 * j) * QKST + d4 * 4];
#pragma unroll
            for (int i = 0; i < 4; i++)
#pragma unroll
                for (int j = 0; j < 4; j++) {
                    s[i][j] = fmaf(qv[i].x, kv[j].x, s[i][j]);
                    s[i][j] = fmaf(qv[i].y, kv[j].y, s[i][j]);
                    s[i][j] = fmaf(qv[i].z, kv[j].z, s[i][j]);
                    s[i][j] = fmaf(qv[i].w, kv[j].w, s[i][j]);
                }
        }

#pragma unroll
        for (int i = 0; i < 4; i++) {
            const unsigned char* mrow =
                &g_mask8[(size_t)(q0 + 4 * ty + i) * S_ + k0];
#pragma unroll
            for (int j = 0; j < 4; j++)
                s[i][j] = mrow[tx + 16 * j] ? s[i][j] * SCALE_ : -1e30f;
        }

        float tmax[4];
#pragma unroll
        for (int i = 0; i < 4; i++)
            tmax[i] = fmaxf(fmaxf(s[i][0], s[i][1]), fmaxf(s[i][2], s[i][3]));
#pragma unroll
        for (int off = 1; off < 16; off <<= 1)
#pragma unroll
            for (int i = 0; i < 4; i++)
                tmax[i] = fmaxf(tmax[i], __shfl_xor_sync(0xffffffffu, tmax[i], off));

        float tsum[4];
#pragma unroll
        for (int i = 0; i < 4; i++) {
            float mnew = fmaxf(m_run[i], tmax[i]);
            float corr = __expf(m_run[i] - mnew);
            m_run[i] = mnew;
            float t0 = __expf(s[i][0] - mnew);
            float t1 = __expf(s[i][1] - mnew);
            float t2 = __expf(s[i][2] - mnew);
            float t3 = __expf(s[i][3] - mnew);
            s[i][0] = t0; s[i][1] = t1; s[i][2] = t2; s[i][3] = t3;
            tsum[i] = (t0 + t1) + (t2 + t3);
            l_run[i] *= corr;
#pragma unroll
            for (int jd = 0; jd < 4; jd++) acc[i][jd] *= corr;
        }
#pragma unroll
        for (int off = 1; off < 16; off <<= 1)
#pragma unroll
            for (int i = 0; i < 4; i++)
                tsum[i] += __shfl_xor_sync(0xffffffffu, tsum[i], off);
#pragma unroll
        for (int i = 0; i < 4; i++) l_run[i] += tsum[i];

        __syncthreads();
#pragma unroll
        for (int i = 0; i < 4; i++)
#pragma unroll
            for (int j = 0; j < 4; j++)
                smf[KPOFF + (4 * ty + i) * QKST + tx + 16 * j] = s[i][j];
        __syncthreads();

#pragma unroll 4
        for (int c0 = 0; c0 < AK; c0 += 4) {
            float prr[4][4];
#pragma unroll
            for (int i = 0; i < 4; i++) {
                float4 t = *(const float4*)&smf[KPOFF + (4 * ty + i) * QKST + c0];
                prr[i][0] = t.x; prr[i][1] = t.y; prr[i][2] = t.z; prr[i][3] = t.w;
            }
#pragma unroll
            for (int cc = 0; cc < 4; cc++) {
                float vv[4];
#pragma unroll
                for (int jd = 0; jd < 4; jd++)
                    vv[jd] = smf[VOFF + (c0 + cc) * HD_ + tx + 16 * jd];
#pragma unroll
                for (int i = 0; i < 4; i++)
#pragma unroll
                    for (int jd = 0; jd < 4; jd++)
                        acc[i][jd] = fmaf(prr[i][cc], vv[jd], acc[i][jd]);
            }
        }
    }

    const int b = bh >> 4;
    const int h = bh & 15;
    float* ctx = (float*)g_ctx4;
#pragma unroll
    for (int i = 0; i < 4; i++) {
        const float inv = 1.0f / l_run[i];
        const int r = q0 + 4 * ty + i;
#pragma unroll
        for (int jd = 0; jd < 4; jd++)
            ctx[((size_t)b * S_ + r) * D_ + h * HD_ + tx + 16 * jd] =
                acc[i][jd] * inv;
    }
}

// ---------------------------------------------------------------------------
// Launch
// ---------------------------------------------------------------------------
extern "C" void kernel_launch(void* const* d_in, const int* in_sizes, int n_in,
                              void* d_out, int out_size)
{
    const float* queries = (const float*)d_in[0];
    const float* keys    = (const float*)d_in[1];
    const float* values  = (const float*)d_in[2];
    const void*  mask    = d_in[3];
    const float* Wq = (const float*)d_in[4];
    const float* bq = (const float*)d_in[5];
    const float* Wk = (const float*)d_in[6];
    const float* bk = (const float*)d_in[7];
    const float* Wv = (const float*)d_in[8];
    const float* bv = (const float*)d_in[9];
    const float* Wo = (const float*)d_in[10];
    const float* bo = (const float*)d_in[11];
    float* out = (float*)d_out;

    (void)in_sizes; (void)n_in; (void)out_size;

    cudaFuncSetAttribute(mma_gemm_kernel,
                         cudaFuncAttributeMaxDynamicSharedMemorySize, GSMEM);
    cudaFuncSetAttribute(attn_kernel,
                         cudaFuncAttributeMaxDynamicSharedMemorySize,
                         ATTN_SMEM_FLOATS * (int)sizeof(float));

    detect_mask_kernel<<<1, 256>>>((const unsigned char*)mask);
    expand_mask_kernel<<<(S_ * S_ + 255) / 256, 256>>>(mask);

    const dim3 ggrid(D_ / 128, (B_ * S_) / 128);    // (8, 64)
    const dim3 tgrid(32, 32);
    const dim3 tblk(32, 8);
    const int  xblocks = (B_ * S_ * D_ / 4) / 256;  // 8192

    // Q
    split_wt_kernel<<<tgrid, tblk>>>(Wq);
    split_x_kernel<<<xblocks, 256>>>((const float4*)queries, 0);
    mma_gemm_kernel<<<ggrid, 256, GSMEM>>>(bq, nullptr, 1);
    // K
    split_wt_kernel<<<tgrid, tblk>>>(Wk);
    split_x_kernel<<<xblocks, 256>>>((const float4*)keys, 0);
    mma_gemm_kernel<<<ggrid, 256, GSMEM>>>(bk, nullptr, 2);
    // V
    split_wt_kernel<<<tgrid, tblk>>>(Wv);
    split_x_kernel<<<xblocks, 256>>>((const float4*)values, 0);
    mma_gemm_kernel<<<ggrid, 256, GSMEM>>>(bv, nullptr, 3);

    // attention
    dim3 agrid(S_ / AQ, B_ * H_);
    attn_kernel<<<agrid, 256, ATTN_SMEM_FLOATS * (int)sizeof(float)>>>();

    // O projection
    split_wt_kernel<<<tgrid, tblk>>>(Wo);
    split_x_kernel<<<xblocks, 256>>>(nullptr, 1);
    mma_gemm_kernel<<<ggrid, 256, GSMEM>>>(bo, out, 0);
}

// round 5
// speedup vs baseline: 2.7769x; 1.7552x over previous
#include <cuda_runtime.h>
#include <cuda_bf16.h>
#include <math.h>
#include <stdint.h>

#define B_  4
#define S_  2048
#define D_  1024
#define H_  16
#define HD_ 64
#define SCALE_ 0.125f   // 1/sqrt(64)

// ---------------------------------------------------------------------------
// Scratch (allocation-free __device__ globals)
// ---------------------------------------------------------------------------
__device__ uint2 g_xb0[(size_t)B_ * S_ * D_ / 4];   // bf16 X big   [8192][1024]
__device__ uint2 g_xb1[(size_t)B_ * S_ * D_ / 4];   // bf16 X small
__device__ uint2 g_wtb0[(size_t)D_ * D_ / 4];       // bf16 W^T big [n][k]
__device__ uint2 g_wtb1[(size_t)D_ * D_ / 4];       // bf16 W^T small
__device__ uint2 g_qb0[(size_t)B_ * H_ * S_ * HD_ / 4];  // bf16 (B,H,S,HD)
__device__ uint2 g_qb1[(size_t)B_ * H_ * S_ * HD_ / 4];
__device__ uint2 g_kb0[(size_t)B_ * H_ * S_ * HD_ / 4];
__device__ uint2 g_kb1[(size_t)B_ * H_ * S_ * HD_ / 4];
__device__ uint2 g_vb0[(size_t)B_ * H_ * S_ * HD_ / 4];
__device__ uint2 g_vb1[(size_t)B_ * H_ * S_ * HD_ / 4];
__device__ unsigned char g_mask8[(size_t)S_ * S_];
__device__ int g_mask_is_byte;

// ---------------------------------------------------------------------------
// PTX helpers (sm_80-era: valid on plain compute_100 target)
// ---------------------------------------------------------------------------
__device__ __forceinline__ uint32_t smem_u32(const void* p) {
    uint32_t a;
    asm("{ .reg .u64 t; cvta.to.shared.u64 t, %1; cvt.u32.u64 %0, t; }"
        : "=r"(a) : "l"(p));
    return a;
}
#define CP_ASYNC16(dst, src) \
    asm volatile("cp.async.cg.shared.global [%0], [%1], 16;" \
                 :: "r"(dst), "l"(src) : "memory")
#define CP_COMMIT()  asm volatile("cp.async.commit_group;" ::: "memory")
#define CP_WAIT1()   asm volatile("cp.async.wait_group 1;" ::: "memory")
#define CP_WAIT0()   asm volatile("cp.async.wait_group 0;" ::: "memory")

__device__ __forceinline__ void ldsm4(uint32_t* r, uint32_t addr) {
    asm volatile("ldmatrix.sync.aligned.m8n8.x4.shared.b16 {%0,%1,%2,%3}, [%4];"
                 : "=r"(r[0]), "=r"(r[1]), "=r"(r[2]), "=r"(r[3]) : "r"(addr));
}
__device__ __forceinline__ void ldsm4t(uint32_t* r, uint32_t addr) {
    asm volatile("ldmatrix.sync.aligned.m8n8.x4.trans.shared.b16 {%0,%1,%2,%3}, [%4];"
                 : "=r"(r[0]), "=r"(r[1]), "=r"(r[2]), "=r"(r[3]) : "r"(addr));
}
__device__ __forceinline__ void mma_bf16(float* c, const uint32_t* a,
                                         const uint32_t* b) {
    asm volatile(
        "mma.sync.aligned.m16n8k16.row.col.f32.bf16.bf16.f32 "
        "{%0,%1,%2,%3}, {%4,%5,%6,%7}, {%8,%9}, {%0,%1,%2,%3};"
        : "+f"(c[0]), "+f"(c[1]), "+f"(c[2]), "+f"(c[3])
        : "r"(a[0]), "r"(a[1]), "r"(a[2]), "r"(a[3]), "r"(b[0]), "r"(b[1]));
}

// exp(d) for d <= 0 on the FMA pipe (no MUFU). rel err ~2.4e-6.
__device__ __forceinline__ float exp_nm(float d) {
    float y = fmaxf(d * 1.4426950408889634f, -80.0f);
    float fi = rintf(y);
    float f = y - fi;                       // [-0.5, 0.5]
    float p = 0.0013333558f;
    p = fmaf(p, f, 0.0096181291f);
    p = fmaf(p, f, 0.0555041087f);
    p = fmaf(p, f, 0.2402265070f);
    p = fmaf(p, f, 0.6931471806f);
    p = fmaf(p, f, 1.0f);
    return p * __int_as_float(((int)fi + 127) << 23);
}

// ---------------------------------------------------------------------------
// Mask dtype probe (proven)
// ---------------------------------------------------------------------------
__global__ void detect_mask_kernel(const unsigned char* __restrict__ m) {
    __shared__ int any;
    if (threadIdx.x == 0) any = 0;
    __syncthreads();
    int found = 0;
    for (int i = threadIdx.x; i < 16384; i += 256)
        if (m[4 * i + 1] != 0) found = 1;
    if (found) atomicOr(&any, 1);
    __syncthreads();
    if (threadIdx.x == 0) g_mask_is_byte = any;
}

__global__ void expand_mask_kernel(const void* __restrict__ mraw) {
    int idx = blockIdx.x * blockDim.x + threadIdx.x;
    if (idx >= S_ * S_) return;
    unsigned char v;
    if (g_mask_is_byte) v = (((const unsigned char*)mraw)[idx] != 0) ? 1 : 0;
    else                v = (((const int*)mraw)[idx] != 0) ? 1 : 0;
    g_mask8[idx] = v;
}

// ---------------------------------------------------------------------------
// Prep: split X (fp32) -> bf16 big + bf16 residual
// ---------------------------------------------------------------------------
__global__ void split_x_kernel(const float4* __restrict__ src) {
    size_t i = (size_t)blockIdx.x * 256 + threadIdx.x;
    float4 x = src[i];
    __nv_bfloat16 h0x = __float2bfloat16(x.x);
    __nv_bfloat16 h0y = __float2bfloat16(x.y);
    __nv_bfloat16 h0z = __float2bfloat16(x.z);
    __nv_bfloat16 h0w = __float2bfloat16(x.w);
    float rx = x.x - __bfloat162float(h0x);
    float ry = x.y - __bfloat162float(h0y);
    float rz = x.z - __bfloat162float(h0z);
    float rw = x.w - __bfloat162float(h0w);
    __nv_bfloat162 b0a; b0a.x = h0x; b0a.y = h0y;
    __nv_bfloat162 b0b; b0b.x = h0z; b0b.y = h0w;
    __nv_bfloat162 b1a = __floats2bfloat162_rn(rx, ry);
    __nv_bfloat162 b1b = __floats2bfloat162_rn(rz, rw);
    uint2 u0, u1;
    u0.x = *(uint32_t*)&b0a; u0.y = *(uint32_t*)&b0b;
    u1.x = *(uint32_t*)&b1a; u1.y = *(uint32_t*)&b1b;
    g_xb0[i] = u0;
    g_xb1[i] = u1;
}

// Prep: WT[n][k] = W[k][n], split to bf16 pairs. grid (32,32), block (32,8).
__global__ void split_wt_kernel(const float* __restrict__ W) {
    __shared__ float t[32][33];
    const int tx = threadIdx.x, ty = threadIdx.y;
    const int n0 = blockIdx.x * 32, k0 = blockIdx.y * 32;
    __nv_bfloat16* wb0 = (__nv_bfloat16*)g_wtb0;
    __nv_bfloat16* wb1 = (__nv_bfloat16*)g_wtb1;
#pragma unroll
    for (int j = 0; j < 32; j += 8)
        t[ty + j][tx] = W[(size_t)(k0 + ty + j) * D_ + n0 + tx];
    __syncthreads();
#pragma unroll
    for (int j = 0; j < 32; j += 8) {
        float v = t[tx][ty + j];
        __nv_bfloat16 b = __float2bfloat16(v);
        float r = v - __bfloat162float(b);
        size_t o = (size_t)(n0 + ty + j) * D_ + k0 + tx;
        wb0[o] = b;
        wb1[o] = __float2bfloat16(r);
    }
}

// ---------------------------------------------------------------------------
// bf16x3 mma.sync GEMM (proven R4 core). Epilogue:
//   ysel 0  -> fp32 Y + bias (d_out)
//   ysel 1..3 -> bf16 big/small split-heads into g_{q,k,v}b{0,1}; Q scaled.
// ---------------------------------------------------------------------------
#define TPB  10240
#define STGB (4 * TPB)
#define GSMEM (2 * STGB)

__global__ __launch_bounds__(256)
void mma_gemm_kernel(const float* __restrict__ bias,
                     float* __restrict__ Yext, int ysel)
{
    extern __shared__ char sm[];
    const uint32_t sbase = smem_u32(sm);

    const int tid  = threadIdx.x;
    const int wid  = tid >> 5;
    const int lane = tid & 31;
    const int wm   = wid >> 2;
    const int wn   = wid & 3;
    const int m0   = blockIdx.y * 128;
    const int n0   = blockIdx.x * 128;

    const int lrow0 = tid >> 2;
    const int lseg  = (tid & 3) * 16;

    const char* pxb0 = (const char*)g_xb0;
    const char* pxb1 = (const char*)g_xb1;
    const char* pwb0 = (const char*)g_wtb0;
    const char* pwb1 = (const char*)g_wtb1;

    float c[4][4][4];
#pragma unroll
    for (int i = 0; i < 4; i++)
#pragma unroll
        for (int j = 0; j < 4; j++)
#pragma unroll
            for (int r = 0; r < 4; r++) c[i][j][r] = 0.0f;

#define LOAD_STAGE(st, kt) do {                                               \
    const uint32_t sb = sbase + (st) * STGB;                                  \
    const int kbyte = (kt) * 64;                                              \
    _Pragma("unroll")                                                         \
    for (int it = 0; it < 2; it++) {                                          \
        const int row = lrow0 + it * 64;                                      \
        const uint32_t doff = (uint32_t)(row * 80 + lseg);                    \
        const size_t gx = (size_t)(m0 + row) * 2048 + kbyte + lseg;           \
        const size_t gw = (size_t)(n0 + row) * 2048 + kbyte + lseg;           \
        CP_ASYNC16(sb + 0 * TPB + doff, pxb0 + gx);                           \
        CP_ASYNC16(sb + 1 * TPB + doff, pxb1 + gx);                           \
        CP_ASYNC16(sb + 2 * TPB + doff, pwb0 + gw);                           \
        CP_ASYNC16(sb + 3 * TPB + doff, pwb1 + gw);                           \
    }                                                                         \
    CP_COMMIT();                                                              \
} while (0)

    const uint32_t aoffs = (uint32_t)((lane & 15) * 80 + (lane >> 4) * 16);
    const uint32_t boffs = (uint32_t)(((lane >> 4) * 8 + (lane & 7)) * 80 +
                                      ((lane >> 3) & 1) * 16);

    LOAD_STAGE(0, 0);

    const int NT = D_ / 32;
    for (int kt = 0; kt < NT; kt++) {
        if (kt + 1 < NT) { LOAD_STAGE((kt + 1) & 1, kt + 1); CP_WAIT1(); }
        else             { CP_WAIT0(); }
        __syncthreads();

        const uint32_t sb = sbase + (kt & 1) * STGB;

#pragma unroll
        for (int ks = 0; ks < 2; ks++) {
            const uint32_t kb = (uint32_t)(ks * 32);

            uint32_t a0[4][4], a1[4][4];
#pragma unroll
            for (int i = 0; i < 4; i++) {
                const uint32_t ad =
                    sb + (uint32_t)((wm * 64 + 16 * i) * 80) + aoffs + kb;
                ldsm4(a0[i], ad);
                ldsm4(a1[i], ad + TPB);
            }
            uint32_t b0r[4][2], b1r[4][2];
#pragma unroll
            for (int p = 0; p < 2; p++) {
                const uint32_t bd =
                    sb + 2 * TPB + (uint32_t)((wn * 32 + 16 * p) * 80) + boffs + kb;
                uint32_t t0[4], t1[4];
                ldsm4(t0, bd);
                ldsm4(t1, bd + TPB);
                b0r[2 * p][0] = t0[0]; b0r[2 * p][1] = t0[1];
                b0r[2 * p + 1][0] = t0[2]; b0r[2 * p + 1][1] = t0[3];
                b1r[2 * p][0] = t1[0]; b1r[2 * p][1] = t1[1];
                b1r[2 * p + 1][0] = t1[2]; b1r[2 * p + 1][1] = t1[3];
            }
#pragma unroll
            for (int i = 0; i < 4; i++)
#pragma unroll
                for (int j = 0; j < 4; j++) {
                    mma_bf16(c[i][j], a0[i], b0r[j]);
                    mma_bf16(c[i][j], a0[i], b1r[j]);
                    mma_bf16(c[i][j], a1[i], b0r[j]);
                }
        }
        __syncthreads();
    }

    // ---- epilogue ----
    if (ysel == 0) {
#pragma unroll
        for (int i = 0; i < 4; i++) {
            const int r0 = m0 + wm * 64 + 16 * i + (lane >> 2);
#pragma unroll
            for (int j = 0; j < 4; j++) {
                const int colp = n0 + wn * 32 + 8 * j + 2 * (lane & 3);
                const float bx = bias[colp], by = bias[colp + 1];
                float2 v0 = {c[i][j][0] + bx, c[i][j][1] + by};
                float2 v1 = {c[i][j][2] + bx, c[i][j][3] + by};
                *(float2*)&Yext[(size_t)r0 * D_ + colp] = v0;
                *(float2*)&Yext[(size_t)(r0 + 8) * D_ + colp] = v1;
            }
        }
    } else {
        uint32_t* d0 = (ysel == 1) ? (uint32_t*)g_qb0
                     : (ysel == 2) ? (uint32_t*)g_kb0 : (uint32_t*)g_vb0;
        uint32_t* d1 = (ysel == 1) ? (uint32_t*)g_qb1
                     : (ysel == 2) ? (uint32_t*)g_kb1 : (uint32_t*)g_vb1;
        const float scl = (ysel == 1) ? SCALE_ : 1.0f;
#pragma unroll
        for (int i = 0; i < 4; i++) {
            const int r0 = m0 + wm * 64 + 16 * i + (lane >> 2);
#pragma unroll
            for (int j = 0; j < 4; j++) {
                const int colp = n0 + wn * 32 + 8 * j + 2 * (lane & 3);
                const float bx = bias[colp], by = bias[colp + 1];
                const int h = colp >> 6;
                const int d = colp & 63;
#pragma unroll
                for (int half = 0; half < 2; half++) {
                    const int rr = r0 + 8 * half;
                    const int bb = rr >> 11, s = rr & (S_ - 1);
                    float vx = (c[i][j][2 * half + 0] + bx) * scl;
                    float vy = (c[i][j][2 * half + 1] + by) * scl;
                    __nv_bfloat162 hb = __floats2bfloat162_rn(vx, vy);
                    __nv_bfloat162 hs = __floats2bfloat162_rn(
                        vx - __bfloat162float(hb.x), vy - __bfloat162float(hb.y));
                    size_t idx =
                        (((size_t)(bb * H_ + h) * S_ + s) * HD_ + d) >> 1;
                    d0[idx] = *(uint32_t*)&hb;
                    d1[idx] = *(uint32_t*)&hs;
                }
            }
        }
    }
#undef LOAD_STAGE
}

// ---------------------------------------------------------------------------
// Tensor-core flash attention: BQ=128 (8 warps x m16), BK=64.
// QK^T and PV via bf16 mma with 2-term error correction; exp on FMA pipe.
// Smem: 2 KV stages of {Kb0,Kb1,Vb0,Vb1} 64x144B each (rows padded 128->144).
// ---------------------------------------------------------------------------
#define ATT_ROWB 144
#define ATT_TILE (64 * ATT_ROWB)       // 9216
#define ATT_STAGE (4 * ATT_TILE)       // 36864
#define ATT_SMEM (2 * ATT_STAGE)       // 73728

__global__ __launch_bounds__(256)
void attn_mma_kernel()
{
    extern __shared__ char sm[];
    const uint32_t sb = smem_u32(sm);

    const int tid  = threadIdx.x;
    const int wid  = tid >> 5;
    const int lane = tid & 31;
    const int q0   = blockIdx.x * 128;
    const int bh   = blockIdx.y;

    const size_t off = (size_t)bh * S_ * HD_ * 2;  // bytes
    const char* pq0 = (const char*)g_qb0 + off;
    const char* pq1 = (const char*)g_qb1 + off;
    const char* pk0 = (const char*)g_kb0 + off;
    const char* pk1 = (const char*)g_kb1 + off;
    const char* pv0 = (const char*)g_vb0 + off;
    const char* pv1 = (const char*)g_vb1 + off;

    // ---- stage Q (128x64 bf16 x2) through stage0, load fragments ----
#pragma unroll
    for (int sg = 0; sg < 4; sg++) {
        const int seg = tid + 256 * sg;          // 1024 segs per set
        const int row = seg >> 3, c16 = seg & 7;
        const size_t gsrc = (size_t)(q0 + row) * 128 + c16 * 16;
        const uint32_t dd = (uint32_t)(row * ATT_ROWB + c16 * 16);
        CP_ASYNC16(sb + dd, pq0 + gsrc);
        CP_ASYNC16(sb + 18432 + dd, pq1 + gsrc);
    }
    CP_COMMIT(); CP_WAIT0(); __syncthreads();

    uint32_t qbf[4][4], qsf[4][4];
    {
        const uint32_t ao = (uint32_t)((wid * 16 + (lane & 15)) * ATT_ROWB +
                                       (lane >> 4) * 16);
#pragma unroll
        for (int kf = 0; kf < 4; kf++) {
            ldsm4(qbf[kf], sb + ao + kf * 32);
            ldsm4(qsf[kf], sb + 18432 + ao + kf * 32);
        }
    }
    __syncthreads();

    float acc[8][4];
#pragma unroll
    for (int nf = 0; nf < 8; nf++)
#pragma unroll
        for (int e = 0; e < 4; e++) acc[nf][e] = 0.0f;
    float mrun0 = -INFINITY, mrun1 = -INFINITY, lrun0 = 0.0f, lrun1 = 0.0f;

    // KV loader: 8 cp.async per thread (4 sets x 2 segs)
#define LOAD_KV(st, t) do {                                                   \
    const uint32_t stg_ = sb + (st) * ATT_STAGE;                              \
    const int kk0_ = (t) * 64;                                                \
    _Pragma("unroll")                                                         \
    for (int jj = 0; jj < 2; jj++) {                                          \
        const int seg = tid + 256 * jj;                                       \
        const int row = seg >> 3, c16 = seg & 7;                              \
        const size_t gs = (size_t)(kk0_ + row) * 128 + c16 * 16;              \
        const uint32_t dd = (uint32_t)(row * ATT_ROWB + c16 * 16);            \
        CP_ASYNC16(stg_ + 0 * ATT_TILE + dd, pk0 + gs);                       \
        CP_ASYNC16(stg_ + 1 * ATT_TILE + dd, pk1 + gs);                       \
        CP_ASYNC16(stg_ + 2 * ATT_TILE + dd, pv0 + gs);                       \
        CP_ASYNC16(stg_ + 3 * ATT_TILE + dd, pv1 + gs);                       \
    }                                                                         \
    CP_COMMIT();                                                              \
} while (0)

    LOAD_KV(0, 0);

    const uint32_t boff = (uint32_t)(((lane >> 4) * 8 + (lane & 7)) * ATT_ROWB +
                                     ((lane >> 3) & 1) * 16);
    const unsigned char* mbase =
        g_mask8 + (size_t)(q0 + wid * 16 + (lane >> 2)) * S_ + 2 * (lane & 3);

    for (int t = 0; t < S_ / 64; t++) {
        if (t + 1 < S_ / 64) { LOAD_KV((t + 1) & 1, t + 1); CP_WAIT1(); }
        else                 { CP_WAIT0(); }
        __syncthreads();

        const uint32_t stg = sb + (t & 1) * ATT_STAGE;

        // ---- scores: c[nf] over 8 n-frags (s cols), 3-term mma ----
        float c[8][4];
#pragma unroll
        for (int nf = 0; nf < 8; nf++)
#pragma unroll
            for (int e = 0; e < 4; e++) c[nf][e] = 0.0f;

#pragma unroll
        for (int sg = 0; sg < 4; sg++) {
#pragma unroll
            for (int kf = 0; kf < 4; kf++) {
                const uint32_t ka = stg + (uint32_t)(sg * 16 * ATT_ROWB) +
                                    kf * 32 + boff;
                uint32_t tb[4], ts[4];
                ldsm4(tb, ka);
                ldsm4(ts, ka + ATT_TILE);
                mma_bf16(c[2 * sg], qbf[kf], tb);
                mma_bf16(c[2 * sg], qbf[kf], ts);
                mma_bf16(c[2 * sg], qsf[kf], tb);
                mma_bf16(c[2 * sg + 1], qbf[kf], tb + 2);
                mma_bf16(c[2 * sg + 1], qbf[kf], ts + 2);
                mma_bf16(c[2 * sg + 1], qsf[kf], tb + 2);
            }
        }

        // ---- mask (scores already scaled via Q) ----
        const int k0 = t * 64;
#pragma unroll
        for (int nf = 0; nf < 8; nf++) {
            unsigned short u0 = *(const unsigned short*)(mbase + k0 + 8 * nf);
            unsigned short u1 = *(const unsigned short*)(mbase + 8 * S_ + k0 + 8 * nf);
            c[nf][0] = (u0 & 0xFF) ? c[nf][0] : -1e30f;
            c[nf][1] = (u0 >> 8)   ? c[nf][1] : -1e30f;
            c[nf][2] = (u1 & 0xFF) ? c[nf][2] : -1e30f;
            c[nf][3] = (u1 >> 8)   ? c[nf][3] : -1e30f;
        }

        // ---- row max (local + quad shuffle) ----
        float rm0 = -INFINITY, rm1 = -INFINITY;
#pragma unroll
        for (int nf = 0; nf < 8; nf++) {
            rm0 = fmaxf(rm0, fmaxf(c[nf][0], c[nf][1]));
            rm1 = fmaxf(rm1, fmaxf(c[nf][2], c[nf][3]));
        }
        rm0 = fmaxf(rm0, __shfl_xor_sync(0xffffffffu, rm0, 1));
        rm0 = fmaxf(rm0, __shfl_xor_sync(0xffffffffu, rm0, 2));
        rm1 = fmaxf(rm1, __shfl_xor_sync(0xffffffffu, rm1, 1));
        rm1 = fmaxf(rm1, __shfl_xor_sync(0xffffffffu, rm1, 2));

        const float mn0 = fmaxf(mrun0, rm0);
        const float mn1 = fmaxf(mrun1, rm1);
        const float cr0 = exp_nm(mrun0 - mn0);
        const float cr1 = exp_nm(mrun1 - mn1);
        mrun0 = mn0; mrun1 = mn1;

        // ---- p = exp(s - m) (FMA-pipe poly), row sums ----
        float ts0 = 0.0f, ts1 = 0.0f;
#pragma unroll
        for (int nf = 0; nf < 8; nf++) {
            c[nf][0] = exp_nm(c[nf][0] - mn0);
            c[nf][1] = exp_nm(c[nf][1] - mn0);
            c[nf][2] = exp_nm(c[nf][2] - mn1);
            c[nf][3] = exp_nm(c[nf][3] - mn1);
            ts0 += c[nf][0] + c[nf][1];
            ts1 += c[nf][2] + c[nf][3];
        }
        ts0 += __shfl_xor_sync(0xffffffffu, ts0, 1);
        ts0 += __shfl_xor_sync(0xffffffffu, ts0, 2);
        ts1 += __shfl_xor_sync(0xffffffffu, ts1, 1);
        ts1 += __shfl_xor_sync(0xffffffffu, ts1, 2);
        lrun0 = lrun0 * cr0 + ts0;
        lrun1 = lrun1 * cr1 + ts1;

#pragma unroll
        for (int nf = 0; nf < 8; nf++) {
            acc[nf][0] *= cr0; acc[nf][1] *= cr0;
            acc[nf][2] *= cr1; acc[nf][3] *= cr1;
        }

        // ---- PV: split P to bf16 pairs, 3-term mma with V (ldmatrix.trans) ----
#pragma unroll
        for (int kf = 0; kf < 4; kf++) {
            uint32_t pab[4], pas[4];
#pragma unroll
            for (int q = 0; q < 2; q++) {          // n-frag 2kf+q
                const float* pc = c[2 * kf + q];
#pragma unroll
                for (int half = 0; half < 2; half++) {
                    float v0 = pc[2 * half], v1 = pc[2 * half + 1];
                    __nv_bfloat162 hb = __floats2bfloat162_rn(v0, v1);
                    __nv_bfloat162 hs = __floats2bfloat162_rn(
                        v0 - __bfloat162float(hb.x), v1 - __bfloat162float(hb.y));
                    pab[2 * q + half] = *(uint32_t*)&hb;
                    pas[2 * q + half] = *(uint32_t*)&hs;
                }
            }
#pragma unroll
            for (int dg = 0; dg < 4; dg++) {
                const uint32_t va = stg + 2 * ATT_TILE +
                    (uint32_t)((kf * 16 + (lane & 15)) * ATT_ROWB) +
                    dg * 32 + (lane >> 4) * 16;
                uint32_t vb[4], vs[4];
                ldsm4t(vb, va);
                ldsm4t(vs, va + ATT_TILE);
                mma_bf16(acc[2 * dg], pab, vb);
                mma_bf16(acc[2 * dg], pab, vs);
                mma_bf16(acc[2 * dg], pas, vb);
                mma_bf16(acc[2 * dg + 1], pab, vb + 2);
                mma_bf16(acc[2 * dg + 1], pab, vs + 2);
                mma_bf16(acc[2 * dg + 1], pas, vb + 2);
            }
        }
        __syncthreads();
    }

    // ---- epilogue: normalize, split to bf16, write O-projection input ----
    const float inv0 = 1.0f / lrun0;
    const float inv1 = 1.0f / lrun1;
    const int b = bh >> 4;
    const int h = bh & 15;
    const int row0 = q0 + wid * 16 + (lane >> 2);
    uint32_t* xb0 = (uint32_t*)g_xb0;
    uint32_t* xb1 = (uint32_t*)g_xb1;
#pragma unroll
    for (int nf = 0; nf < 8; nf++) {
        const int col = h * 64 + 8 * nf + 2 * (lane & 3);
#pragma unroll
        for (int half = 0; half < 2; half++) {
            const int rr = row0 + 8 * half;
            const float inv = half ? inv1 : inv0;
            float v0 = acc[nf][2 * half + 0] * inv;
            float v1 = acc[nf][2 * half + 1] * inv;
            __nv_bfloat162 hb = __floats2bfloat162_rn(v0, v1);
            __nv_bfloat162 hs = __floats2bfloat162_rn(
                v0 - __bfloat162float(hb.x), v1 - __bfloat162float(hb.y));
            size_t idx = ((size_t)(b * S_ + rr) * D_ + col) >> 1;
            xb0[idx] = *(uint32_t*)&hb;
            xb1[idx] = *(uint32_t*)&hs;
        }
    }
#undef LOAD_KV
}

// ---------------------------------------------------------------------------
// Launch
// ---------------------------------------------------------------------------
extern "C" void kernel_launch(void* const* d_in, const int* in_sizes, int n_in,
                              void* d_out, int out_size)
{
    const float* queries = (const float*)d_in[0];
    const float* keys    = (const float*)d_in[1];
    const float* values  = (const float*)d_in[2];
    const void*  mask    = d_in[3];
    const float* Wq = (const float*)d_in[4];
    const float* bq = (const float*)d_in[5];
    const float* Wk = (const float*)d_in[6];
    const float* bk = (const float*)d_in[7];
    const float* Wv = (const float*)d_in[8];
    const float* bv = (const float*)d_in[9];
    const float* Wo = (const float*)d_in[10];
    const float* bo = (const float*)d_in[11];
    float* out = (float*)d_out;

    (void)in_sizes; (void)n_in; (void)out_size;

    cudaFuncSetAttribute(mma_gemm_kernel,
                         cudaFuncAttributeMaxDynamicSharedMemorySize, GSMEM);
    cudaFuncSetAttribute(attn_mma_kernel,
                         cudaFuncAttributeMaxDynamicSharedMemorySize, ATT_SMEM);

    detect_mask_kernel<<<1, 256>>>((const unsigned char*)mask);
    expand_mask_kernel<<<(S_ * S_ + 255) / 256, 256>>>(mask);

    const dim3 ggrid(D_ / 128, (B_ * S_) / 128);    // (8, 64)
    const dim3 tgrid(32, 32);
    const dim3 tblk(32, 8);
    const int  xblocks = (B_ * S_ * D_ / 4) / 256;  // 8192

    // Q (scores pre-scaled via Q epilogue)
    split_wt_kernel<<<tgrid, tblk>>>(Wq);
    split_x_kernel<<<xblocks, 256>>>((const float4*)queries);
    mma_gemm_kernel<<<ggrid, 256, GSMEM>>>(bq, nullptr, 1);
    // K
    split_wt_kernel<<<tgrid, tblk>>>(Wk);
    split_x_kernel<<<xblocks, 256>>>((const float4*)keys);
    mma_gemm_kernel<<<ggrid, 256, GSMEM>>>(bk, nullptr, 2);
    // V
    split_wt_kernel<<<tgrid, tblk>>>(Wv);
    split_x_kernel<<<xblocks, 256>>>((const float4*)values);
    mma_gemm_kernel<<<ggrid, 256, GSMEM>>>(bv, nullptr, 3);

    // attention (writes bf16-split ctx directly into g_xb0/g_xb1)
    dim3 agrid(S_ / 128, B_ * H_);                  // (16, 64)
    attn_mma_kernel<<<agrid, 256, ATT_SMEM>>>();

    // O projection
    split_wt_kernel<<<tgrid, tblk>>>(Wo);
    mma_gemm_kernel<<<ggrid, 256, GSMEM>>>(bo, out, 0);
}

// round 7
// speedup vs baseline: 3.0780x; 1.1085x over previous
#include <cuda_runtime.h>
#include <cuda_bf16.h>
#include <math.h>
#include <stdint.h>

#define B_  4
#define S_  2048
#define D_  1024
#define H_  16
#define HD_ 64
#define SCALE_ 0.125f   // 1/sqrt(64)

#define XSLOT ((size_t)B_ * S_ * D_ / 4)   // uint2 elems per X slot
#define WSLOT ((size_t)D_ * D_ / 4)        // uint2 elems per WT slot

// ---------------------------------------------------------------------------
// Scratch (allocation-free __device__ globals)
// ---------------------------------------------------------------------------
__device__ uint2 g_xs0[3 * XSLOT];   // bf16 X big,  slots 0..2 (48MB)
__device__ uint2 g_xs1[3 * XSLOT];   // bf16 X small
__device__ uint2 g_wt0[3 * WSLOT];   // bf16 W^T big [n][k], slots 0..2
__device__ uint2 g_wt1[3 * WSLOT];   // bf16 W^T small
__device__ uint2 g_qb0[(size_t)B_ * H_ * S_ * HD_ / 4];  // bf16 (B,H,S,HD)
__device__ uint2 g_qb1[(size_t)B_ * H_ * S_ * HD_ / 4];
__device__ uint2 g_kb0[(size_t)B_ * H_ * S_ * HD_ / 4];
__device__ uint2 g_kb1[(size_t)B_ * H_ * S_ * HD_ / 4];
__device__ uint2 g_vb0[(size_t)B_ * H_ * S_ * HD_ / 4];
__device__ uint2 g_vb1[(size_t)B_ * H_ * S_ * HD_ / 4];
__device__ unsigned char g_mask8[(size_t)S_ * S_];
__device__ int g_mask_is_byte;

// ---------------------------------------------------------------------------
// PTX helpers (sm_80-era: valid on plain compute_100 target)
// ---------------------------------------------------------------------------
__device__ __forceinline__ uint32_t smem_u32(const void* p) {
    uint32_t a;
    asm("{ .reg .u64 t; cvta.to.shared.u64 t, %1; cvt.u32.u64 %0, t; }"
        : "=r"(a) : "l"(p));
    return a;
}
#define CP_ASYNC16(dst, src) \
    asm volatile("cp.async.cg.shared.global [%0], [%1], 16;" \
                 :: "r"(dst), "l"(src) : "memory")
#define CP_COMMIT()  asm volatile("cp.async.commit_group;" ::: "memory")
#define CP_WAIT1()   asm volatile("cp.async.wait_group 1;" ::: "memory")
#define CP_WAIT0()   asm volatile("cp.async.wait_group 0;" ::: "memory")

__device__ __forceinline__ void ldsm4(uint32_t* r, uint32_t addr) {
    asm volatile("ldmatrix.sync.aligned.m8n8.x4.shared.b16 {%0,%1,%2,%3}, [%4];"
                 : "=r"(r[0]), "=r"(r[1]), "=r"(r[2]), "=r"(r[3]) : "r"(addr));
}
__device__ __forceinline__ void ldsm4t(uint32_t* r, uint32_t addr) {
    asm volatile("ldmatrix.sync.aligned.m8n8.x4.trans.shared.b16 {%0,%1,%2,%3}, [%4];"
                 : "=r"(r[0]), "=r"(r[1]), "=r"(r[2]), "=r"(r[3]) : "r"(addr));
}
__device__ __forceinline__ void mma_bf16(float* c, const uint32_t* a,
                                         const uint32_t* b) {
    asm volatile(
        "mma.sync.aligned.m16n8k16.row.col.f32.bf16.bf16.f32 "
        "{%0,%1,%2,%3}, {%4,%5,%6,%7}, {%8,%9}, {%0,%1,%2,%3};"
        : "+f"(c[0]), "+f"(c[1]), "+f"(c[2]), "+f"(c[3])
        : "r"(a[0]), "r"(a[1]), "r"(a[2]), "r"(a[3]), "r"(b[0]), "r"(b[1]));
}

// exp(d) for d <= 0 on the FMA pipe (no MUFU). rel err ~2.4e-6.
__device__ __forceinline__ float exp_nm(float d) {
    float y = fmaxf(d * 1.4426950408889634f, -80.0f);
    float fi = rintf(y);
    float f = y - fi;                       // [-0.5, 0.5]
    float p = 0.0013333558f;
    p = fmaf(p, f, 0.0096181291f);
    p = fmaf(p, f, 0.0555041087f);
    p = fmaf(p, f, 0.2402265070f);
    p = fmaf(p, f, 0.6931471806f);
    p = fmaf(p, f, 1.0f);
    return p * __int_as_float(((int)fi + 127) << 23);
}

// ---------------------------------------------------------------------------
// Mask dtype probe (proven)
// ---------------------------------------------------------------------------
__global__ void detect_mask_kernel(const unsigned char* __restrict__ m) {
    __shared__ int any;
    if (threadIdx.x == 0) any = 0;
    __syncthreads();
    int found = 0;
    for (int i = threadIdx.x; i < 16384; i += 256)
        if (m[4 * i + 1] != 0) found = 1;
    if (found) atomicOr(&any, 1);
    __syncthreads();
    if (threadIdx.x == 0) g_mask_is_byte = any;
}

__global__ void expand_mask_kernel(const void* __restrict__ mraw) {
    int idx = blockIdx.x * blockDim.x + threadIdx.x;
    if (idx >= S_ * S_) return;
    unsigned char v;
    if (g_mask_is_byte) v = (((const unsigned char*)mraw)[idx] != 0) ? 1 : 0;
    else                v = (((const int*)mraw)[idx] != 0) ? 1 : 0;
    g_mask8[idx] = v;
}

// ---------------------------------------------------------------------------
// Prep: split Q/K/V inputs (fp32) -> bf16 big + residual, into slot blockIdx.y
// ---------------------------------------------------------------------------
__global__ void split_x3_kernel(const float4* __restrict__ q,
                                const float4* __restrict__ k,
                                const float4* __restrict__ v)
{
    const int z = blockIdx.y;
    const float4* src = (z == 0) ? q : (z == 1) ? k : v;
    size_t i = (size_t)blockIdx.x * 256 + threadIdx.x;
    float4 x = src[i];
    __nv_bfloat16 h0x = __float2bfloat16(x.x);
    __nv_bfloat16 h0y = __float2bfloat16(x.y);
    __nv_bfloat16 h0z = __float2bfloat16(x.z);
    __nv_bfloat16 h0w = __float2bfloat16(x.w);
    float rx = x.x - __bfloat162float(h0x);
    float ry = x.y - __bfloat162float(h0y);
    float rz = x.z - __bfloat162float(h0z);
    float rw = x.w - __bfloat162float(h0w);
    __nv_bfloat162 b0a; b0a.x = h0x; b0a.y = h0y;
    __nv_bfloat162 b0b; b0b.x = h0z; b0b.y = h0w;
    __nv_bfloat162 b1a = __floats2bfloat162_rn(rx, ry);
    __nv_bfloat162 b1b = __floats2bfloat162_rn(rz, rw);
    uint2 u0, u1;
    u0.x = *(uint32_t*)&b0a; u0.y = *(uint32_t*)&b0b;
    u1.x = *(uint32_t*)&b1a; u1.y = *(uint32_t*)&b1b;
    g_xs0[(size_t)z * XSLOT + i] = u0;
    g_xs1[(size_t)z * XSLOT + i] = u1;
}

// Prep: WT[n][k] = W[k][n], split to bf16 pairs into given slot.
__global__ void split_wt_kernel(const float* __restrict__ W, int slot) {
    __shared__ float t[32][33];
    const int tx = threadIdx.x, ty = threadIdx.y;
    const int n0 = blockIdx.x * 32, k0 = blockIdx.y * 32;
    __nv_bfloat16* wb0 = (__nv_bfloat16*)(g_wt0 + (size_t)slot * WSLOT);
    __nv_bfloat16* wb1 = (__nv_bfloat16*)(g_wt1 + (size_t)slot * WSLOT);
#pragma unroll
    for (int j = 0; j < 32; j += 8)
        t[ty + j][tx] = W[(size_t)(k0 + ty + j) * D_ + n0 + tx];
    __syncthreads();
#pragma unroll
    for (int j = 0; j < 32; j += 8) {
        float v = t[tx][ty + j];
        __nv_bfloat16 b = __float2bfloat16(v);
        float r = v - __bfloat162float(b);
        size_t o = (size_t)(n0 + ty + j) * D_ + k0 + tx;
        wb0[o] = b;
        wb1[o] = __float2bfloat16(r);
    }
}

// ---------------------------------------------------------------------------
// bf16x3 mma.sync GEMM. 3-stage cp.async pipeline, ONE sync per k-tile.
// ysel = -1: fused QKV (slot = blockIdx.z, dst q/k/v split-heads bf16 pairs)
// ysel =  0: O projection (slot 0, fp32 out + bias)
// ---------------------------------------------------------------------------
#define TPB  10240
#define STGB (4 * TPB)
#define GSMEM (3 * STGB)    // 122880

__global__ __launch_bounds__(256)
void mma_gemm_kernel(const float* __restrict__ biasA,
                     const float* __restrict__ biasB,
                     const float* __restrict__ biasC,
                     float* __restrict__ Yext, int ysel)
{
    extern __shared__ char sm[];
    const uint32_t sbase = smem_u32(sm);

    const int tid  = threadIdx.x;
    const int wid  = tid >> 5;
    const int lane = tid & 31;
    const int wm   = wid >> 2;
    const int wn   = wid & 3;
    const int m0   = blockIdx.y * 128;
    const int n0   = blockIdx.x * 128;
    const int z    = blockIdx.z;
    const int slot = (ysel < 0) ? z : 0;
    const int ysl  = (ysel < 0) ? (z + 1) : 0;
    const float* bias = (ysel >= 0) ? biasA
                      : (z == 0) ? biasA : (z == 1) ? biasB : biasC;

    const int lrow0 = tid >> 2;
    const int lseg  = (tid & 3) * 16;

    const char* pxb0 = (const char*)(g_xs0 + (size_t)slot * XSLOT);
    const char* pxb1 = (const char*)(g_xs1 + (size_t)slot * XSLOT);
    const char* pwb0 = (const char*)(g_wt0 + (size_t)slot * WSLOT);
    const char* pwb1 = (const char*)(g_wt1 + (size_t)slot * WSLOT);

    float c[4][4][4];
#pragma unroll
    for (int i = 0; i < 4; i++)
#pragma unroll
        for (int j = 0; j < 4; j++)
#pragma unroll
            for (int r = 0; r < 4; r++) c[i][j][r] = 0.0f;

#define LOAD_STAGE(st, kt) do {                                               \
    const uint32_t sb = sbase + (st) * STGB;                                  \
    const int kbyte = (kt) * 64;                                              \
    _Pragma("unroll")                                                         \
    for (int it = 0; it < 2; it++) {                                          \
        const int row = lrow0 + it * 64;                                      \
        const uint32_t doff = (uint32_t)(row * 80 + lseg);                    \
        const size_t gx = (size_t)(m0 + row) * 2048 + kbyte + lseg;           \
        const size_t gw = (size_t)(n0 + row) * 2048 + kbyte + lseg;           \
        CP_ASYNC16(sb + 0 * TPB + doff, pxb0 + gx);                           \
        CP_ASYNC16(sb + 1 * TPB + doff, pxb1 + gx);                           \
        CP_ASYNC16(sb + 2 * TPB + doff, pwb0 + gw);                           \
        CP_ASYNC16(sb + 3 * TPB + doff, pwb1 + gw);                           \
    }                                                                         \
    CP_COMMIT();                                                              \
} while (0)

    const uint32_t aoffs = (uint32_t)((lane & 15) * 80 + (lane >> 4) * 16);
    const uint32_t boffs = (uint32_t)(((lane >> 4) * 8 + (lane & 7)) * 80 +
                                      ((lane >> 3) & 1) * 16);

    LOAD_STAGE(0, 0);
    LOAD_STAGE(1, 1);

    const int NT = D_ / 32;       // 32 k-tiles
    int stq = 0;                  // stage of current k-tile
    for (int kt = 0; kt < NT; kt++) {
        if (kt + 1 < NT) CP_WAIT1();   // oldest (stage kt) done
        else             CP_WAIT0();
        __syncthreads();               // all warps past consuming kt-1

        // prefetch kt+2 into the stage consumed at kt-1
        if (kt + 2 < NT) {
            int stn = stq + 2; if (stn >= 3) stn -= 3;
            LOAD_STAGE(stn, kt + 2);
        }

        const uint32_t sb = sbase + stq * STGB;
        stq++; if (stq == 3) stq = 0;

#pragma unroll
        for (int ks = 0; ks < 2; ks++) {
            const uint32_t kb = (uint32_t)(ks * 32);

            uint32_t a0[4][4], a1[4][4];
#pragma unroll
            for (int i = 0; i < 4; i++) {
                const uint32_t ad =
                    sb + (uint32_t)((wm * 64 + 16 * i) * 80) + aoffs + kb;
                ldsm4(a0[i], ad);
                ldsm4(a1[i], ad + TPB);
            }
            uint32_t b0r[4][2], b1r[4][2];
#pragma unroll
            for (int p = 0; p < 2; p++) {
                const uint32_t bd =
                    sb + 2 * TPB + (uint32_t)((wn * 32 + 16 * p) * 80) + boffs + kb;
                uint32_t t0[4], t1[4];
                ldsm4(t0, bd);
                ldsm4(t1, bd + TPB);
                b0r[2 * p][0] = t0[0]; b0r[2 * p][1] = t0[1];
                b0r[2 * p + 1][0] = t0[2]; b0r[2 * p + 1][1] = t0[3];
                b1r[2 * p][0] = t1[0]; b1r[2 * p][1] = t1[1];
                b1r[2 * p + 1][0] = t1[2]; b1r[2 * p + 1][1] = t1[3];
            }
#pragma unroll
            for (int i = 0; i < 4; i++)
#pragma unroll
                for (int j = 0; j < 4; j++) {
                    mma_bf16(c[i][j], a0[i], b0r[j]);
                    mma_bf16(c[i][j], a0[i], b1r[j]);
                    mma_bf16(c[i][j], a1[i], b0r[j]);
                }
        }
    }

    // ---- epilogue ----
    if (ysl == 0) {
#pragma unroll
        for (int i = 0; i < 4; i++) {
            const int r0 = m0 + wm * 64 + 16 * i + (lane >> 2);
#pragma unroll
            for (int j = 0; j < 4; j++) {
                const int colp = n0 + wn * 32 + 8 * j + 2 * (lane & 3);
                const float bx = bias[colp], by = bias[colp + 1];
                float2 v0 = {c[i][j][0] + bx, c[i][j][1] + by};
                float2 v1 = {c[i][j][2] + bx, c[i][j][3] + by};
                *(float2*)&Yext[(size_t)r0 * D_ + colp] = v0;
                *(float2*)&Yext[(size_t)(r0 + 8) * D_ + colp] = v1;
            }
        }
    } else {
        uint32_t* d0 = (ysl == 1) ? (uint32_t*)g_qb0
                     : (ysl == 2) ? (uint32_t*)g_kb0 : (uint32_t*)g_vb0;
        uint32_t* d1 = (ysl == 1) ? (uint32_t*)g_qb1
                     : (ysl == 2) ? (uint32_t*)g_kb1 : (uint32_t*)g_vb1;
        const float scl = (ysl == 1) ? SCALE_ : 1.0f;
#pragma unroll
        for (int i = 0; i < 4; i++) {
            const int r0 = m0 + wm * 64 + 16 * i + (lane >> 2);
#pragma unroll
            for (int j = 0; j < 4; j++) {
                const int colp = n0 + wn * 32 + 8 * j + 2 * (lane & 3);
                const float bx = bias[colp], by = bias[colp + 1];
                const int h = colp >> 6;
                const int d = colp & 63;
#pragma unroll
                for (int half = 0; half < 2; half++) {
                    const int rr = r0 + 8 * half;
                    const int bb = rr >> 11, s = rr & (S_ - 1);
                    float vx = (c[i][j][2 * half + 0] + bx) * scl;
                    float vy = (c[i][j][2 * half + 1] + by) * scl;
                    __nv_bfloat162 hb = __floats2bfloat162_rn(vx, vy);
                    __nv_bfloat162 hs = __floats2bfloat162_rn(
                        vx - __bfloat162float(hb.x), vy - __bfloat162float(hb.y));
                    size_t idx =
                        (((size_t)(bb * H_ + h) * S_ + s) * HD_ + d) >> 1;
                    d0[idx] = *(uint32_t*)&hb;
                    d1[idx] = *(uint32_t*)&hs;
                }
            }
        }
    }
#undef LOAD_STAGE
}

// ---------------------------------------------------------------------------
// Tensor-core flash attention (R5 core, targeting 2 CTAs/SM).
// ---------------------------------------------------------------------------
#define ATT_ROWB 144
#define ATT_TILE (64 * ATT_ROWB)       // 9216
#define ATT_STAGE (4 * ATT_TILE)       // 36864
#define ATT_SMEM (2 * ATT_STAGE)       // 73728

__global__ __launch_bounds__(256, 2)
void attn_mma_kernel()
{
    extern __shared__ char sm[];
    const uint32_t sb = smem_u32(sm);

    const int tid  = threadIdx.x;
    const int wid  = tid >> 5;
    const int lane = tid & 31;
    const int q0   = blockIdx.x * 128;
    const int bh   = blockIdx.y;

    const size_t off = (size_t)bh * S_ * HD_ * 2;  // bytes
    const char* pq0 = (const char*)g_qb0 + off;
    const char* pq1 = (const char*)g_qb1 + off;
    const char* pk0 = (const char*)g_kb0 + off;
    const char* pk1 = (const char*)g_kb1 + off;
    const char* pv0 = (const char*)g_vb0 + off;
    const char* pv1 = (const char*)g_vb1 + off;

    // ---- stage Q (128x64 bf16 x2) through stage0, load fragments ----
#pragma unroll
    for (int sg = 0; sg < 4; sg++) {
        const int seg = tid + 256 * sg;
        const int row = seg >> 3, c16 = seg & 7;
        const size_t gsrc = (size_t)(q0 + row) * 128 + c16 * 16;
        const uint32_t dd = (uint32_t)(row * ATT_ROWB + c16 * 16);
        CP_ASYNC16(sb + dd, pq0 + gsrc);
        CP_ASYNC16(sb + 18432 + dd, pq1 + gsrc);
    }
    CP_COMMIT(); CP_WAIT0(); __syncthreads();

    uint32_t qbf[4][4], qsf[4][4];
    {
        const uint32_t ao = (uint32_t)((wid * 16 + (lane & 15)) * ATT_ROWB +
                                       (lane >> 4) * 16);
#pragma unroll
        for (int kf = 0; kf < 4; kf++) {
            ldsm4(qbf[kf], sb + ao + kf * 32);
            ldsm4(qsf[kf], sb + 18432 + ao + kf * 32);
        }
    }
    __syncthreads();

    float acc[8][4];
#pragma unroll
    for (int nf = 0; nf < 8; nf++)
#pragma unroll
        for (int e = 0; e < 4; e++) acc[nf][e] = 0.0f;
    float mrun0 = -INFINITY, mrun1 = -INFINITY, lrun0 = 0.0f, lrun1 = 0.0f;

#define LOAD_KV(st, t) do {                                                   \
    const uint32_t stg_ = sb + (st) * ATT_STAGE;                              \
    const int kk0_ = (t) * 64;                                                \
    _Pragma("unroll")                                                         \
    for (int jj = 0; jj < 2; jj++) {                                          \
        const int seg = tid + 256 * jj;                                       \
        const int row = seg >> 3, c16 = seg & 7;                              \
        const size_t gs = (size_t)(kk0_ + row) * 128 + c16 * 16;              \
        const uint32_t dd = (uint32_t)(row * ATT_ROWB + c16 * 16);            \
        CP_ASYNC16(stg_ + 0 * ATT_TILE + dd, pk0 + gs);                       \
        CP_ASYNC16(stg_ + 1 * ATT_TILE + dd, pk1 + gs);                       \
        CP_ASYNC16(stg_ + 2 * ATT_TILE + dd, pv0 + gs);                       \
        CP_ASYNC16(stg_ + 3 * ATT_TILE + dd, pv1 + gs);                       \
    }                                                                         \
    CP_COMMIT();                                                              \
} while (0)

    LOAD_KV(0, 0);

    const uint32_t boff = (uint32_t)(((lane >> 4) * 8 + (lane & 7)) * ATT_ROWB +
                                     ((lane >> 3) & 1) * 16);
    const unsigned char* mbase =
        g_mask8 + (size_t)(q0 + wid * 16 + (lane >> 2)) * S_ + 2 * (lane & 3);
    const unsigned char* mbase8 = mbase + 8 * S_;

    for (int t = 0; t < S_ / 64; t++) {
        if (t + 1 < S_ / 64) { LOAD_KV((t + 1) & 1, t + 1); CP_WAIT1(); }
        else                 { CP_WAIT0(); }
        __syncthreads();

        const uint32_t stg = sb + (t & 1) * ATT_STAGE;

        // ---- scores ----
        float c[8][4];
#pragma unroll
        for (int nf = 0; nf < 8; nf++)
#pragma unroll
            for (int e = 0; e < 4; e++) c[nf][e] = 0.0f;

#pragma unroll
        for (int sg = 0; sg < 4; sg++) {
#pragma unroll
            for (int kf = 0; kf < 4; kf++) {
                const uint32_t ka = stg + (uint32_t)(sg * 16 * ATT_ROWB) +
                                    kf * 32 + boff;
                uint32_t tb[4], ts[4];
                ldsm4(tb, ka);
                ldsm4(ts, ka + ATT_TILE);
                mma_bf16(c[2 * sg], qbf[kf], tb);
                mma_bf16(c[2 * sg], qbf[kf], ts);
                mma_bf16(c[2 * sg], qsf[kf], tb);
                mma_bf16(c[2 * sg + 1], qbf[kf], tb + 2);
                mma_bf16(c[2 * sg + 1], qbf[kf], ts + 2);
                mma_bf16(c[2 * sg + 1], qsf[kf], tb + 2);
            }
        }

        // ---- mask ----
        const int k0 = t * 64;
#pragma unroll
        for (int nf = 0; nf < 8; nf++) {
            unsigned short u0 = *(const unsigned short*)(mbase + k0 + 8 * nf);
            unsigned short u1 = *(const unsigned short*)(mbase8 + k0 + 8 * nf);
            c[nf][0] = (u0 & 0xFF) ? c[nf][0] : -1e30f;
            c[nf][1] = (u0 >> 8)   ? c[nf][1] : -1e30f;
            c[nf][2] = (u1 & 0xFF) ? c[nf][2] : -1e30f;
            c[nf][3] = (u1 >> 8)   ? c[nf][3] : -1e30f;
        }

        // ---- row max ----
        float rm0 = -INFINITY, rm1 = -INFINITY;
#pragma unroll
        for (int nf = 0; nf < 8; nf++) {
            rm0 = fmaxf(rm0, fmaxf(c[nf][0], c[nf][1]));
            rm1 = fmaxf(rm1, fmaxf(c[nf][2], c[nf][3]));
        }
        rm0 = fmaxf(rm0, __shfl_xor_sync(0xffffffffu, rm0, 1));
        rm0 = fmaxf(rm0, __shfl_xor_sync(0xffffffffu, rm0, 2));
        rm1 = fmaxf(rm1, __shfl_xor_sync(0xffffffffu, rm1, 1));
        rm1 = fmaxf(rm1, __shfl_xor_sync(0xffffffffu, rm1, 2));

        const float mn0 = fmaxf(mrun0, rm0);
        const float mn1 = fmaxf(mrun1, rm1);
        const float cr0 = exp_nm(mrun0 - mn0);
        const float cr1 = exp_nm(mrun1 - mn1);
        mrun0 = mn0; mrun1 = mn1;

        // ---- exp + row sums ----
        float ts0 = 0.0f, ts1 = 0.0f;
#pragma unroll
        for (int nf = 0; nf < 8; nf++) {
            c[nf][0] = exp_nm(c[nf][0] - mn0);
            c[nf][1] = exp_nm(c[nf][1] - mn0);
            c[nf][2] = exp_nm(c[nf][2] - mn1);
            c[nf][3] = exp_nm(c[nf][3] - mn1);
            ts0 += c[nf][0] + c[nf][1];
            ts1 += c[nf][2] + c[nf][3];
        }
        ts0 += __shfl_xor_sync(0xffffffffu, ts0, 1);
        ts0 += __shfl_xor_sync(0xffffffffu, ts0, 2);
        ts1 += __shfl_xor_sync(0xffffffffu, ts1, 1);
        ts1 += __shfl_xor_sync(0xffffffffu, ts1, 2);
        lrun0 = lrun0 * cr0 + ts0;
        lrun1 = lrun1 * cr1 + ts1;

#pragma unroll
        for (int nf = 0; nf < 8; nf++) {
            acc[nf][0] *= cr0; acc[nf][1] *= cr0;
            acc[nf][2] *= cr1; acc[nf][3] *= cr1;
        }

        // ---- PV ----
#pragma unroll
        for (int kf = 0; kf < 4; kf++) {
            uint32_t pab[4], pas[4];
#pragma unroll
            for (int q = 0; q < 2; q++) {
                const float* pc = c[2 * kf + q];
#pragma unroll
                for (int half = 0; half < 2; half++) {
                    float v0 = pc[2 * half], v1 = pc[2 * half + 1];
                    __nv_bfloat162 hb = __floats2bfloat162_rn(v0, v1);
                    __nv_bfloat162 hs = __floats2bfloat162_rn(
                        v0 - __bfloat162float(hb.x), v1 - __bfloat162float(hb.y));
                    pab[2 * q + half] = *(uint32_t*)&hb;
                    pas[2 * q + half] = *(uint32_t*)&hs;
                }
            }
#pragma unroll
            for (int dg = 0; dg < 4; dg++) {
                const uint32_t va = stg + 2 * ATT_TILE +
                    (uint32_t)((kf * 16 + (lane & 15)) * ATT_ROWB) +
                    dg * 32 + (lane >> 4) * 16;
                uint32_t vb[4], vs[4];
                ldsm4t(vb, va);
                ldsm4t(vs, va + ATT_TILE);
                mma_bf16(acc[2 * dg], pab, vb);
                mma_bf16(acc[2 * dg], pab, vs);
                mma_bf16(acc[2 * dg], pas, vb);
                mma_bf16(acc[2 * dg + 1], pab, vb + 2);
                mma_bf16(acc[2 * dg + 1], pab, vs + 2);
                mma_bf16(acc[2 * dg + 1], pas, vb + 2);
            }
        }
        __syncthreads();
    }

    // ---- epilogue: normalize, split to bf16, write O-projection input ----
    const float inv0 = 1.0f / lrun0;
    const float inv1 = 1.0f / lrun1;
    const int b = bh >> 4;
    const int h = bh & 15;
    const int row0 = q0 + wid * 16 + (lane >> 2);
    uint32_t* xb0 = (uint32_t*)g_xs0;   // slot 0
    uint32_t* xb1 = (uint32_t*)g_xs1;
#pragma unroll
    for (int nf = 0; nf < 8; nf++) {
        const int col = h * 64 + 8 * nf + 2 * (lane & 3);
#pragma unroll
        for (int half = 0; half < 2; half++) {
            const int rr = row0 + 8 * half;
            const float inv = half ? inv1 : inv0;
            float v0 = acc[nf][2 * half + 0] * inv;
            float v1 = acc[nf][2 * half + 1] * inv;
            __nv_bfloat162 hb = __floats2bfloat162_rn(v0, v1);
            __nv_bfloat162 hs = __floats2bfloat162_rn(
                v0 - __bfloat162float(hb.x), v1 - __bfloat162float(hb.y));
            size_t idx = ((size_t)(b * S_ + rr) * D_ + col) >> 1;
            xb0[idx] = *(uint32_t*)&hb;
            xb1[idx] = *(uint32_t*)&hs;
        }
    }
#undef LOAD_KV
}

// ---------------------------------------------------------------------------
// Launch
// ---------------------------------------------------------------------------
extern "C" void kernel_launch(void* const* d_in, const int* in_sizes, int n_in,
                              void* d_out, int out_size)
{
    const float* queries = (const float*)d_in[0];
    const float* keys    = (const float*)d_in[1];
    const float* values  = (const float*)d_in[2];
    const void*  mask    = d_in[3];
    const float* Wq = (const float*)d_in[4];
    const float* bq = (const float*)d_in[5];
    const float* Wk = (const float*)d_in[6];
    const float* bk = (const float*)d_in[7];
    const float* Wv = (const float*)d_in[8];
    const float* bv = (const float*)d_in[9];
    const float* Wo = (const float*)d_in[10];
    const float* bo = (const float*)d_in[11];
    float* out = (float*)d_out;

    (void)in_sizes; (void)n_in; (void)out_size;

    cudaFuncSetAttribute(mma_gemm_kernel,
                         cudaFuncAttributeMaxDynamicSharedMemorySize, GSMEM);
    cudaFuncSetAttribute(attn_mma_kernel,
                         cudaFuncAttributeMaxDynamicSharedMemorySize, ATT_SMEM);

    detect_mask_kernel<<<1, 256>>>((const unsigned char*)mask);
    expand_mask_kernel<<<(S_ * S_ + 255) / 256, 256>>>(mask);

    const dim3 tgrid(32, 32);
    const dim3 tblk(32, 8);

    // QKV prep
    split_wt_kernel<<<tgrid, tblk>>>(Wq, 0);
    split_wt_kernel<<<tgrid, tblk>>>(Wk, 1);
    split_wt_kernel<<<tgrid, tblk>>>(Wv, 2);
    split_x3_kernel<<<dim3((B_ * S_ * D_ / 4) / 256, 3), 256>>>(
        (const float4*)queries, (const float4*)keys, (const float4*)values);

    // fused QKV projections
    dim3 qkvgrid(D_ / 128, (B_ * S_) / 128, 3);     // (8, 64, 3)
    mma_gemm_kernel<<<qkvgrid, 256, GSMEM>>>(bq, bk, bv, nullptr, -1);

    // Wo split (slot 0 free after QKV gemm)
    split_wt_kernel<<<tgrid, tblk>>>(Wo, 0);

    // attention (writes bf16-split ctx into x slot 0)
    dim3 agrid(S_ / 128, B_ * H_);                  // (16, 64)
    attn_mma_kernel<<<agrid, 256, ATT_SMEM>>>();

    // O projection
    dim3 ogrid(D_ / 128, (B_ * S_) / 128, 1);
    mma_gemm_kernel<<<ogrid, 256, GSMEM>>>(bo, nullptr, nullptr, out, 0);
}

// round 8
// speedup vs baseline: 3.4167x; 1.1100x over previous
#include <cuda_runtime.h>
#include <cuda_bf16.h>
#include <math.h>
#include <stdint.h>

#define B_  4
#define S_  2048
#define D_  1024
#define H_  16
#define HD_ 64
#define SCALE_ 0.125f   // 1/sqrt(64)

#define XSLOT ((size_t)B_ * S_ * D_ / 4)   // uint2 elems per X slot
#define WSLOT ((size_t)D_ * D_ / 4)        // uint2 elems per WT slot

// ---------------------------------------------------------------------------
// Scratch (allocation-free __device__ globals)
// ---------------------------------------------------------------------------
__device__ uint2 g_xs0[3 * XSLOT];   // bf16 X big,  slots 0..2
__device__ uint2 g_xs1[3 * XSLOT];   // bf16 X small
__device__ uint2 g_wt0[3 * WSLOT];   // bf16 W^T big [n][k], slots 0..2
__device__ uint2 g_wt1[3 * WSLOT];   // bf16 W^T small
__device__ uint2 g_qb0[(size_t)B_ * H_ * S_ * HD_ / 4];  // bf16 (B,H,S,HD)
__device__ uint2 g_qb1[(size_t)B_ * H_ * S_ * HD_ / 4];
__device__ uint2 g_kb0[(size_t)B_ * H_ * S_ * HD_ / 4];
__device__ uint2 g_kb1[(size_t)B_ * H_ * S_ * HD_ / 4];
__device__ uint2 g_vb0[(size_t)B_ * H_ * S_ * HD_ / 4];
__device__ uint2 g_vb1[(size_t)B_ * H_ * S_ * HD_ / 4];
__device__ unsigned long long g_maskbits[(size_t)S_ * S_ / 64];  // 512KB
__device__ int g_mask_is_byte;

// ---------------------------------------------------------------------------
// PTX helpers (sm_80-era: valid on plain compute_100 target)
// ---------------------------------------------------------------------------
__device__ __forceinline__ uint32_t smem_u32(const void* p) {
    uint32_t a;
    asm("{ .reg .u64 t; cvta.to.shared.u64 t, %1; cvt.u32.u64 %0, t; }"
        : "=r"(a) : "l"(p));
    return a;
}
#define CP_ASYNC16(dst, src) \
    asm volatile("cp.async.cg.shared.global [%0], [%1], 16;" \
                 :: "r"(dst), "l"(src) : "memory")
#define CP_COMMIT()  asm volatile("cp.async.commit_group;" ::: "memory")
#define CP_WAIT0()   asm volatile("cp.async.wait_group 0;" ::: "memory")

__device__ __forceinline__ void ldsm4(uint32_t* r, uint32_t addr) {
    asm volatile("ldmatrix.sync.aligned.m8n8.x4.shared.b16 {%0,%1,%2,%3}, [%4];"
                 : "=r"(r[0]), "=r"(r[1]), "=r"(r[2]), "=r"(r[3]) : "r"(addr));
}
__device__ __forceinline__ void ldsm4t(uint32_t* r, uint32_t addr) {
    asm volatile("ldmatrix.sync.aligned.m8n8.x4.trans.shared.b16 {%0,%1,%2,%3}, [%4];"
                 : "=r"(r[0]), "=r"(r[1]), "=r"(r[2]), "=r"(r[3]) : "r"(addr));
}
__device__ __forceinline__ void mma_bf16(float* c, const uint32_t* a,
                                         const uint32_t* b) {
    asm volatile(
        "mma.sync.aligned.m16n8k16.row.col.f32.bf16.bf16.f32 "
        "{%0,%1,%2,%3}, {%4,%5,%6,%7}, {%8,%9}, {%0,%1,%2,%3};"
        : "+f"(c[0]), "+f"(c[1]), "+f"(c[2]), "+f"(c[3])
        : "r"(a[0]), "r"(a[1]), "r"(a[2]), "r"(a[3]), "r"(b[0]), "r"(b[1]));
}

// exp(d) for d <= 0 on the FMA pipe (no MUFU). rel err ~2.4e-6.
__device__ __forceinline__ float exp_nm(float d) {
    float y = fmaxf(d * 1.4426950408889634f, -80.0f);
    float fi = rintf(y);
    float f = y - fi;                       // [-0.5, 0.5]
    float p = 0.0013333558f;
    p = fmaf(p, f, 0.0096181291f);
    p = fmaf(p, f, 0.0555041087f);
    p = fmaf(p, f, 0.2402265070f);
    p = fmaf(p, f, 0.6931471806f);
    p = fmaf(p, f, 1.0f);
    return p * __int_as_float(((int)fi + 127) << 23);
}

// ---------------------------------------------------------------------------
// Mask dtype probe (proven)
// ---------------------------------------------------------------------------
__global__ void detect_mask_kernel(const unsigned char* __restrict__ m) {
    __shared__ int any;
    if (threadIdx.x == 0) any = 0;
    __syncthreads();
    int found = 0;
    for (int i = threadIdx.x; i < 16384; i += 256)
        if (m[4 * i + 1] != 0) found = 1;
    if (found) atomicOr(&any, 1);
    __syncthreads();
    if (threadIdx.x == 0) g_mask_is_byte = any;
}

// Mask -> bitmask (row-major, 32 u64 per row). Warp-ballot.
__global__ void mask_bits_kernel(const void* __restrict__ mraw) {
    const int wg   = (blockIdx.x * blockDim.x + threadIdx.x) >> 5;
    const int lane = threadIdx.x & 31;
    const int nw   = (gridDim.x * blockDim.x) >> 5;
    const int isb  = g_mask_is_byte;
    const unsigned char* m8 = (const unsigned char*)mraw;
    const int* m32 = (const int*)mraw;
    for (int chunk = wg; chunk < S_ * S_ / 64; chunk += nw) {
        const size_t base = (size_t)chunk * 64;
        int v0, v1;
        if (isb) {
            v0 = m8[base + lane] != 0;
            v1 = m8[base + 32 + lane] != 0;
        } else {
            v0 = m32[base + lane] != 0;
            v1 = m32[base + 32 + lane] != 0;
        }
        uint32_t b0 = __ballot_sync(0xffffffffu, v0);
        uint32_t b1 = __ballot_sync(0xffffffffu, v1);
        if (lane == 0)
            g_maskbits[chunk] =
                (unsigned long long)b0 | ((unsigned long long)b1 << 32);
    }
}

// ---------------------------------------------------------------------------
// Prep: split Q/K/V inputs (fp32) -> bf16 big + residual, into slot blockIdx.y
// ---------------------------------------------------------------------------
__global__ void split_x3_kernel(const float4* __restrict__ q,
                                const float4* __restrict__ k,
                                const float4* __restrict__ v)
{
    const int z = blockIdx.y;
    const float4* src = (z == 0) ? q : (z == 1) ? k : v;
    size_t i = (size_t)blockIdx.x * 256 + threadIdx.x;
    float4 x = src[i];
    __nv_bfloat16 h0x = __float2bfloat16(x.x);
    __nv_bfloat16 h0y = __float2bfloat16(x.y);
    __nv_bfloat16 h0z = __float2bfloat16(x.z);
    __nv_bfloat16 h0w = __float2bfloat16(x.w);
    float rx = x.x - __bfloat162float(h0x);
    float ry = x.y - __bfloat162float(h0y);
    float rz = x.z - __bfloat162float(h0z);
    float rw = x.w - __bfloat162float(h0w);
    __nv_bfloat162 b0a; b0a.x = h0x; b0a.y = h0y;
    __nv_bfloat162 b0b; b0b.x = h0z; b0b.y = h0w;
    __nv_bfloat162 b1a = __floats2bfloat162_rn(rx, ry);
    __nv_bfloat162 b1b = __floats2bfloat162_rn(rz, rw);
    uint2 u0, u1;
    u0.x = *(uint32_t*)&b0a; u0.y = *(uint32_t*)&b0b;
    u1.x = *(uint32_t*)&b1a; u1.y = *(uint32_t*)&b1b;
    g_xs0[(size_t)z * XSLOT + i] = u0;
    g_xs1[(size_t)z * XSLOT + i] = u1;
}

// Prep: WT[n][k] = W[k][n], split to bf16 pairs into given slot.
__global__ void split_wt_kernel(const float* __restrict__ W, int slot) {
    __shared__ float t[32][33];
    const int tx = threadIdx.x, ty = threadIdx.y;
    const int n0 = blockIdx.x * 32, k0 = blockIdx.y * 32;
    __nv_bfloat16* wb0 = (__nv_bfloat16*)(g_wt0 + (size_t)slot * WSLOT);
    __nv_bfloat16* wb1 = (__nv_bfloat16*)(g_wt1 + (size_t)slot * WSLOT);
#pragma unroll
    for (int j = 0; j < 32; j += 8)
        t[ty + j][tx] = W[(size_t)(k0 + ty + j) * D_ + n0 + tx];
    __syncthreads();
#pragma unroll
    for (int j = 0; j < 32; j += 8) {
        float v = t[tx][ty + j];
        __nv_bfloat16 b = __float2bfloat16(v);
        float r = v - __bfloat162float(b);
        size_t o = (size_t)(n0 + ty + j) * D_ + k0 + tx;
        wb0[o] = b;
        wb1[o] = __float2bfloat16(r);
    }
}

// ---------------------------------------------------------------------------
// bf16x3 mma.sync GEMM. 2-stage cp.async, ONE sync per k-tile, 2 CTAs/SM.
// ysel = -1: fused QKV (slot = blockIdx.z); ysel = 0: O projection.
// ---------------------------------------------------------------------------
#define TPB  10240
#define STGB (4 * TPB)
#define GSMEM (2 * STGB)    // 81920

__global__ __launch_bounds__(256, 2)
void mma_gemm_kernel(const float* __restrict__ biasA,
                     const float* __restrict__ biasB,
                     const float* __restrict__ biasC,
                     float* __restrict__ Yext, int ysel)
{
    extern __shared__ char sm[];
    const uint32_t sbase = smem_u32(sm);

    const int tid  = threadIdx.x;
    const int wid  = tid >> 5;
    const int lane = tid & 31;
    const int wm   = wid >> 2;
    const int wn   = wid & 3;
    const int m0   = blockIdx.y * 128;
    const int n0   = blockIdx.x * 128;
    const int z    = blockIdx.z;
    const int slot = (ysel < 0) ? z : 0;
    const int ysl  = (ysel < 0) ? (z + 1) : 0;
    const float* bias = (ysel >= 0) ? biasA
                      : (z == 0) ? biasA : (z == 1) ? biasB : biasC;

    const int lrow0 = tid >> 2;
    const int lseg  = (tid & 3) * 16;

    const char* pxb0 = (const char*)(g_xs0 + (size_t)slot * XSLOT);
    const char* pxb1 = (const char*)(g_xs1 + (size_t)slot * XSLOT);
    const char* pwb0 = (const char*)(g_wt0 + (size_t)slot * WSLOT);
    const char* pwb1 = (const char*)(g_wt1 + (size_t)slot * WSLOT);

    float c[4][4][4];
#pragma unroll
    for (int i = 0; i < 4; i++)
#pragma unroll
        for (int j = 0; j < 4; j++)
#pragma unroll
            for (int r = 0; r < 4; r++) c[i][j][r] = 0.0f;

#define LOAD_STAGE(st, kt) do {                                               \
    const uint32_t sb = sbase + (st) * STGB;                                  \
    const int kbyte = (kt) * 64;                                              \
    _Pragma("unroll")                                                         \
    for (int it = 0; it < 2; it++) {                                          \
        const int row = lrow0 + it * 64;                                      \
        const uint32_t doff = (uint32_t)(row * 80 + lseg);                    \
        const size_t gx = (size_t)(m0 + row) * 2048 + kbyte + lseg;           \
        const size_t gw = (size_t)(n0 + row) * 2048 + kbyte + lseg;           \
        CP_ASYNC16(sb + 0 * TPB + doff, pxb0 + gx);                           \
        CP_ASYNC16(sb + 1 * TPB + doff, pxb1 + gx);                           \
        CP_ASYNC16(sb + 2 * TPB + doff, pwb0 + gw);                           \
        CP_ASYNC16(sb + 3 * TPB + doff, pwb1 + gw);                           \
    }                                                                         \
    CP_COMMIT();                                                              \
} while (0)

    const uint32_t aoffs = (uint32_t)((lane & 15) * 80 + (lane >> 4) * 16);
    const uint32_t boffs = (uint32_t)(((lane >> 4) * 8 + (lane & 7)) * 80 +
                                      ((lane >> 3) & 1) * 16);

    LOAD_STAGE(0, 0);

    const int NT = D_ / 32;       // 32 k-tiles
    for (int kt = 0; kt < NT; kt++) {
        CP_WAIT0();               // stage kt&1 data landed
        __syncthreads();          // + all warps done reading stage (kt+1)&1
        if (kt + 1 < NT) LOAD_STAGE((kt + 1) & 1, kt + 1);

        const uint32_t sb = sbase + (kt & 1) * STGB;

#pragma unroll
        for (int ks = 0; ks < 2; ks++) {
            const uint32_t kb = (uint32_t)(ks * 32);

            uint32_t a0[4][4], a1[4][4];
#pragma unroll
            for (int i = 0; i < 4; i++) {
                const uint32_t ad =
                    sb + (uint32_t)((wm * 64 + 16 * i) * 80) + aoffs + kb;
                ldsm4(a0[i], ad);
                ldsm4(a1[i], ad + TPB);
            }
            uint32_t b0r[4][2], b1r[4][2];
#pragma unroll
            for (int p = 0; p < 2; p++) {
                const uint32_t bd =
                    sb + 2 * TPB + (uint32_t)((wn * 32 + 16 * p) * 80) + boffs + kb;
                uint32_t t0[4], t1[4];
                ldsm4(t0, bd);
                ldsm4(t1, bd + TPB);
                b0r[2 * p][0] = t0[0]; b0r[2 * p][1] = t0[1];
                b0r[2 * p + 1][0] = t0[2]; b0r[2 * p + 1][1] = t0[3];
                b1r[2 * p][0] = t1[0]; b1r[2 * p][1] = t1[1];
                b1r[2 * p + 1][0] = t1[2]; b1r[2 * p + 1][1] = t1[3];
            }
#pragma unroll
            for (int i = 0; i < 4; i++)
#pragma unroll
                for (int j = 0; j < 4; j++) {
                    mma_bf16(c[i][j], a0[i], b0r[j]);
                    mma_bf16(c[i][j], a0[i], b1r[j]);
                    mma_bf16(c[i][j], a1[i], b0r[j]);
                }
        }
    }

    // ---- epilogue ----
    if (ysl == 0) {
#pragma unroll
        for (int i = 0; i < 4; i++) {
            const int r0 = m0 + wm * 64 + 16 * i + (lane >> 2);
#pragma unroll
            for (int j = 0; j < 4; j++) {
                const int colp = n0 + wn * 32 + 8 * j + 2 * (lane & 3);
                const float bx = bias[colp], by = bias[colp + 1];
                float2 v0 = {c[i][j][0] + bx, c[i][j][1] + by};
                float2 v1 = {c[i][j][2] + bx, c[i][j][3] + by};
                *(float2*)&Yext[(size_t)r0 * D_ + colp] = v0;
                *(float2*)&Yext[(size_t)(r0 + 8) * D_ + colp] = v1;
            }
        }
    } else {
        uint32_t* d0 = (ysl == 1) ? (uint32_t*)g_qb0
                     : (ysl == 2) ? (uint32_t*)g_kb0 : (uint32_t*)g_vb0;
        uint32_t* d1 = (ysl == 1) ? (uint32_t*)g_qb1
                     : (ysl == 2) ? (uint32_t*)g_kb1 : (uint32_t*)g_vb1;
        const float scl = (ysl == 1) ? SCALE_ : 1.0f;
#pragma unroll
        for (int i = 0; i < 4; i++) {
            const int r0 = m0 + wm * 64 + 16 * i + (lane >> 2);
#pragma unroll
            for (int j = 0; j < 4; j++) {
                const int colp = n0 + wn * 32 + 8 * j + 2 * (lane & 3);
                const float bx = bias[colp], by = bias[colp + 1];
                const int h = colp >> 6;
                const int d = colp & 63;
#pragma unroll
                for (int half = 0; half < 2; half++) {
                    const int rr = r0 + 8 * half;
                    const int bb = rr >> 11, s = rr & (S_ - 1);
                    float vx = (c[i][j][2 * half + 0] + bx) * scl;
                    float vy = (c[i][j][2 * half + 1] + by) * scl;
                    __nv_bfloat162 hb = __floats2bfloat162_rn(vx, vy);
                    __nv_bfloat162 hs = __floats2bfloat162_rn(
                        vx - __bfloat162float(hb.x), vy - __bfloat162float(hb.y));
                    size_t idx =
                        (((size_t)(bb * H_ + h) * S_ + s) * HD_ + d) >> 1;
                    d0[idx] = *(uint32_t*)&hb;
                    d1[idx] = *(uint32_t*)&hs;
                }
            }
        }
    }
#undef LOAD_STAGE
}

// ---------------------------------------------------------------------------
// Tensor-core flash attention: single sync per tile, bitmask mask, 2 CTAs/SM.
// ---------------------------------------------------------------------------
#define ATT_ROWB 144
#define ATT_TILE (64 * ATT_ROWB)       // 9216
#define ATT_STAGE (4 * ATT_TILE)       // 36864
#define ATT_SMEM (2 * ATT_STAGE)       // 73728

__global__ __launch_bounds__(256, 2)
void attn_mma_kernel()
{
    extern __shared__ char sm[];
    const uint32_t sb = smem_u32(sm);

    const int tid  = threadIdx.x;
    const int wid  = tid >> 5;
    const int lane = tid & 31;
    const int q0   = blockIdx.x * 128;
    const int bh   = blockIdx.y;

    const size_t off = (size_t)bh * S_ * HD_ * 2;  // bytes
    const char* pq0 = (const char*)g_qb0 + off;
    const char* pq1 = (const char*)g_qb1 + off;
    const char* pk0 = (const char*)g_kb0 + off;
    const char* pk1 = (const char*)g_kb1 + off;
    const char* pv0 = (const char*)g_vb0 + off;
    const char* pv1 = (const char*)g_vb1 + off;

    // ---- stage Q (128x64 bf16 x2) through stage0, load fragments ----
#pragma unroll
    for (int sg = 0; sg < 4; sg++) {
        const int seg = tid + 256 * sg;
        const int row = seg >> 3, c16 = seg & 7;
        const size_t gsrc = (size_t)(q0 + row) * 128 + c16 * 16;
        const uint32_t dd = (uint32_t)(row * ATT_ROWB + c16 * 16);
        CP_ASYNC16(sb + dd, pq0 + gsrc);
        CP_ASYNC16(sb + 18432 + dd, pq1 + gsrc);
    }
    CP_COMMIT(); CP_WAIT0(); __syncthreads();

    uint32_t qbf[4][4], qsf[4][4];
    {
        const uint32_t ao = (uint32_t)((wid * 16 + (lane & 15)) * ATT_ROWB +
                                       (lane >> 4) * 16);
#pragma unroll
        for (int kf = 0; kf < 4; kf++) {
            ldsm4(qbf[kf], sb + ao + kf * 32);
            ldsm4(qsf[kf], sb + 18432 + ao + kf * 32);
        }
    }
    __syncthreads();

    float acc[8][4];
#pragma unroll
    for (int nf = 0; nf < 8; nf++)
#pragma unroll
        for (int e = 0; e < 4; e++) acc[nf][e] = 0.0f;
    float mrun0 = -INFINITY, mrun1 = -INFINITY, lrun0 = 0.0f, lrun1 = 0.0f;

#define LOAD_KV(st, t) do {                                                   \
    const uint32_t stg_ = sb + (st) * ATT_STAGE;                              \
    const int kk0_ = (t) * 64;                                                \
    _Pragma("unroll")                                                         \
    for (int jj = 0; jj < 2; jj++) {                                          \
        const int seg = tid + 256 * jj;                                       \
        const int row = seg >> 3, c16 = seg & 7;                              \
        const size_t gs = (size_t)(kk0_ + row) * 128 + c16 * 16;              \
        const uint32_t dd = (uint32_t)(row * ATT_ROWB + c16 * 16);            \
        CP_ASYNC16(stg_ + 0 * ATT_TILE + dd, pk0 + gs);                       \
        CP_ASYNC16(stg_ + 1 * ATT_TILE + dd, pk1 + gs);                       \
        CP_ASYNC16(stg_ + 2 * ATT_TILE + dd, pv0 + gs);                       \
        CP_ASYNC16(stg_ + 3 * ATT_TILE + dd, pv1 + gs);                       \
    }                                                                         \
    CP_COMMIT();                                                              \
} while (0)

    LOAD_KV(0, 0);

    const uint32_t boff = (uint32_t)(((lane >> 4) * 8 + (lane & 7)) * ATT_ROWB +
                                     ((lane >> 3) & 1) * 16);
    const int row0 = q0 + wid * 16 + (lane >> 2);
    const uint32_t msh = 2 * (lane & 3);

    for (int t = 0; t < S_ / 64; t++) {
        CP_WAIT0();               // stage t&1 landed
        __syncthreads();          // + all warps done reading stage (t+1)&1
        if (t + 1 < S_ / 64) LOAD_KV((t + 1) & 1, t + 1);

        const uint32_t stg = sb + (t & 1) * ATT_STAGE;

        // mask bits for this tile (hoisted: LDG overlaps ldsm/mma below)
        const unsigned long long mm0 = g_maskbits[(size_t)row0 * 32 + t];
        const unsigned long long mm1 = g_maskbits[(size_t)(row0 + 8) * 32 + t];

        // ---- scores ----
        float c[8][4];
#pragma unroll
        for (int nf = 0; nf < 8; nf++)
#pragma unroll
            for (int e = 0; e < 4; e++) c[nf][e] = 0.0f;

#pragma unroll
        for (int sg = 0; sg < 4; sg++) {
#pragma unroll
            for (int kf = 0; kf < 4; kf++) {
                const uint32_t ka = stg + (uint32_t)(sg * 16 * ATT_ROWB) +
                                    kf * 32 + boff;
                uint32_t tb[4], ts[4];
                ldsm4(tb, ka);
                ldsm4(ts, ka + ATT_TILE);
                mma_bf16(c[2 * sg], qbf[kf], tb);
                mma_bf16(c[2 * sg], qbf[kf], ts);
                mma_bf16(c[2 * sg], qsf[kf], tb);
                mma_bf16(c[2 * sg + 1], qbf[kf], tb + 2);
                mma_bf16(c[2 * sg + 1], qbf[kf], ts + 2);
                mma_bf16(c[2 * sg + 1], qsf[kf], tb + 2);
            }
        }

        // ---- mask via bit extraction ----
#pragma unroll
        for (int nf = 0; nf < 8; nf++) {
            const uint32_t b0 = (uint32_t)(mm0 >> (8 * nf + msh));
            const uint32_t b1 = (uint32_t)(mm1 >> (8 * nf + msh));
            c[nf][0] = (b0 & 1u) ? c[nf][0] : -1e30f;
            c[nf][1] = (b0 & 2u) ? c[nf][1] : -1e30f;
            c[nf][2] = (b1 & 1u) ? c[nf][2] : -1e30f;
            c[nf][3] = (b1 & 2u) ? c[nf][3] : -1e30f;
        }

        // ---- row max ----
        float rm0 = -INFINITY, rm1 = -INFINITY;
#pragma unroll
        for (int nf = 0; nf < 8; nf++) {
            rm0 = fmaxf(rm0, fmaxf(c[nf][0], c[nf][1]));
            rm1 = fmaxf(rm1, fmaxf(c[nf][2], c[nf][3]));
        }
        rm0 = fmaxf(rm0, __shfl_xor_sync(0xffffffffu, rm0, 1));
        rm0 = fmaxf(rm0, __shfl_xor_sync(0xffffffffu, rm0, 2));
        rm1 = fmaxf(rm1, __shfl_xor_sync(0xffffffffu, rm1, 1));
        rm1 = fmaxf(rm1, __shfl_xor_sync(0xffffffffu, rm1, 2));

        const float mn0 = fmaxf(mrun0, rm0);
        const float mn1 = fmaxf(mrun1, rm1);
        const float cr0 = exp_nm(mrun0 - mn0);
        const float cr1 = exp_nm(mrun1 - mn1);
        mrun0 = mn0; mrun1 = mn1;

        // ---- exp + row sums ----
        float ts0 = 0.0f, ts1 = 0.0f;
#pragma unroll
        for (int nf = 0; nf < 8; nf++) {
            c[nf][0] = exp_nm(c[nf][0] - mn0);
            c[nf][1] = exp_nm(c[nf][1] - mn0);
            c[nf][2] = exp_nm(c[nf][2] - mn1);
            c[nf][3] = exp_nm(c[nf][3] - mn1);
            ts0 += c[nf][0] + c[nf][1];
            ts1 += c[nf][2] + c[nf][3];
        }
        ts0 += __shfl_xor_sync(0xffffffffu, ts0, 1);
        ts0 += __shfl_xor_sync(0xffffffffu, ts0, 2);
        ts1 += __shfl_xor_sync(0xffffffffu, ts1, 1);
        ts1 += __shfl_xor_sync(0xffffffffu, ts1, 2);
        lrun0 = lrun0 * cr0 + ts0;
        lrun1 = lrun1 * cr1 + ts1;

#pragma unroll
        for (int nf = 0; nf < 8; nf++) {
            acc[nf][0] *= cr0; acc[nf][1] *= cr0;
            acc[nf][2] *= cr1; acc[nf][3] *= cr1;
        }

        // ---- PV ----
#pragma unroll
        for (int kf = 0; kf < 4; kf++) {
            uint32_t pab[4], pas[4];
#pragma unroll
            for (int q = 0; q < 2; q++) {
                const float* pc = c[2 * kf + q];
#pragma unroll
                for (int half = 0; half < 2; half++) {
                    float v0 = pc[2 * half], v1 = pc[2 * half + 1];
                    __nv_bfloat162 hb = __floats2bfloat162_rn(v0, v1);
                    __nv_bfloat162 hs = __floats2bfloat162_rn(
                        v0 - __bfloat162float(hb.x), v1 - __bfloat162float(hb.y));
                    pab[2 * q + half] = *(uint32_t*)&hb;
                    pas[2 * q + half] = *(uint32_t*)&hs;
                }
            }
#pragma unroll
            for (int dg = 0; dg < 4; dg++) {
                const uint32_t va = stg + 2 * ATT_TILE +
                    (uint32_t)((kf * 16 + (lane & 15)) * ATT_ROWB) +
                    dg * 32 + (lane >> 4) * 16;
                uint32_t vb[4], vs[4];
                ldsm4t(vb, va);
                ldsm4t(vs, va + ATT_TILE);
                mma_bf16(acc[2 * dg], pab, vb);
                mma_bf16(acc[2 * dg], pab, vs);
                mma_bf16(acc[2 * dg], pas, vb);
                mma_bf16(acc[2 * dg + 1], pab, vb + 2);
                mma_bf16(acc[2 * dg + 1], pab, vs + 2);
                mma_bf16(acc[2 * dg + 1], pas, vb + 2);
            }
        }
    }

    // ---- epilogue: normalize, split to bf16, write O-projection input ----
    const float inv0 = 1.0f / lrun0;
    const float inv1 = 1.0f / lrun1;
    const int b = bh >> 4;
    const int h = bh & 15;
    uint32_t* xb0 = (uint32_t*)g_xs0;   // slot 0
    uint32_t* xb1 = (uint32_t*)g_xs1;
#pragma unroll
    for (int nf = 0; nf < 8; nf++) {
        const int col = h * 64 + 8 * nf + 2 * (lane & 3);
#pragma unroll
        for (int half = 0; half < 2; half++) {
            const int rr = row0 + 8 * half;
            const float inv = half ? inv1 : inv0;
            float v0 = acc[nf][2 * half + 0] * inv;
            float v1 = acc[nf][2 * half + 1] * inv;
            __nv_bfloat162 hb = __floats2bfloat162_rn(v0, v1);
            __nv_bfloat162 hs = __floats2bfloat162_rn(
                v0 - __bfloat162float(hb.x), v1 - __bfloat162float(hb.y));
            size_t idx = ((size_t)(b * S_ + rr) * D_ + col) >> 1;
            xb0[idx] = *(uint32_t*)&hb;
            xb1[idx] = *(uint32_t*)&hs;
        }
    }
#undef LOAD_KV
}

// ---------------------------------------------------------------------------
// Launch
// ---------------------------------------------------------------------------
extern "C" void kernel_launch(void* const* d_in, const int* in_sizes, int n_in,
                              void* d_out, int out_size)
{
    const float* queries = (const float*)d_in[0];
    const float* keys    = (const float*)d_in[1];
    const float* values  = (const float*)d_in[2];
    const void*  mask    = d_in[3];
    const float* Wq = (const float*)d_in[4];
    const float* bq = (const float*)d_in[5];
    const float* Wk = (const float*)d_in[6];
    const float* bk = (const float*)d_in[7];
    const float* Wv = (const float*)d_in[8];
    const float* bv = (const float*)d_in[9];
    const float* Wo = (const float*)d_in[10];
    const float* bo = (const float*)d_in[11];
    float* out = (float*)d_out;

    (void)in_sizes; (void)n_in; (void)out_size;

    cudaFuncSetAttribute(mma_gemm_kernel,
                         cudaFuncAttributeMaxDynamicSharedMemorySize, GSMEM);
    cudaFuncSetAttribute(attn_mma_kernel,
                         cudaFuncAttributeMaxDynamicSharedMemorySize, ATT_SMEM);

    detect_mask_kernel<<<1, 256>>>((const unsigned char*)mask);
    mask_bits_kernel<<<128, 256>>>(mask);

    const dim3 tgrid(32, 32);
    const dim3 tblk(32, 8);

    // QKV prep
    split_wt_kernel<<<tgrid, tblk>>>(Wq, 0);
    split_wt_kernel<<<tgrid, tblk>>>(Wk, 1);
    split_wt_kernel<<<tgrid, tblk>>>(Wv, 2);
    split_x3_kernel<<<dim3((B_ * S_ * D_ / 4) / 256, 3), 256>>>(
        (const float4*)queries, (const float4*)keys, (const float4*)values);

    // fused QKV projections
    dim3 qkvgrid(D_ / 128, (B_ * S_) / 128, 3);     // (8, 64, 3)
    mma_gemm_kernel<<<qkvgrid, 256, GSMEM>>>(bq, bk, bv, nullptr, -1);

    // Wo split (slot 0 free after QKV gemm)
    split_wt_kernel<<<tgrid, tblk>>>(Wo, 0);

    // attention (writes bf16-split ctx into x slot 0)
    dim3 agrid(S_ / 128, B_ * H_);                  // (16, 64)
    attn_mma_kernel<<<agrid, 256, ATT_SMEM>>>();

    // O projection
    dim3 ogrid(D_ / 128, (B_ * S_) / 128, 1);
    mma_gemm_kernel<<<ogrid, 256, GSMEM>>>(bo, nullptr, nullptr, out, 0);
}

// round 12
// speedup vs baseline: 3.4478x; 1.0091x over previous
#include <cuda_runtime.h>
#include <cuda_bf16.h>
#include <math.h>
#include <stdint.h>

#define B_  4
#define S_  2048
#define D_  1024
#define H_  16
#define HD_ 64
#define SCALE_ 0.125f   // 1/sqrt(64)

// ---------------------------------------------------------------------------
// Scratch (allocation-free __device__ globals; uint4 for 16B cp.async align)
// ---------------------------------------------------------------------------
__device__ uint4 g_xs0[3 * 524288];      // int8 X hi, 3 slots x 8192x1024
__device__ uint4 g_xs1[3 * 524288];      // int8 X lo
__device__ uint4 g_wt0[3 * 65536];       // int8 W^T hi [n][k], 3 slots
__device__ uint4 g_wt1[3 * 65536];       // int8 W^T lo
__device__ float g_sx[3 * 8192];         // per-row X scales
__device__ float g_sw[3 * 1024];         // per-col W scales
__device__ uint2 g_qb0[(size_t)B_ * H_ * S_ * HD_ / 4];  // bf16 (B,H,S,HD)
__device__ uint2 g_qb1[(size_t)B_ * H_ * S_ * HD_ / 4];
__device__ uint2 g_kb0[(size_t)B_ * H_ * S_ * HD_ / 4];
__device__ uint2 g_kb1[(size_t)B_ * H_ * S_ * HD_ / 4];
__device__ uint2 g_vb0[(size_t)B_ * H_ * S_ * HD_ / 4];
__device__ uint2 g_vb1[(size_t)B_ * H_ * S_ * HD_ / 4];
__device__ uint32_t g_ctxb0[4194304];    // bf16x2 ctx big  (B,S,D)
__device__ uint32_t g_ctxb1[4194304];    // bf16x2 ctx small
__device__ unsigned long long g_maskbits[(size_t)S_ * S_ / 64];
__device__ int g_mask_is_byte;

// ---------------------------------------------------------------------------
// PTX helpers (sm_80-era: valid on plain compute_100 target)
// ---------------------------------------------------------------------------
__device__ __forceinline__ uint32_t smem_u32(const void* p) {
    uint32_t a;
    asm("{ .reg .u64 t; cvta.to.shared.u64 t, %1; cvt.u32.u64 %0, t; }"
        : "=r"(a) : "l"(p));
    return a;
}
#define CP_ASYNC16(dst, src) \
    asm volatile("cp.async.cg.shared.global [%0], [%1], 16;" \
                 :: "r"(dst), "l"(src) : "memory")
#define CP_COMMIT()  asm volatile("cp.async.commit_group;" ::: "memory")
#define CP_WAIT0()   asm volatile("cp.async.wait_group 0;" ::: "memory")

__device__ __forceinline__ void ldsm4(uint32_t* r, uint32_t addr) {
    asm volatile("ldmatrix.sync.aligned.m8n8.x4.shared.b16 {%0,%1,%2,%3}, [%4];"
                 : "=r"(r[0]), "=r"(r[1]), "=r"(r[2]), "=r"(r[3]) : "r"(addr));
}
__device__ __forceinline__ void ldsm4t(uint32_t* r, uint32_t addr) {
    asm volatile("ldmatrix.sync.aligned.m8n8.x4.trans.shared.b16 {%0,%1,%2,%3}, [%4];"
                 : "=r"(r[0]), "=r"(r[1]), "=r"(r[2]), "=r"(r[3]) : "r"(addr));
}
__device__ __forceinline__ void mma_bf16(float* c, const uint32_t* a,
                                         const uint32_t* b) {
    asm volatile(
        "mma.sync.aligned.m16n8k16.row.col.f32.bf16.bf16.f32 "
        "{%0,%1,%2,%3}, {%4,%5,%6,%7}, {%8,%9}, {%0,%1,%2,%3};"
        : "+f"(c[0]), "+f"(c[1]), "+f"(c[2]), "+f"(c[3])
        : "r"(a[0]), "r"(a[1]), "r"(a[2]), "r"(a[3]), "r"(b[0]), "r"(b[1]));
}
__device__ __forceinline__ void mma_s8(int* c, const uint32_t* a,
                                       const uint32_t* b) {
    asm volatile(
        "mma.sync.aligned.m16n8k32.row.col.s32.s8.s8.s32 "
        "{%0,%1,%2,%3}, {%4,%5,%6,%7}, {%8,%9}, {%0,%1,%2,%3};"
        : "+r"(c[0]), "+r"(c[1]), "+r"(c[2]), "+r"(c[3])
        : "r"(a[0]), "r"(a[1]), "r"(a[2]), "r"(a[3]), "r"(b[0]), "r"(b[1]));
}

// exp(d) for d <= 0 on the FMA pipe (no MUFU). rel err ~2.4e-6.
__device__ __forceinline__ float exp_nm(float d) {
    float y = fmaxf(d * 1.4426950408889634f, -80.0f);
    float fi = rintf(y);
    float f = y - fi;
    float p = 0.0013333558f;
    p = fmaf(p, f, 0.0096181291f);
    p = fmaf(p, f, 0.0555041087f);
    p = fmaf(p, f, 0.2402265070f);
    p = fmaf(p, f, 0.6931471806f);
    p = fmaf(p, f, 1.0f);
    return p * __int_as_float(((int)fi + 127) << 23);
}

// quantize u in [-127,127] units: hi = rint(u), lo = rint((u-hi)*256)
__device__ __forceinline__ void quant2(float u, int& h, int& l) {
    float hf = rintf(fminf(fmaxf(u, -127.0f), 127.0f));
    float lf = rintf(fminf(fmaxf((u - hf) * 256.0f, -127.0f), 127.0f));
    h = (int)hf; l = (int)lf;
}

// ---------------------------------------------------------------------------
// Mask dtype probe + bitmask (proven)
// ---------------------------------------------------------------------------
__global__ void detect_mask_kernel(const unsigned char* __restrict__ m) {
    __shared__ int any;
    if (threadIdx.x == 0) any = 0;
    __syncthreads();
    int found = 0;
    for (int i = threadIdx.x; i < 16384; i += 256)
        if (m[4 * i + 1] != 0) found = 1;
    if (found) atomicOr(&any, 1);
    __syncthreads();
    if (threadIdx.x == 0) g_mask_is_byte = any;
}

__global__ void mask_bits_kernel(const void* __restrict__ mraw) {
    const int wg   = (blockIdx.x * blockDim.x + threadIdx.x) >> 5;
    const int lane = threadIdx.x & 31;
    const int nw   = (gridDim.x * blockDim.x) >> 5;
    const int isb  = g_mask_is_byte;
    const unsigned char* m8 = (const unsigned char*)mraw;
    const int* m32 = (const int*)mraw;
    for (int chunk = wg; chunk < S_ * S_ / 64; chunk += nw) {
        const size_t base = (size_t)chunk * 64;
        int v0, v1;
        if (isb) { v0 = m8[base + lane] != 0; v1 = m8[base + 32 + lane] != 0; }
        else     { v0 = m32[base + lane] != 0; v1 = m32[base + 32 + lane] != 0; }
        uint32_t b0 = __ballot_sync(0xffffffffu, v0);
        uint32_t b1 = __ballot_sync(0xffffffffu, v1);
        if (lane == 0)
            g_maskbits[chunk] =
                (unsigned long long)b0 | ((unsigned long long)b1 << 32);
    }
}

// ---------------------------------------------------------------------------
// Quantize Q/K/V inputs: per-row 2-level int8. grid (1024, 3), block 256.
// One warp per row of 1024 floats.
// ---------------------------------------------------------------------------
__global__ void quant_x3_kernel(const float4* __restrict__ q,
                                const float4* __restrict__ k,
                                const float4* __restrict__ v)
{
    const int z    = blockIdx.y;
    const int lane = threadIdx.x & 31;
    const int row  = blockIdx.x * 8 + (threadIdx.x >> 5);
    const float4* src = ((z == 0) ? q : (z == 1) ? k : v) + (size_t)row * 256;

    float4 val[8];
    float mx = 1e-30f;
#pragma unroll
    for (int j = 0; j < 8; j++) {
        val[j] = src[lane + 32 * j];
        mx = fmaxf(mx, fmaxf(fmaxf(fabsf(val[j].x), fabsf(val[j].y)),
                             fmaxf(fabsf(val[j].z), fabsf(val[j].w))));
    }
#pragma unroll
    for (int o = 16; o >= 1; o >>= 1)
        mx = fmaxf(mx, __shfl_xor_sync(0xffffffffu, mx, o));

    const float s1 = mx / 127.0f;
    const float inv = 127.0f / mx;
    if (lane == 0) g_sx[z * 8192 + row] = s1;

    uint32_t* d0 = (uint32_t*)g_xs0 + (size_t)z * 2097152 + (size_t)row * 256;
    uint32_t* d1 = (uint32_t*)g_xs1 + (size_t)z * 2097152 + (size_t)row * 256;
#pragma unroll
    for (int j = 0; j < 8; j++) {
        int h0, l0, h1, l1, h2, l2, h3, l3;
        quant2(val[j].x * inv, h0, l0);
        quant2(val[j].y * inv, h1, l1);
        quant2(val[j].z * inv, h2, l2);
        quant2(val[j].w * inv, h3, l3);
        uint32_t ph = ((uint32_t)(uint8_t)h0) | ((uint32_t)(uint8_t)h1 << 8) |
                      ((uint32_t)(uint8_t)h2 << 16) | ((uint32_t)(uint8_t)h3 << 24);
        uint32_t pl = ((uint32_t)(uint8_t)l0) | ((uint32_t)(uint8_t)l1 << 8) |
                      ((uint32_t)(uint8_t)l2 << 16) | ((uint32_t)(uint8_t)l3 << 24);
        d0[lane + 32 * j] = ph;
        d1[lane + 32 * j] = pl;
    }
}

// ---------------------------------------------------------------------------
// Quantize ctx (bf16 pairs -> int8 slot 0). grid 1024, block 256.
// Lane owns 32 CONSECUTIVE elements; output uint32 index lane*8 + t covers
// elements lane*32 + 4t .. +3. Byte offset == element index.
// ---------------------------------------------------------------------------
__global__ void quant_ctx_kernel()
{
    const int lane = threadIdx.x & 31;
    const int row  = blockIdx.x * 8 + (threadIdx.x >> 5);
    const uint32_t* cb0 = g_ctxb0 + (size_t)row * 512 + lane * 16;
    const uint32_t* cb1 = g_ctxb1 + (size_t)row * 512 + lane * 16;

    float vv[32];                       // elements lane*32 .. lane*32+31
    float mx = 1e-30f;
#pragma unroll
    for (int j = 0; j < 16; j++) {
        uint32_t u0 = cb0[j];
        uint32_t u1 = cb1[j];
        __nv_bfloat162 hb = *(__nv_bfloat162*)&u0;
        __nv_bfloat162 hs = *(__nv_bfloat162*)&u1;
        float f0 = __bfloat162float(hb.x) + __bfloat162float(hs.x);
        float f1 = __bfloat162float(hb.y) + __bfloat162float(hs.y);
        vv[2 * j] = f0; vv[2 * j + 1] = f1;
        mx = fmaxf(mx, fmaxf(fabsf(f0), fabsf(f1)));
    }
#pragma unroll
    for (int o = 16; o >= 1; o >>= 1)
        mx = fmaxf(mx, __shfl_xor_sync(0xffffffffu, mx, o));

    const float s1 = mx / 127.0f;
    const float inv = 127.0f / mx;
    if (lane == 0) g_sx[row] = s1;   // slot 0

    uint32_t* d0 = (uint32_t*)g_xs0 + (size_t)row * 256 + lane * 8;
    uint32_t* d1 = (uint32_t*)g_xs1 + (size_t)row * 256 + lane * 8;
#pragma unroll
    for (int t = 0; t < 8; t++) {
        int h0, l0, h1, l1, h2, l2, h3, l3;
        quant2(vv[4 * t + 0] * inv, h0, l0);
        quant2(vv[4 * t + 1] * inv, h1, l1);
        quant2(vv[4 * t + 2] * inv, h2, l2);
        quant2(vv[4 * t + 3] * inv, h3, l3);
        uint32_t ph = ((uint32_t)(uint8_t)h0) | ((uint32_t)(uint8_t)h1 << 8) |
                      ((uint32_t)(uint8_t)h2 << 16) | ((uint32_t)(uint8_t)h3 << 24);
        uint32_t pl = ((uint32_t)(uint8_t)l0) | ((uint32_t)(uint8_t)l1 << 8) |
                      ((uint32_t)(uint8_t)l2 << 16) | ((uint32_t)(uint8_t)l3 << 24);
        d0[t] = ph;
        d1[t] = pl;
    }
}

// Quantize W -> WT int8 pairs + per-col scales. grid 32, block (32,8).
__global__ void quant_w_kernel(const float* __restrict__ W, int slot)
{
    __shared__ float pm[8][33];
    __shared__ float sscale[32];
    __shared__ float tile[32][33];
    const int tx = threadIdx.x, ty = threadIdx.y;
    const int n0 = blockIdx.x * 32;

    float mx = 1e-30f;
    for (int k = ty; k < D_; k += 8)
        mx = fmaxf(mx, fabsf(W[(size_t)k * D_ + n0 + tx]));
    pm[ty][tx] = mx;
    __syncthreads();
    if (ty == 0) {
        float m = pm[0][tx];
#pragma unroll
        for (int u = 1; u < 8; u++) m = fmaxf(m, pm[u][tx]);
        sscale[tx] = m / 127.0f;
        g_sw[slot * 1024 + n0 + tx] = m / 127.0f;
    }
    __syncthreads();

    char* wh = (char*)g_wt0 + (size_t)slot * 1048576;
    char* wl = (char*)g_wt1 + (size_t)slot * 1048576;
    for (int k0 = 0; k0 < D_; k0 += 32) {
#pragma unroll
        for (int j = 0; j < 4; j++)
            tile[ty + 8 * j][tx] = W[(size_t)(k0 + ty + 8 * j) * D_ + n0 + tx];
        __syncthreads();
#pragma unroll
        for (int j = 0; j < 4; j++) {
            const int n = ty + 8 * j;
            const float inv = 1.0f / sscale[n];
            float u = tile[tx][n] * inv;
            int h, l;
            quant2(u, h, l);
            wh[(size_t)(n0 + n) * D_ + k0 + tx] = (char)h;
            wl[(size_t)(n0 + n) * D_ + k0 + tx] = (char)l;
        }
        __syncthreads();
    }
}

// ---------------------------------------------------------------------------
// int8 2-level mma GEMM. 2-stage cp.async, 1 sync/k-tile, 2 CTAs/SM.
// Smem row (per operand): [32B hi | 32B lo | 16B pad] = 80B. Stage 20KB.
// ysel = -1: fused QKV (slot = blockIdx.z); ysel = 0: O projection.
// ---------------------------------------------------------------------------
#define TPB  10240
#define STGB (2 * TPB)      // 20480
#define GSMEM (2 * STGB)    // 40960

__global__ __launch_bounds__(256, 2)
void mma_gemm_kernel(const float* __restrict__ biasA,
                     const float* __restrict__ biasB,
                     const float* __restrict__ biasC,
                     float* __restrict__ Yext, int ysel)
{
    extern __shared__ char sm[];
    const uint32_t sbase = smem_u32(sm);

    const int tid  = threadIdx.x;
    const int wid  = tid >> 5;
    const int lane = tid & 31;
    const int wm   = wid >> 2;
    const int wn   = wid & 3;
    const int m0   = blockIdx.y * 128;
    const int n0   = blockIdx.x * 128;
    const int z    = blockIdx.z;
    const int slot = (ysel < 0) ? z : 0;
    const int ysl  = (ysel < 0) ? (z + 1) : 0;
    const float* bias = (ysel >= 0) ? biasA
                      : (z == 0) ? biasA : (z == 1) ? biasB : biasC;

    const char* pxh = (const char*)g_xs0 + (size_t)slot * 8388608;
    const char* pxl = (const char*)g_xs1 + (size_t)slot * 8388608;
    const char* pwh = (const char*)g_wt0 + (size_t)slot * 1048576;
    const char* pwl = (const char*)g_wt1 + (size_t)slot * 1048576;

    const int lrow = tid >> 1;
    const int lop  = tid & 1;
    const char* lsh = lop ? pwh : pxh;
    const char* lsl = lop ? pwl : pxl;
    const int lgb   = lop ? n0 : m0;
    const uint32_t ldst0 = lop * TPB + (uint32_t)lrow * 80;

    int A1[4][4][4];
#pragma unroll
    for (int i = 0; i < 4; i++)
#pragma unroll
        for (int j = 0; j < 4; j++)
#pragma unroll
            for (int e = 0; e < 4; e++) A1[i][j][e] = 0;

#define LOAD_STAGE(st, kt) do {                                               \
    const uint32_t d = sbase + (st) * STGB + ldst0;                           \
    const size_t g = (size_t)(lgb + lrow) * 1024 + (kt) * 32;                 \
    CP_ASYNC16(d,      lsh + g);                                              \
    CP_ASYNC16(d + 16, lsh + g + 16);                                         \
    CP_ASYNC16(d + 32, lsl + g);                                              \
    CP_ASYNC16(d + 48, lsl + g + 16);                                         \
    CP_COMMIT();                                                              \
} while (0)

    const uint32_t aoffs = (uint32_t)((lane & 15) * 80 + (lane >> 4) * 16);
    const uint32_t boffs = (uint32_t)(((lane >> 4) * 8 + (lane & 7)) * 80 +
                                      ((lane >> 3) & 1) * 16);

    LOAD_STAGE(0, 0);

    const int NT = D_ / 32;       // 32 k-tiles
    for (int kt = 0; kt < NT; kt++) {
        CP_WAIT0();
        __syncthreads();
        if (kt + 1 < NT) LOAD_STAGE((kt + 1) & 1, kt + 1);

        const uint32_t sb = sbase + (kt & 1) * STGB;

        uint32_t ahi[4][4], alo[4][4];
#pragma unroll
        for (int i = 0; i < 4; i++) {
            const uint32_t ad =
                sb + (uint32_t)((wm * 64 + 16 * i) * 80) + aoffs;
            ldsm4(ahi[i], ad);
            ldsm4(alo[i], ad + 32);
        }
        uint32_t bhi[4][2], blo[4][2];
#pragma unroll
        for (int p = 0; p < 2; p++) {
            const uint32_t bd =
                sb + TPB + (uint32_t)((wn * 32 + 16 * p) * 80) + boffs;
            uint32_t t0[4], t1[4];
            ldsm4(t0, bd);
            ldsm4(t1, bd + 32);
            bhi[2 * p][0] = t0[0]; bhi[2 * p][1] = t0[1];
            bhi[2 * p + 1][0] = t0[2]; bhi[2 * p + 1][1] = t0[3];
            blo[2 * p][0] = t1[0]; blo[2 * p][1] = t1[1];
            blo[2 * p + 1][0] = t1[2]; blo[2 * p + 1][1] = t1[3];
        }
#pragma unroll
        for (int i = 0; i < 4; i++)
#pragma unroll
            for (int j = 0; j < 4; j++) {
                int a2[4] = {0, 0, 0, 0};
                mma_s8(a2, ahi[i], blo[j]);
                mma_s8(a2, alo[i], bhi[j]);
                mma_s8(A1[i][j], ahi[i], bhi[j]);
#pragma unroll
                for (int e = 0; e < 4; e++)
                    A1[i][j][e] += (a2[e] + 128) >> 8;
            }
    }

    // ---- epilogue: apply scales + bias ----
    const float* sxp = g_sx + slot * 8192;
    const float* swp = g_sw + slot * 1024;

    if (ysl == 0) {
#pragma unroll
        for (int i = 0; i < 4; i++) {
            const int r0 = m0 + wm * 64 + 16 * i + (lane >> 2);
            const float sxa = sxp[r0], sxb = sxp[r0 + 8];
#pragma unroll
            for (int j = 0; j < 4; j++) {
                const int colp = n0 + wn * 32 + 8 * j + 2 * (lane & 3);
                const float swa = swp[colp], swb = swp[colp + 1];
                const float bx = bias[colp], by = bias[colp + 1];
                float2 v0 = {(float)A1[i][j][0] * (sxa * swa) + bx,
                             (float)A1[i][j][1] * (sxa * swb) + by};
                float2 v1 = {(float)A1[i][j][2] * (sxb * swa) + bx,
                             (float)A1[i][j][3] * (sxb * swb) + by};
                *(float2*)&Yext[(size_t)r0 * D_ + colp] = v0;
                *(float2*)&Yext[(size_t)(r0 + 8) * D_ + colp] = v1;
            }
        }
    } else {
        uint32_t* d0 = (ysl == 1) ? (uint32_t*)g_qb0
                     : (ysl == 2) ? (uint32_t*)g_kb0 : (uint32_t*)g_vb0;
        uint32_t* d1 = (ysl == 1) ? (uint32_t*)g_qb1
                     : (ysl == 2) ? (uint32_t*)g_kb1 : (uint32_t*)g_vb1;
        const float scl = (ysl == 1) ? SCALE_ : 1.0f;
#pragma unroll
        for (int i = 0; i < 4; i++) {
            const int r0 = m0 + wm * 64 + 16 * i + (lane >> 2);
            const float sxa = sxp[r0] * scl, sxb = sxp[r0 + 8] * scl;
#pragma unroll
            for (int j = 0; j < 4; j++) {
                const int colp = n0 + wn * 32 + 8 * j + 2 * (lane & 3);
                const float swa = swp[colp], swb = swp[colp + 1];
                const float bx = bias[colp] * scl, by = bias[colp + 1] * scl;
                const int h = colp >> 6;
                const int d = colp & 63;
#pragma unroll
                for (int half = 0; half < 2; half++) {
                    const int rr = r0 + 8 * half;
                    const int bb = rr >> 11, s = rr & (S_ - 1);
                    const float sx = half ? sxb : sxa;
                    float vx = (float)A1[i][j][2 * half + 0] * (sx * swa) + bx;
                    float vy = (float)A1[i][j][2 * half + 1] * (sx * swb) + by;
                    __nv_bfloat162 hb = __floats2bfloat162_rn(vx, vy);
                    __nv_bfloat162 hs = __floats2bfloat162_rn(
                        vx - __bfloat162float(hb.x), vy - __bfloat162float(hb.y));
                    size_t idx =
                        (((size_t)(bb * H_ + h) * S_ + s) * HD_ + d) >> 1;
                    d0[idx] = *(uint32_t*)&hb;
                    d1[idx] = *(uint32_t*)&hs;
                }
            }
        }
    }
#undef LOAD_STAGE
}

// ---------------------------------------------------------------------------
// Tensor-core flash attention (proven R8 core; ctx pair arrays as output)
// ---------------------------------------------------------------------------
#define ATT_ROWB 144
#define ATT_TILE (64 * ATT_ROWB)
#define ATT_STAGE (4 * ATT_TILE)
#define ATT_SMEM (2 * ATT_STAGE)

__global__ __launch_bounds__(256, 2)
void attn_mma_kernel()
{
    extern __shared__ char sm[];
    const uint32_t sb = smem_u32(sm);

    const int tid  = threadIdx.x;
    const int wid  = tid >> 5;
    const int lane = tid & 31;
    const int q0   = blockIdx.x * 128;
    const int bh   = blockIdx.y;

    const size_t off = (size_t)bh * S_ * HD_ * 2;
    const char* pq0 = (const char*)g_qb0 + off;
    const char* pq1 = (const char*)g_qb1 + off;
    const char* pk0 = (const char*)g_kb0 + off;
    const char* pk1 = (const char*)g_kb1 + off;
    const char* pv0 = (const char*)g_vb0 + off;
    const char* pv1 = (const char*)g_vb1 + off;

#pragma unroll
    for (int sg = 0; sg < 4; sg++) {
        const int seg = tid + 256 * sg;
        const int row = seg >> 3, c16 = seg & 7;
        const size_t gsrc = (size_t)(q0 + row) * 128 + c16 * 16;
        const uint32_t dd = (uint32_t)(row * ATT_ROWB + c16 * 16);
        CP_ASYNC16(sb + dd, pq0 + gsrc);
        CP_ASYNC16(sb + 18432 + dd, pq1 + gsrc);
    }
    CP_COMMIT(); CP_WAIT0(); __syncthreads();

    uint32_t qbf[4][4], qsf[4][4];
    {
        const uint32_t ao = (uint32_t)((wid * 16 + (lane & 15)) * ATT_ROWB +
                                       (lane >> 4) * 16);
#pragma unroll
        for (int kf = 0; kf < 4; kf++) {
            ldsm4(qbf[kf], sb + ao + kf * 32);
            ldsm4(qsf[kf], sb + 18432 + ao + kf * 32);
        }
    }
    __syncthreads();

    float acc[8][4];
#pragma unroll
    for (int nf = 0; nf < 8; nf++)
#pragma unroll
        for (int e = 0; e < 4; e++) acc[nf][e] = 0.0f;
    float mrun0 = -INFINITY, mrun1 = -INFINITY, lrun0 = 0.0f, lrun1 = 0.0f;

#define LOAD_KV(st, t) do {                                                   \
    const uint32_t stg_ = sb + (st) * ATT_STAGE;                              \
    const int kk0_ = (t) * 64;                                                \
    _Pragma("unroll")                                                         \
    for (int jj = 0; jj < 2; jj++) {                                          \
        const int seg = tid + 256 * jj;                                       \
        const int row = seg >> 3, c16 = seg & 7;                              \
        const size_t gs = (size_t)(kk0_ + row) * 128 + c16 * 16;              \
        const uint32_t dd = (uint32_t)(row * ATT_ROWB + c16 * 16);            \
        CP_ASYNC16(stg_ + 0 * ATT_TILE + dd, pk0 + gs);                       \
        CP_ASYNC16(stg_ + 1 * ATT_TILE + dd, pk1 + gs);                       \
        CP_ASYNC16(stg_ + 2 * ATT_TILE + dd, pv0 + gs);                       \
        CP_ASYNC16(stg_ + 3 * ATT_TILE + dd, pv1 + gs);                       \
    }                                                                         \
    CP_COMMIT();                                                              \
} while (0)

    LOAD_KV(0, 0);

    const uint32_t boff = (uint32_t)(((lane >> 4) * 8 + (lane & 7)) * ATT_ROWB +
                                     ((lane >> 3) & 1) * 16);
    const int row0 = q0 + wid * 16 + (lane >> 2);
    const uint32_t msh = 2 * (lane & 3);

    for (int t = 0; t < S_ / 64; t++) {
        CP_WAIT0();
        __syncthreads();
        if (t + 1 < S_ / 64) LOAD_KV((t + 1) & 1, t + 1);

        const uint32_t stg = sb + (t & 1) * ATT_STAGE;

        const unsigned long long mm0 = g_maskbits[(size_t)row0 * 32 + t];
        const unsigned long long mm1 = g_maskbits[(size_t)(row0 + 8) * 32 + t];

        float c[8][4];
#pragma unroll
        for (int nf = 0; nf < 8; nf++)
#pragma unroll
            for (int e = 0; e < 4; e++) c[nf][e] = 0.0f;

#pragma unroll
        for (int sg = 0; sg < 4; sg++) {
#pragma unroll
            for (int kf = 0; kf < 4; kf++) {
                const uint32_t ka = stg + (uint32_t)(sg * 16 * ATT_ROWB) +
                                    kf * 32 + boff;
                uint32_t tb[4], ts[4];
                ldsm4(tb, ka);
                ldsm4(ts, ka + ATT_TILE);
                mma_bf16(c[2 * sg], qbf[kf], tb);
                mma_bf16(c[2 * sg], qbf[kf], ts);
                mma_bf16(c[2 * sg], qsf[kf], tb);
                mma_bf16(c[2 * sg + 1], qbf[kf], tb + 2);
                mma_bf16(c[2 * sg + 1], qbf[kf], ts + 2);
                mma_bf16(c[2 * sg + 1], qsf[kf], tb + 2);
            }
        }

#pragma unroll
        for (int nf = 0; nf < 8; nf++) {
            const uint32_t b0 = (uint32_t)(mm0 >> (8 * nf + msh));
            const uint32_t b1 = (uint32_t)(mm1 >> (8 * nf + msh));
            c[nf][0] = (b0 & 1u) ? c[nf][0] : -1e30f;
            c[nf][1] = (b0 & 2u) ? c[nf][1] : -1e30f;
            c[nf][2] = (b1 & 1u) ? c[nf][2] : -1e30f;
            c[nf][3] = (b1 & 2u) ? c[nf][3] : -1e30f;
        }

        float rm0 = -INFINITY, rm1 = -INFINITY;
#pragma unroll
        for (int nf = 0; nf < 8; nf++) {
            rm0 = fmaxf(rm0, fmaxf(c[nf][0], c[nf][1]));
            rm1 = fmaxf(rm1, fmaxf(c[nf][2], c[nf][3]));
        }
        rm0 = fmaxf(rm0, __shfl_xor_sync(0xffffffffu, rm0, 1));
        rm0 = fmaxf(rm0, __shfl_xor_sync(0xffffffffu, rm0, 2));
        rm1 = fmaxf(rm1, __shfl_xor_sync(0xffffffffu, rm1, 1));
        rm1 = fmaxf(rm1, __shfl_xor_sync(0xffffffffu, rm1, 2));

        const float mn0 = fmaxf(mrun0, rm0);
        const float mn1 = fmaxf(mrun1, rm1);
        const float cr0 = exp_nm(mrun0 - mn0);
        const float cr1 = exp_nm(mrun1 - mn1);
        mrun0 = mn0; mrun1 = mn1;

        float ts0 = 0.0f, ts1 = 0.0f;
#pragma unroll
        for (int nf = 0; nf < 8; nf++) {
            c[nf][0] = exp_nm(c[nf][0] - mn0);
            c[nf][1] = exp_nm(c[nf][1] - mn0);
            c[nf][2] = exp_nm(c[nf][2] - mn1);
            c[nf][3] = exp_nm(c[nf][3] - mn1);
            ts0 += c[nf][0] + c[nf][1];
            ts1 += c[nf][2] + c[nf][3];
        }
        ts0 += __shfl_xor_sync(0xffffffffu, ts0, 1);
        ts0 += __shfl_xor_sync(0xffffffffu, ts0, 2);
        ts1 += __shfl_xor_sync(0xffffffffu, ts1, 1);
        ts1 += __shfl_xor_sync(0xffffffffu, ts1, 2);
        lrun0 = lrun0 * cr0 + ts0;
        lrun1 = lrun1 * cr1 + ts1;

#pragma unroll
        for (int nf = 0; nf < 8; nf++) {
            acc[nf][0] *= cr0; acc[nf][1] *= cr0;
            acc[nf][2] *= cr1; acc[nf][3] *= cr1;
        }

#pragma unroll
        for (int kf = 0; kf < 4; kf++) {
            uint32_t pab[4], pas[4];
#pragma unroll
            for (int q = 0; q < 2; q++) {
                const float* pc = c[2 * kf + q];
#pragma unroll
                for (int half = 0; half < 2; half++) {
                    float v0 = pc[2 * half], v1 = pc[2 * half + 1];
                    __nv_bfloat162 hb = __floats2bfloat162_rn(v0, v1);
                    __nv_bfloat162 hs = __floats2bfloat162_rn(
                        v0 - __bfloat162float(hb.x), v1 - __bfloat162float(hb.y));
                    pab[2 * q + half] = *(uint32_t*)&hb;
                    pas[2 * q + half] = *(uint32_t*)&hs;
                }
            }
#pragma unroll
            for (int dg = 0; dg < 4; dg++) {
                const uint32_t va = stg + 2 * ATT_TILE +
                    (uint32_t)((kf * 16 + (lane & 15)) * ATT_ROWB) +
                    dg * 32 + (lane >> 4) * 16;
                uint32_t vb[4], vs[4];
                ldsm4t(vb, va);
                ldsm4t(vs, va + ATT_TILE);
                mma_bf16(acc[2 * dg], pab, vb);
                mma_bf16(acc[2 * dg], pab, vs);
                mma_bf16(acc[2 * dg], pas, vb);
                mma_bf16(acc[2 * dg + 1], pab, vb + 2);
                mma_bf16(acc[2 * dg + 1], pab, vs + 2);
                mma_bf16(acc[2 * dg + 1], pas, vb + 2);
            }
        }
    }

    // ---- epilogue: normalize, split to bf16, write ctx pair arrays ----
    const float inv0 = 1.0f / lrun0;
    const float inv1 = 1.0f / lrun1;
    const int b = bh >> 4;
    const int h = bh & 15;
#pragma unroll
    for (int nf = 0; nf < 8; nf++) {
        const int col = h * 64 + 8 * nf + 2 * (lane & 3);
#pragma unroll
        for (int half = 0; half < 2; half++) {
            const int rr = row0 + 8 * half;
            const float inv = half ? inv1 : inv0;
            float v0 = acc[nf][2 * half + 0] * inv;
            float v1 = acc[nf][2 * half + 1] * inv;
            __nv_bfloat162 hb = __floats2bfloat162_rn(v0, v1);
            __nv_bfloat162 hs = __floats2bfloat162_rn(
                v0 - __bfloat162float(hb.x), v1 - __bfloat162float(hb.y));
            size_t idx = ((size_t)(b * S_ + rr) * D_ + col) >> 1;
            g_ctxb0[idx] = *(uint32_t*)&hb;
            g_ctxb1[idx] = *(uint32_t*)&hs;
        }
    }
#undef LOAD_KV
}

// ---------------------------------------------------------------------------
// Launch
// ---------------------------------------------------------------------------
extern "C" void kernel_launch(void* const* d_in, const int* in_sizes, int n_in,
                              void* d_out, int out_size)
{
    const float* queries = (const float*)d_in[0];
    const float* keys    = (const float*)d_in[1];
    const float* values  = (const float*)d_in[2];
    const void*  mask    = d_in[3];
    const float* Wq = (const float*)d_in[4];
    const float* bq = (const float*)d_in[5];
    const float* Wk = (const float*)d_in[6];
    const float* bk = (const float*)d_in[7];
    const float* Wv = (const float*)d_in[8];
    const float* bv = (const float*)d_in[9];
    const float* Wo = (const float*)d_in[10];
    const float* bo = (const float*)d_in[11];
    float* out = (float*)d_out;

    (void)in_sizes; (void)n_in; (void)out_size;

    cudaFuncSetAttribute(mma_gemm_kernel,
                         cudaFuncAttributeMaxDynamicSharedMemorySize, GSMEM);
    cudaFuncSetAttribute(attn_mma_kernel,
                         cudaFuncAttributeMaxDynamicSharedMemorySize, ATT_SMEM);

    detect_mask_kernel<<<1, 256>>>((const unsigned char*)mask);
    mask_bits_kernel<<<128, 256>>>(mask);

    const dim3 wblk(32, 8);

    // QKV quantization prep
    quant_w_kernel<<<32, wblk>>>(Wq, 0);
    quant_w_kernel<<<32, wblk>>>(Wk, 1);
    quant_w_kernel<<<32, wblk>>>(Wv, 2);
    quant_x3_kernel<<<dim3(1024, 3), 256>>>(
        (const float4*)queries, (const float4*)keys, (const float4*)values);

    // fused QKV projections (int8)
    dim3 qkvgrid(D_ / 128, (B_ * S_) / 128, 3);
    mma_gemm_kernel<<<qkvgrid, 256, GSMEM>>>(bq, bk, bv, nullptr, -1);

    // Wo quant (slot 0 free after QKV gemm)
    quant_w_kernel<<<32, wblk>>>(Wo, 0);

    // attention (bf16, writes ctx bf16 pairs)
    dim3 agrid(S_ / 128, B_ * H_);
    attn_mma_kernel<<<agrid, 256, ATT_SMEM>>>();

    // ctx quantization + O projection
    quant_ctx_kernel<<<1024, 256>>>();
    dim3 ogrid(D_ / 128, (B_ * S_) / 128, 1);
    mma_gemm_kernel<<<ogrid, 256, GSMEM>>>(bo, nullptr, nullptr, out, 0);
}

// round 15
// speedup vs baseline: 3.6766x; 1.0664x over previous
#include <cuda_runtime.h>
#include <cuda_bf16.h>
#include <math.h>
#include <stdint.h>

#define B_  4
#define S_  2048
#define D_  1024
#define H_  16
#define HD_ 64
#define SCALE_ 0.125f   // 1/sqrt(64)

// ---------------------------------------------------------------------------
// Scratch (allocation-free __device__ globals)
// ---------------------------------------------------------------------------
__device__ uint4 g_xs0[3 * 524288];      // int8 X hi, 3 slots x 8192x1024
__device__ uint4 g_xs1[3 * 524288];      // int8 X lo
__device__ uint4 g_wt0[4 * 65536];       // int8 W^T hi [n][k], 4 slots
__device__ uint4 g_wt1[4 * 65536];       // int8 W^T lo
__device__ float g_sx[3 * 8192];         // per-row X scales
__device__ float g_sw[4 * 1024];         // per-col W scales
__device__ uint2 g_qb0[(size_t)B_ * H_ * S_ * HD_ / 4];  // bf16 (B,H,S,HD)
__device__ uint2 g_qb1[(size_t)B_ * H_ * S_ * HD_ / 4];
__device__ uint2 g_kb0[(size_t)B_ * H_ * S_ * HD_ / 4];
__device__ uint2 g_kb1[(size_t)B_ * H_ * S_ * HD_ / 4];
__device__ uint2 g_vb0[(size_t)B_ * H_ * S_ * HD_ / 4];
__device__ uint2 g_vb1[(size_t)B_ * H_ * S_ * HD_ / 4];
__device__ uint4 g_q8h[524288];          // int8 Q hi (B,H,S,HD) 8MB
__device__ uint4 g_q8l[524288];
__device__ uint4 g_k8h[524288];
__device__ uint4 g_k8l[524288];
__device__ float g_sq[131072];           // per (bh,s) Q scale (incl SCALE_)
__device__ float g_sk[131072];           // per (bh,s) K scale
__device__ uint32_t g_ctxb0[4194304];    // bf16x2 ctx big  (B,S,D)
__device__ uint32_t g_ctxb1[4194304];
__device__ unsigned long long g_maskbits[(size_t)S_ * S_ / 64];
__device__ int g_mask_is_byte;

// ---------------------------------------------------------------------------
// PTX helpers
// ---------------------------------------------------------------------------
__device__ __forceinline__ uint32_t smem_u32(const void* p) {
    uint32_t a;
    asm("{ .reg .u64 t; cvta.to.shared.u64 t, %1; cvt.u32.u64 %0, t; }"
        : "=r"(a) : "l"(p));
    return a;
}
#define CP_ASYNC16(dst, src) \
    asm volatile("cp.async.cg.shared.global [%0], [%1], 16;" \
                 :: "r"(dst), "l"(src) : "memory")
#define CP_COMMIT()  asm volatile("cp.async.commit_group;" ::: "memory")
#define CP_WAIT0()   asm volatile("cp.async.wait_group 0;" ::: "memory")

__device__ __forceinline__ void ldsm4(uint32_t* r, uint32_t addr) {
    asm volatile("ldmatrix.sync.aligned.m8n8.x4.shared.b16 {%0,%1,%2,%3}, [%4];"
                 : "=r"(r[0]), "=r"(r[1]), "=r"(r[2]), "=r"(r[3]) : "r"(addr));
}
__device__ __forceinline__ void ldsm4t(uint32_t* r, uint32_t addr) {
    asm volatile("ldmatrix.sync.aligned.m8n8.x4.trans.shared.b16 {%0,%1,%2,%3}, [%4];"
                 : "=r"(r[0]), "=r"(r[1]), "=r"(r[2]), "=r"(r[3]) : "r"(addr));
}
__device__ __forceinline__ void mma_bf16(float* c, const uint32_t* a,
                                         const uint32_t* b) {
    asm volatile(
        "mma.sync.aligned.m16n8k16.row.col.f32.bf16.bf16.f32 "
        "{%0,%1,%2,%3}, {%4,%5,%6,%7}, {%8,%9}, {%0,%1,%2,%3};"
        : "+f"(c[0]), "+f"(c[1]), "+f"(c[2]), "+f"(c[3])
        : "r"(a[0]), "r"(a[1]), "r"(a[2]), "r"(a[3]), "r"(b[0]), "r"(b[1]));
}
__device__ __forceinline__ void mma_s8(int* c, const uint32_t* a,
                                       const uint32_t* b) {
    asm volatile(
        "mma.sync.aligned.m16n8k32.row.col.s32.s8.s8.s32 "
        "{%0,%1,%2,%3}, {%4,%5,%6,%7}, {%8,%9}, {%0,%1,%2,%3};"
        : "+r"(c[0]), "+r"(c[1]), "+r"(c[2]), "+r"(c[3])
        : "r"(a[0]), "r"(a[1]), "r"(a[2]), "r"(a[3]), "r"(b[0]), "r"(b[1]));
}

// exp(d) for d <= 0 on the FMA pipe (no MUFU). rel err ~2.4e-6.
__device__ __forceinline__ float exp_nm(float d) {
    float y = fmaxf(d * 1.4426950408889634f, -80.0f);
    float fi = rintf(y);
    float f = y - fi;
    float p = 0.0013333558f;
    p = fmaf(p, f, 0.0096181291f);
    p = fmaf(p, f, 0.0555041087f);
    p = fmaf(p, f, 0.2402265070f);
    p = fmaf(p, f, 0.6931471806f);
    p = fmaf(p, f, 1.0f);
    return p * __int_as_float(((int)fi + 127) << 23);
}

// quantize u in [-127,127] units: hi = rint(u), lo = rint((u-hi)*256)
__device__ __forceinline__ void quant2(float u, int& h, int& l) {
    float hf = rintf(fminf(fmaxf(u, -127.0f), 127.0f));
    float lf = rintf(fminf(fmaxf((u - hf) * 256.0f, -127.0f), 127.0f));
    h = (int)hf; l = (int)lf;
}

// ---------------------------------------------------------------------------
// Mask dtype probe + bitmask (proven)
// ---------------------------------------------------------------------------
__global__ void detect_mask_kernel(const unsigned char* __restrict__ m) {
    __shared__ int any;
    if (threadIdx.x == 0) any = 0;
    __syncthreads();
    int found = 0;
    for (int i = threadIdx.x; i < 16384; i += 256)
        if (m[4 * i + 1] != 0) found = 1;
    if (found) atomicOr(&any, 1);
    __syncthreads();
    if (threadIdx.x == 0) g_mask_is_byte = any;
}

__global__ void mask_bits_kernel(const void* __restrict__ mraw) {
    const int wg   = (blockIdx.x * blockDim.x + threadIdx.x) >> 5;
    const int lane = threadIdx.x & 31;
    const int nw   = (gridDim.x * blockDim.x) >> 5;
    const int isb  = g_mask_is_byte;
    const unsigned char* m8 = (const unsigned char*)mraw;
    const int* m32 = (const int*)mraw;
    for (int chunk = wg; chunk < S_ * S_ / 64; chunk += nw) {
        const size_t base = (size_t)chunk * 64;
        int v0, v1;
        if (isb) { v0 = m8[base + lane] != 0; v1 = m8[base + 32 + lane] != 0; }
        else     { v0 = m32[base + lane] != 0; v1 = m32[base + 32 + lane] != 0; }
        uint32_t b0 = __ballot_sync(0xffffffffu, v0);
        uint32_t b1 = __ballot_sync(0xffffffffu, v1);
        if (lane == 0)
            g_maskbits[chunk] =
                (unsigned long long)b0 | ((unsigned long long)b1 << 32);
    }
}

// ---------------------------------------------------------------------------
// Quantize Q/K/V inputs (proven)
// ---------------------------------------------------------------------------
__global__ void quant_x3_kernel(const float4* __restrict__ q,
                                const float4* __restrict__ k,
                                const float4* __restrict__ v)
{
    const int z    = blockIdx.y;
    const int lane = threadIdx.x & 31;
    const int row  = blockIdx.x * 8 + (threadIdx.x >> 5);
    const float4* src = ((z == 0) ? q : (z == 1) ? k : v) + (size_t)row * 256;

    float4 val[8];
    float mx = 1e-30f;
#pragma unroll
    for (int j = 0; j < 8; j++) {
        val[j] = src[lane + 32 * j];
        mx = fmaxf(mx, fmaxf(fmaxf(fabsf(val[j].x), fabsf(val[j].y)),
                             fmaxf(fabsf(val[j].z), fabsf(val[j].w))));
    }
#pragma unroll
    for (int o = 16; o >= 1; o >>= 1)
        mx = fmaxf(mx, __shfl_xor_sync(0xffffffffu, mx, o));

    const float s1 = mx / 127.0f;
    const float inv = 127.0f / mx;
    if (lane == 0) g_sx[z * 8192 + row] = s1;

    uint32_t* d0 = (uint32_t*)g_xs0 + (size_t)z * 2097152 + (size_t)row * 256;
    uint32_t* d1 = (uint32_t*)g_xs1 + (size_t)z * 2097152 + (size_t)row * 256;
#pragma unroll
    for (int j = 0; j < 8; j++) {
        int h0, l0, h1, l1, h2, l2, h3, l3;
        quant2(val[j].x * inv, h0, l0);
        quant2(val[j].y * inv, h1, l1);
        quant2(val[j].z * inv, h2, l2);
        quant2(val[j].w * inv, h3, l3);
        uint32_t ph = ((uint32_t)(uint8_t)h0) | ((uint32_t)(uint8_t)h1 << 8) |
                      ((uint32_t)(uint8_t)h2 << 16) | ((uint32_t)(uint8_t)h3 << 24);
        uint32_t pl = ((uint32_t)(uint8_t)l0) | ((uint32_t)(uint8_t)l1 << 8) |
                      ((uint32_t)(uint8_t)l2 << 16) | ((uint32_t)(uint8_t)l3 << 24);
        d0[lane + 32 * j] = ph;
        d1[lane + 32 * j] = pl;
    }
}

// Quantize ctx (proven R12 version)
__global__ void quant_ctx_kernel()
{
    const int lane = threadIdx.x & 31;
    const int row  = blockIdx.x * 8 + (threadIdx.x >> 5);
    const uint32_t* cb0 = g_ctxb0 + (size_t)row * 512 + lane * 16;
    const uint32_t* cb1 = g_ctxb1 + (size_t)row * 512 + lane * 16;

    float vv[32];
    float mx = 1e-30f;
#pragma unroll
    for (int j = 0; j < 16; j++) {
        uint32_t u0 = cb0[j];
        uint32_t u1 = cb1[j];
        __nv_bfloat162 hb = *(__nv_bfloat162*)&u0;
        __nv_bfloat162 hs = *(__nv_bfloat162*)&u1;
        float f0 = __bfloat162float(hb.x) + __bfloat162float(hs.x);
        float f1 = __bfloat162float(hb.y) + __bfloat162float(hs.y);
        vv[2 * j] = f0; vv[2 * j + 1] = f1;
        mx = fmaxf(mx, fmaxf(fabsf(f0), fabsf(f1)));
    }
#pragma unroll
    for (int o = 16; o >= 1; o >>= 1)
        mx = fmaxf(mx, __shfl_xor_sync(0xffffffffu, mx, o));

    const float s1 = mx / 127.0f;
    const float inv = 127.0f / mx;
    if (lane == 0) g_sx[row] = s1;   // slot 0

    uint32_t* d0 = (uint32_t*)g_xs0 + (size_t)row * 256 + lane * 8;
    uint32_t* d1 = (uint32_t*)g_xs1 + (size_t)row * 256 + lane * 8;
#pragma unroll
    for (int t = 0; t < 8; t++) {
        int h0, l0, h1, l1, h2, l2, h3, l3;
        quant2(vv[4 * t + 0] * inv, h0, l0);
        quant2(vv[4 * t + 1] * inv, h1, l1);
        quant2(vv[4 * t + 2] * inv, h2, l2);
        quant2(vv[4 * t + 3] * inv, h3, l3);
        uint32_t ph = ((uint32_t)(uint8_t)h0) | ((uint32_t)(uint8_t)h1 << 8) |
                      ((uint32_t)(uint8_t)h2 << 16) | ((uint32_t)(uint8_t)h3 << 24);
        uint32_t pl = ((uint32_t)(uint8_t)l0) | ((uint32_t)(uint8_t)l1 << 8) |
                      ((uint32_t)(uint8_t)l2 << 16) | ((uint32_t)(uint8_t)l3 << 24);
        d0[t] = ph;
        d1[t] = pl;
    }
}

// Quantize ALL FOUR W -> WT int8 pairs. grid (32, 4), block (32,8).
__global__ void quant_w4_kernel(const float* __restrict__ Wq,
                                const float* __restrict__ Wk,
                                const float* __restrict__ Wv,
                                const float* __restrict__ Wo)
{
    __shared__ float pm[8][33];
    __shared__ float sscale[32];
    __shared__ float tile[32][33];
    const int tx = threadIdx.x, ty = threadIdx.y;
    const int n0 = blockIdx.x * 32;
    const int slot = blockIdx.y;
    const float* W = (slot == 0) ? Wq : (slot == 1) ? Wk
                   : (slot == 2) ? Wv : Wo;

    float mx = 1e-30f;
    for (int k = ty; k < D_; k += 8)
        mx = fmaxf(mx, fabsf(W[(size_t)k * D_ + n0 + tx]));
    pm[ty][tx] = mx;
    __syncthreads();
    if (ty == 0) {
        float m = pm[0][tx];
#pragma unroll
        for (int u = 1; u < 8; u++) m = fmaxf(m, pm[u][tx]);
        sscale[tx] = m / 127.0f;
        g_sw[slot * 1024 + n0 + tx] = m / 127.0f;
    }
    __syncthreads();

    char* wh = (char*)g_wt0 + (size_t)slot * 1048576;
    char* wl = (char*)g_wt1 + (size_t)slot * 1048576;
    for (int k0 = 0; k0 < D_; k0 += 32) {
#pragma unroll
        for (int j = 0; j < 4; j++)
            tile[ty + 8 * j][tx] = W[(size_t)(k0 + ty + 8 * j) * D_ + n0 + tx];
        __syncthreads();
#pragma unroll
        for (int j = 0; j < 4; j++) {
            const int n = ty + 8 * j;
            const float inv = 1.0f / sscale[n];
            float u = tile[tx][n] * inv;
            int h, l;
            quant2(u, h, l);
            wh[(size_t)(n0 + n) * D_ + k0 + tx] = (char)h;
            wl[(size_t)(n0 + n) * D_ + k0 + tx] = (char)l;
        }
        __syncthreads();
    }
}

// Re-quantize Q/K bf16-pairs -> 2-level int8 rows + per-row scale.
// grid (16384, 2), block 256; one warp per (bh,s) row of 64 elems.
__global__ void quant_qk8_kernel()
{
    const int z    = blockIdx.y;                 // 0 = Q, 1 = K
    const int lane = threadIdx.x & 31;
    const size_t row = (size_t)blockIdx.x * 8 + (threadIdx.x >> 5);

    const uint32_t* b0 = (z ? (const uint32_t*)g_kb0 : (const uint32_t*)g_qb0)
                         + row * 32;
    const uint32_t* b1 = (z ? (const uint32_t*)g_kb1 : (const uint32_t*)g_qb1)
                         + row * 32;
    uint32_t u0 = b0[lane], u1 = b1[lane];
    __nv_bfloat162 hb = *(__nv_bfloat162*)&u0;
    __nv_bfloat162 hs = *(__nv_bfloat162*)&u1;
    float v0 = __bfloat162float(hb.x) + __bfloat162float(hs.x);
    float v1 = __bfloat162float(hb.y) + __bfloat162float(hs.y);

    float mx = fmaxf(fmaxf(fabsf(v0), fabsf(v1)), 1e-30f);
#pragma unroll
    for (int o = 16; o >= 1; o >>= 1)
        mx = fmaxf(mx, __shfl_xor_sync(0xffffffffu, mx, o));

    const float s1 = mx / 127.0f;
    const float inv = 127.0f / mx;
    if (lane == 0) { if (z) g_sk[row] = s1; else g_sq[row] = s1; }

    int h0, l0, h1, l1;
    quant2(v0 * inv, h0, l0);
    quant2(v1 * inv, h1, l1);
    uint16_t ph = (uint16_t)(((uint32_t)(uint8_t)h0) | ((uint32_t)(uint8_t)h1 << 8));
    uint16_t pl = (uint16_t)(((uint32_t)(uint8_t)l0) | ((uint32_t)(uint8_t)l1 << 8));
    uint16_t* dh = (uint16_t*)(z ? g_k8h : g_q8h) + row * 32;
    uint16_t* dl = (uint16_t*)(z ? g_k8l : g_q8l) + row * 32;
    dh[lane] = ph;
    dl[lane] = pl;
}

// ---------------------------------------------------------------------------
// int8 2-level mma GEMM (proven R12 core; W slot 3 for O projection)
// ---------------------------------------------------------------------------
#define TPB  10240
#define STGB (2 * TPB)
#define GSMEM (2 * STGB)

__global__ __launch_bounds__(256, 2)
void mma_gemm_kernel(const float* __restrict__ biasA,
                     const float* __restrict__ biasB,
                     const float* __restrict__ biasC,
                     float* __restrict__ Yext, int ysel)
{
    extern __shared__ char sm[];
    const uint32_t sbase = smem_u32(sm);

    const int tid  = threadIdx.x;
    const int wid  = tid >> 5;
    const int lane = tid & 31;
    const int wm   = wid >> 2;
    const int wn   = wid & 3;
    const int m0   = blockIdx.y * 128;
    const int n0   = blockIdx.x * 128;
    const int z    = blockIdx.z;
    const int xslot = (ysel < 0) ? z : 0;
    const int wslot = (ysel < 0) ? z : 3;
    const int ysl  = (ysel < 0) ? (z + 1) : 0;
    const float* bias = (ysel >= 0) ? biasA
                      : (z == 0) ? biasA : (z == 1) ? biasB : biasC;

    const char* pxh = (const char*)g_xs0 + (size_t)xslot * 8388608;
    const char* pxl = (const char*)g_xs1 + (size_t)xslot * 8388608;
    const char* pwh = (const char*)g_wt0 + (size_t)wslot * 1048576;
    const char* pwl = (const char*)g_wt1 + (size_t)wslot * 1048576;

    const int lrow = tid >> 1;
    const int lop  = tid & 1;
    const char* lsh = lop ? pwh : pxh;
    const char* lsl = lop ? pwl : pxl;
    const int lgb   = lop ? n0 : m0;
    const uint32_t ldst0 = lop * TPB + (uint32_t)lrow * 80;

    int A1[4][4][4];
#pragma unroll
    for (int i = 0; i < 4; i++)
#pragma unroll
        for (int j = 0; j < 4; j++)
#pragma unroll
            for (int e = 0; e < 4; e++) A1[i][j][e] = 0;

#define LOAD_STAGE(st, kt) do {                                               \
    const uint32_t d = sbase + (st) * STGB + ldst0;                           \
    const size_t g = (size_t)(lgb + lrow) * 1024 + (kt) * 32;                 \
    CP_ASYNC16(d,      lsh + g);                                              \
    CP_ASYNC16(d + 16, lsh + g + 16);                                         \
    CP_ASYNC16(d + 32, lsl + g);                                              \
    CP_ASYNC16(d + 48, lsl + g + 16);                                         \
    CP_COMMIT();                                                              \
} while (0)

    const uint32_t aoffs = (uint32_t)((lane & 15) * 80 + (lane >> 4) * 16);
    const uint32_t boffs = (uint32_t)(((lane >> 4) * 8 + (lane & 7)) * 80 +
                                      ((lane >> 3) & 1) * 16);

    LOAD_STAGE(0, 0);

    const int NT = D_ / 32;
    for (int kt = 0; kt < NT; kt++) {
        CP_WAIT0();
        __syncthreads();
        if (kt + 1 < NT) LOAD_STAGE((kt + 1) & 1, kt + 1);

        const uint32_t sb = sbase + (kt & 1) * STGB;

        uint32_t ahi[4][4], alo[4][4];
#pragma unroll
        for (int i = 0; i < 4; i++) {
            const uint32_t ad =
                sb + (uint32_t)((wm * 64 + 16 * i) * 80) + aoffs;
            ldsm4(ahi[i], ad);
            ldsm4(alo[i], ad + 32);
        }
        uint32_t bhi[4][2], blo[4][2];
#pragma unroll
        for (int p = 0; p < 2; p++) {
            const uint32_t bd =
                sb + TPB + (uint32_t)((wn * 32 + 16 * p) * 80) + boffs;
            uint32_t t0[4], t1[4];
            ldsm4(t0, bd);
            ldsm4(t1, bd + 32);
            bhi[2 * p][0] = t0[0]; bhi[2 * p][1] = t0[1];
            bhi[2 * p + 1][0] = t0[2]; bhi[2 * p + 1][1] = t0[3];
            blo[2 * p][0] = t1[0]; blo[2 * p][1] = t1[1];
            blo[2 * p + 1][0] = t1[2]; blo[2 * p + 1][1] = t1[3];
        }
#pragma unroll
        for (int i = 0; i < 4; i++)
#pragma unroll
            for (int j = 0; j < 4; j++) {
                int a2[4] = {0, 0, 0, 0};
                mma_s8(a2, ahi[i], blo[j]);
                mma_s8(a2, alo[i], bhi[j]);
                mma_s8(A1[i][j], ahi[i], bhi[j]);
#pragma unroll
                for (int e = 0; e < 4; e++)
                    A1[i][j][e] += (a2[e] + 128) >> 8;
            }
    }

    const float* sxp = g_sx + xslot * 8192;
    const float* swp = g_sw + wslot * 1024;

    if (ysl == 0) {
#pragma unroll
        for (int i = 0; i < 4; i++) {
            const int r0 = m0 + wm * 64 + 16 * i + (lane >> 2);
            const float sxa = sxp[r0], sxb = sxp[r0 + 8];
#pragma unroll
            for (int j = 0; j < 4; j++) {
                const int colp = n0 + wn * 32 + 8 * j + 2 * (lane & 3);
                const float swa = swp[colp], swb = swp[colp + 1];
                const float bx = bias[colp], by = bias[colp + 1];
                float2 v0 = {(float)A1[i][j][0] * (sxa * swa) + bx,
                             (float)A1[i][j][1] * (sxa * swb) + by};
                float2 v1 = {(float)A1[i][j][2] * (sxb * swa) + bx,
                             (float)A1[i][j][3] * (sxb * swb) + by};
                *(float2*)&Yext[(size_t)r0 * D_ + colp] = v0;
                *(float2*)&Yext[(size_t)(r0 + 8) * D_ + colp] = v1;
            }
        }
    } else {
        uint32_t* d0 = (ysl == 1) ? (uint32_t*)g_qb0
                     : (ysl == 2) ? (uint32_t*)g_kb0 : (uint32_t*)g_vb0;
        uint32_t* d1 = (ysl == 1) ? (uint32_t*)g_qb1
                     : (ysl == 2) ? (uint32_t*)g_kb1 : (uint32_t*)g_vb1;
        const float scl = (ysl == 1) ? SCALE_ : 1.0f;
#pragma unroll
        for (int i = 0; i < 4; i++) {
            const int r0 = m0 + wm * 64 + 16 * i + (lane >> 2);
            const float sxa = sxp[r0] * scl, sxb = sxp[r0 + 8] * scl;
#pragma unroll
            for (int j = 0; j < 4; j++) {
                const int colp = n0 + wn * 32 + 8 * j + 2 * (lane & 3);
                const float swa = swp[colp], swb = swp[colp + 1];
                const float bx = bias[colp] * scl, by = bias[colp + 1] * scl;
                const int h = colp >> 6;
                const int d = colp & 63;
#pragma unroll
                for (int half = 0; half < 2; half++) {
                    const int rr = r0 + 8 * half;
                    const int bb = rr >> 11, s = rr & (S_ - 1);
                    const float sx = half ? sxb : sxa;
                    float vx = (float)A1[i][j][2 * half + 0] * (sx * swa) + bx;
                    float vy = (float)A1[i][j][2 * half + 1] * (sx * swb) + by;
                    __nv_bfloat162 hb = __floats2bfloat162_rn(vx, vy);
                    __nv_bfloat162 hs = __floats2bfloat162_rn(
                        vx - __bfloat162float(hb.x), vy - __bfloat162float(hb.y));
                    size_t idx =
                        (((size_t)(bb * H_ + h) * S_ + s) * HD_ + d) >> 1;
                    d0[idx] = *(uint32_t*)&hb;
                    d1[idx] = *(uint32_t*)&hs;
                }
            }
        }
    }
#undef LOAD_STAGE
}

// ---------------------------------------------------------------------------
// Flash attention: int8 QK^T (2-level, per-row scales) + bf16 3-term PV.
// ---------------------------------------------------------------------------
#define AROWB 144
#define ATT_Q (128 * AROWB)
#define ATT_K (64 * AROWB)
#define ATT_STG (ATT_K + 2 * ATT_K + 256)
#define ATT_SMEM (ATT_Q + 2 * ATT_STG)

__global__ __launch_bounds__(256, 2)
void attn_mma_kernel()
{
    extern __shared__ char sm[];
    const uint32_t sb = smem_u32(sm);

    const int tid  = threadIdx.x;
    const int wid  = tid >> 5;
    const int lane = tid & 31;
    const int q0   = blockIdx.x * 128;
    const int bh   = blockIdx.y;

    const size_t roff = (size_t)bh * S_;
    const char* pq8h = (const char*)g_q8h + roff * 64;
    const char* pq8l = (const char*)g_q8l + roff * 64;
    const char* pk8h = (const char*)g_k8h + roff * 64;
    const char* pk8l = (const char*)g_k8l + roff * 64;
    const char* pv0  = (const char*)g_vb0 + roff * 128;
    const char* pv1  = (const char*)g_vb1 + roff * 128;
    const float* psk = g_sk + roff;

#pragma unroll
    for (int sg = 0; sg < 4; sg++) {
        const int seg = tid + 256 * sg;
        const int row = seg >> 3, s8 = seg & 7;
        const uint32_t dd = (uint32_t)(row * AROWB + s8 * 16);
        const char* src = (s8 < 4)
            ? pq8h + (size_t)(q0 + row) * 64 + s8 * 16
            : pq8l + (size_t)(q0 + row) * 64 + (s8 - 4) * 16;
        CP_ASYNC16(sb + dd, src);
    }
    CP_COMMIT();

#define LOAD_KV(st, t) do {                                                   \
    const uint32_t stg_ = sb + ATT_Q + (st) * ATT_STG;                        \
    const int kk0_ = (t) * 64;                                                \
    _Pragma("unroll")                                                         \
    for (int jj = 0; jj < 2; jj++) {                                          \
        const int seg = tid + 256 * jj;                                       \
        const int row = seg >> 3, s8 = seg & 7;                               \
        const uint32_t dd = (uint32_t)(row * AROWB + s8 * 16);                \
        const char* ksrc = (s8 < 4)                                           \
            ? pk8h + (size_t)(kk0_ + row) * 64 + s8 * 16                      \
            : pk8l + (size_t)(kk0_ + row) * 64 + (s8 - 4) * 16;               \
        CP_ASYNC16(stg_ + dd, ksrc);                                          \
        const size_t gv = (size_t)(kk0_ + row) * 128 + s8 * 16;               \
        CP_ASYNC16(stg_ + ATT_K + dd, pv0 + gv);                              \
        CP_ASYNC16(stg_ + 2 * ATT_K + dd, pv1 + gv);                          \
    }                                                                         \
    if (tid < 16)                                                             \
        CP_ASYNC16(stg_ + 3 * ATT_K + tid * 16,                               \
                   (const char*)(psk + kk0_) + tid * 16);                     \
    CP_COMMIT();                                                              \
} while (0)

    LOAD_KV(0, 0);
    CP_WAIT0();
    __syncthreads();

    uint32_t qh[2][4], ql[2][4];
    {
        const uint32_t qbase = sb + (uint32_t)(wid * 16 * AROWB);
        const uint32_t ao = (uint32_t)((lane & 15) * AROWB + (lane >> 4) * 16);
#pragma unroll
        for (int ks = 0; ks < 2; ks++) {
            ldsm4(qh[ks], qbase + ao + ks * 32);
            ldsm4(ql[ks], qbase + ao + ks * 32 + 64);
        }
    }

    const int row0 = q0 + wid * 16 + (lane >> 2);
    const float sq0 = g_sq[roff + row0];
    const float sq1 = g_sq[roff + row0 + 8];
    const uint32_t msh = 2 * (lane & 3);
    const uint32_t boff = (uint32_t)(((lane >> 4) * 8 + (lane & 7)) * AROWB +
                                     ((lane >> 3) & 1) * 16);

    float acc[8][4];
#pragma unroll
    for (int nf = 0; nf < 8; nf++)
#pragma unroll
        for (int e = 0; e < 4; e++) acc[nf][e] = 0.0f;
    float mrun0 = -INFINITY, mrun1 = -INFINITY, lrun0 = 0.0f, lrun1 = 0.0f;

    for (int t = 0; t < S_ / 64; t++) {
        if (t > 0) { CP_WAIT0(); __syncthreads(); }
        if (t + 1 < S_ / 64) LOAD_KV((t + 1) & 1, t + 1);

        const uint32_t stg = sb + ATT_Q + (t & 1) * ATT_STG;

        const unsigned long long mm0 = g_maskbits[(size_t)row0 * 32 + t];
        const unsigned long long mm1 = g_maskbits[(size_t)(row0 + 8) * 32 + t];

        int A1[8][4];
#pragma unroll
        for (int nf = 0; nf < 8; nf++)
#pragma unroll
            for (int e = 0; e < 4; e++) A1[nf][e] = 0;

#pragma unroll
        for (int ks = 0; ks < 2; ks++) {
#pragma unroll
            for (int p = 0; p < 4; p++) {
                const uint32_t kd = stg + (uint32_t)(p * 16 * AROWB) + boff +
                                    ks * 32;
                uint32_t tbh[4], tbl[4];
                ldsm4(tbh, kd);
                ldsm4(tbl, kd + 64);
#pragma unroll
                for (int q = 0; q < 2; q++) {
                    const int nf = 2 * p + q;
                    int a2[4] = {0, 0, 0, 0};
                    mma_s8(a2, qh[ks], tbl + 2 * q);
                    mma_s8(a2, ql[ks], tbh + 2 * q);
                    mma_s8(A1[nf], qh[ks], tbh + 2 * q);
#pragma unroll
                    for (int e = 0; e < 4; e++)
                        A1[nf][e] += (a2[e] + 128) >> 8;
                }
            }
        }

        const float* skp = (const float*)(sm + ATT_Q + (t & 1) * ATT_STG +
                                          3 * ATT_K);
        float c[8][4];
#pragma unroll
        for (int nf = 0; nf < 8; nf++) {
            const float kx = skp[8 * nf + 2 * (lane & 3)];
            const float ky = skp[8 * nf + 2 * (lane & 3) + 1];
            c[nf][0] = (float)A1[nf][0] * (sq0 * kx);
            c[nf][1] = (float)A1[nf][1] * (sq0 * ky);
            c[nf][2] = (float)A1[nf][2] * (sq1 * kx);
            c[nf][3] = (float)A1[nf][3] * (sq1 * ky);
            const uint32_t b0 = (uint32_t)(mm0 >> (8 * nf + msh));
            const uint32_t b1 = (uint32_t)(mm1 >> (8 * nf + msh));
            c[nf][0] = (b0 & 1u) ? c[nf][0] : -1e30f;
            c[nf][1] = (b0 & 2u) ? c[nf][1] : -1e30f;
            c[nf][2] = (b1 & 1u) ? c[nf][2] : -1e30f;
            c[nf][3] = (b1 & 2u) ? c[nf][3] : -1e30f;
        }

        float rm0 = -INFINITY, rm1 = -INFINITY;
#pragma unroll
        for (int nf = 0; nf < 8; nf++) {
            rm0 = fmaxf(rm0, fmaxf(c[nf][0], c[nf][1]));
            rm1 = fmaxf(rm1, fmaxf(c[nf][2], c[nf][3]));
        }
        rm0 = fmaxf(rm0, __shfl_xor_sync(0xffffffffu, rm0, 1));
        rm0 = fmaxf(rm0, __shfl_xor_sync(0xffffffffu, rm0, 2));
        rm1 = fmaxf(rm1, __shfl_xor_sync(0xffffffffu, rm1, 1));
        rm1 = fmaxf(rm1, __shfl_xor_sync(0xffffffffu, rm1, 2));

        const float mn0 = fmaxf(mrun0, rm0);
        const float mn1 = fmaxf(mrun1, rm1);
        const float cr0 = exp_nm(mrun0 - mn0);
        const float cr1 = exp_nm(mrun1 - mn1);
        mrun0 = mn0; mrun1 = mn1;

        float ts0 = 0.0f, ts1 = 0.0f;
#pragma unroll
        for (int nf = 0; nf < 8; nf++) {
            c[nf][0] = exp_nm(c[nf][0] - mn0);
            c[nf][1] = exp_nm(c[nf][1] - mn0);
            c[nf][2] = exp_nm(c[nf][2] - mn1);
            c[nf][3] = exp_nm(c[nf][3] - mn1);
            ts0 += c[nf][0] + c[nf][1];
            ts1 += c[nf][2] + c[nf][3];
        }
        ts0 += __shfl_xor_sync(0xffffffffu, ts0, 1);
        ts0 += __shfl_xor_sync(0xffffffffu, ts0, 2);
        ts1 += __shfl_xor_sync(0xffffffffu, ts1, 1);
        ts1 += __shfl_xor_sync(0xffffffffu, ts1, 2);
        lrun0 = lrun0 * cr0 + ts0;
        lrun1 = lrun1 * cr1 + ts1;

#pragma unroll
        for (int nf = 0; nf < 8; nf++) {
            acc[nf][0] *= cr0; acc[nf][1] *= cr0;
            acc[nf][2] *= cr1; acc[nf][3] *= cr1;
        }

#pragma unroll
        for (int kf = 0; kf < 4; kf++) {
            uint32_t pab[4], pas[4];
#pragma unroll
            for (int q = 0; q < 2; q++) {
                const float* pc = c[2 * kf + q];
#pragma unroll
                for (int half = 0; half < 2; half++) {
                    float v0 = pc[2 * half], v1 = pc[2 * half + 1];
                    __nv_bfloat162 hb = __floats2bfloat162_rn(v0, v1);
                    __nv_bfloat162 hs = __floats2bfloat162_rn(
                        v0 - __bfloat162float(hb.x), v1 - __bfloat162float(hb.y));
                    pab[2 * q + half] = *(uint32_t*)&hb;
                    pas[2 * q + half] = *(uint32_t*)&hs;
                }
            }
#pragma unroll
            for (int dg = 0; dg < 4; dg++) {
                const uint32_t va = stg + ATT_K +
                    (uint32_t)((kf * 16 + (lane & 15)) * AROWB) +
                    dg * 32 + (lane >> 4) * 16;
                uint32_t vb[4], vs[4];
                ldsm4t(vb, va);
                ldsm4t(vs, va + ATT_K);
                mma_bf16(acc[2 * dg], pab, vb);
                mma_bf16(acc[2 * dg], pab, vs);
                mma_bf16(acc[2 * dg], pas, vb);
                mma_bf16(acc[2 * dg + 1], pab, vb + 2);
                mma_bf16(acc[2 * dg + 1], pab, vs + 2);
                mma_bf16(acc[2 * dg + 1], pas, vb + 2);
            }
        }
    }

    const float inv0 = 1.0f / lrun0;
    const float inv1 = 1.0f / lrun1;
    const int b = bh >> 4;
    const int h = bh & 15;
#pragma unroll
    for (int nf = 0; nf < 8; nf++) {
        const int col = h * 64 + 8 * nf + 2 * (lane & 3);
#pragma unroll
        for (int half = 0; half < 2; half++) {
            const int rr = row0 + 8 * half;
            const float inv = half ? inv1 : inv0;
            float v0 = acc[nf][2 * half + 0] * inv;
            float v1 = acc[nf][2 * half + 1] * inv;
            __nv_bfloat162 hb = __floats2bfloat162_rn(v0, v1);
            __nv_bfloat162 hs = __floats2bfloat162_rn(
                v0 - __bfloat162float(hb.x), v1 - __bfloat162float(hb.y));
            size_t idx = ((size_t)(b * S_ + rr) * D_ + col) >> 1;
            g_ctxb0[idx] = *(uint32_t*)&hb;
            g_ctxb1[idx] = *(uint32_t*)&hs;
        }
    }
#undef LOAD_KV
}

// ---------------------------------------------------------------------------
// Launch
// ---------------------------------------------------------------------------
extern "C" void kernel_launch(void* const* d_in, const int* in_sizes, int n_in,
                              void* d_out, int out_size)
{
    const float* queries = (const float*)d_in[0];
    const float* keys    = (const float*)d_in[1];
    const float* values  = (const float*)d_in[2];
    const void*  mask    = d_in[3];
    const float* Wq = (const float*)d_in[4];
    const float* bq = (const float*)d_in[5];
    const float* Wk = (const float*)d_in[6];
    const float* bk = (const float*)d_in[7];
    const float* Wv = (const float*)d_in[8];
    const float* bv = (const float*)d_in[9];
    const float* Wo = (const float*)d_in[10];
    const float* bo = (const float*)d_in[11];
    float* out = (float*)d_out;

    (void)in_sizes; (void)n_in; (void)out_size;

    cudaFuncSetAttribute(mma_gemm_kernel,
                         cudaFuncAttributeMaxDynamicSharedMemorySize, GSMEM);
    cudaFuncSetAttribute(attn_mma_kernel,
                         cudaFuncAttributeMaxDynamicSharedMemorySize, ATT_SMEM);

    detect_mask_kernel<<<1, 256>>>((const unsigned char*)mask);
    mask_bits_kernel<<<128, 256>>>(mask);

    quant_w4_kernel<<<dim3(32, 4), dim3(32, 8)>>>(Wq, Wk, Wv, Wo);
    quant_x3_kernel<<<dim3(1024, 3), 256>>>(
        (const float4*)queries, (const float4*)keys, (const float4*)values);

    dim3 qkvgrid(D_ / 128, (B_ * S_) / 128, 3);
    mma_gemm_kernel<<<qkvgrid, 256, GSMEM>>>(bq, bk, bv, nullptr, -1);

    // Q/K bf16-pairs -> 2-level int8 rows: all 131072 rows
    quant_qk8_kernel<<<dim3(16384, 2), 256>>>();

    dim3 agrid(S_ / 128, B_ * H_);
    attn_mma_kernel<<<agrid, 256, ATT_SMEM>>>();

    quant_ctx_kernel<<<1024, 256>>>();
    dim3 ogrid(D_ / 128, (B_ * S_) / 128, 1);
    mma_gemm_kernel<<<ogrid, 256, GSMEM>>>(bo, nullptr, nullptr, out, 0);
}